// round 9
// baseline (speedup 1.0000x reference)
#include <cuda_runtime.h>
#include <cuda_fp16.h>
#include <cstdint>

#define BB 32
#define IMGSZ 224
#define PSZ 16
#define NSIDE 14
#define NPATCH 196
#define SEQ 197
#define DIM 768
#define NH 12
#define HD 64
#define FF 3072
#define NL 12
#define NCLS 1000
#define TOK (BB*SEQ)     // 6304
#define PTOK (BB*NPATCH) // 6272

// ---------------- scratch (device globals: allocation-free) ----------------
__device__ float  g_x[TOK*DIM];
__device__ float  g_q[TOK*DIM];
__device__ float  g_k[TOK*DIM];
__device__ float  g_v[TOK*DIM];

__device__ __half g_xn_h[TOK*DIM],  g_xn_l[TOK*DIM];
__device__ __half g_o_h[TOK*DIM],   g_o_l[TOK*DIM];
__device__ __half g_h_h[(size_t)TOK*FF], g_h_l[(size_t)TOK*FF];
__device__ __half g_p_h[(size_t)PTOK*DIM], g_p_l[(size_t)PTOK*DIM];
__device__ __half g_cls_h[BB*DIM],  g_cls_l[BB*DIM];

// transposed fp16 hi/lo weights: [N][K] layout per layer
__device__ __half w_pat_h[589824],  w_pat_l[589824];
__device__ __half w_q_h[7077888],   w_q_l[7077888];
__device__ __half w_k_h[7077888],   w_k_l[7077888];
__device__ __half w_v_h[7077888],   w_v_l[7077888];
__device__ __half w_o_h[7077888],   w_o_l[7077888];
__device__ __half w_1_h[28311552],  w_1_l[28311552];
__device__ __half w_2_h[28311552],  w_2_l[28311552];
__device__ __half w_hd_h[768000],   w_hd_l[768000];

struct QKV {
    const __half* bh[3];
    const __half* bl[3];
    const float*  bias[3];
    float*        out[3];
};

// ---------------- weight transpose + hi/lo split ----------------
__global__ void wprep(const float* __restrict__ in, __half* __restrict__ oh,
                      __half* __restrict__ ol, int K, int ng) {
    __shared__ float t[32][33];
    int g = blockIdx.z;
    int e0 = blockIdx.x * 32, k0 = blockIdx.y * 32;
    int tx = threadIdx.x, ty = threadIdx.y;  // 32x8
    const float* gin = in + (size_t)g * K * ng;
    #pragma unroll
    for (int i = 0; i < 4; i++) {
        int kk = k0 + ty + i * 8;
        int e  = e0 + tx;
        float v = 0.f;
        if (e < ng) v = gin[(size_t)kk * ng + e];
        t[ty + i * 8][tx] = v;
    }
    __syncthreads();
    __half* goh = oh + (size_t)g * ng * K;
    __half* gol = ol + (size_t)g * ng * K;
    #pragma unroll
    for (int i = 0; i < 4; i++) {
        int e  = e0 + ty + i * 8;
        int kk = k0 + tx;
        if (e < ng) {
            float v = t[tx][ty + i * 8];
            __half hv = __float2half_rn(v);
            goh[(size_t)e * K + kk] = hv;
            gol[(size_t)e * K + kk] = __float2half_rn(v - __half2float(hv));
        }
    }
}

// ---------------- patch extraction (hi/lo fp16) ----------------
__global__ void patch_extract(const float* __restrict__ img,
                              __half* __restrict__ oh, __half* __restrict__ ol) {
    int idx = blockIdx.x * 256 + threadIdx.x;
    if (idx >= PTOK * DIM) return;
    int kcol = idx % DIM;
    int row  = idx / DIM;
    int b  = row / NPATCH;
    int p  = row % NPATCH;
    int pr = p / NSIDE, pc = p % NSIDE;
    int c  = kcol % 3;
    int t  = kcol / 3;
    int py = t / PSZ, px = t % PSZ;
    float v = img[(((size_t)(b*IMGSZ + pr*PSZ + py) * IMGSZ) + pc*PSZ + px) * 3 + c];
    __half hv = __float2half_rn(v);
    oh[idx] = hv;
    ol[idx] = __float2half_rn(v - __half2float(hv));
}

__global__ void cls_fill(const float* __restrict__ cls, float* __restrict__ x) {
    int i = blockIdx.x * 256 + threadIdx.x;
    if (i < BB * DIM) x[(size_t)(i / DIM) * SEQ * DIM + (i % DIM)] = cls[i % DIM];
}

// ---------------- LayerNorm (fp32 in, fp16 hi/lo out) ----------------
__global__ void ln_kernel(const float* __restrict__ x, const float* __restrict__ g,
                          const float* __restrict__ bt,
                          __half* __restrict__ yh, __half* __restrict__ yl,
                          long long in_stride, long long out_stride) {
    int row = blockIdx.x;
    int tid = threadIdx.x;
    const float* xr = x + (size_t)row * in_stride;
    float v0 = xr[tid], v1 = xr[tid + 256], v2 = xr[tid + 512];

    __shared__ float red1[8];
    __shared__ float red2[8];

    float s = v0 + v1 + v2;
    #pragma unroll
    for (int o = 16; o; o >>= 1) s += __shfl_xor_sync(0xffffffffu, s, o);
    if ((tid & 31) == 0) red1[tid >> 5] = s;
    __syncthreads();
    if (tid == 0) {
        float t = red1[0];
        #pragma unroll
        for (int i = 1; i < 8; i++) t += red1[i];
        red1[0] = t;
    }
    __syncthreads();
    float mean = red1[0] * (1.0f / 768.0f);

    float d0 = v0 - mean, d1 = v1 - mean, d2 = v2 - mean;
    float q = d0*d0 + d1*d1 + d2*d2;
    #pragma unroll
    for (int o = 16; o; o >>= 1) q += __shfl_xor_sync(0xffffffffu, q, o);
    if ((tid & 31) == 0) red2[tid >> 5] = q;
    __syncthreads();
    if (tid == 0) {
        float t = red2[0];
        #pragma unroll
        for (int i = 1; i < 8; i++) t += red2[i];
        red2[0] = t;
    }
    __syncthreads();
    float var = red2[0] * (1.0f / 768.0f);
    float r = rsqrtf(var + 1e-5f);

    size_t ob = (size_t)row * out_stride;
    #pragma unroll
    for (int c = 0; c < 3; c++) {
        float dd = (c == 0 ? d0 : (c == 1 ? d1 : d2));
        int col = tid + c * 256;
        float v = dd * r * g[col] + bt[col];
        __half hv = __float2half_rn(v);
        yh[ob + col] = hv;
        yl[ob + col] = __float2half_rn(v - __half2float(hv));
    }
}

// ---------------- pipelined HMMA GEMM (templated BM x BN) ----------------
#define RS 40                   // padded row stride (halfs): 80B
#define NST 3

__device__ __forceinline__ void cpa16(uint32_t sa, const void* ga, uint32_t ss) {
    asm volatile("cp.async.cg.shared.global [%0], [%1], 16, %2;"
                 :: "r"(sa), "l"(ga), "r"(ss) : "memory");
}

template<int BM, int BN>
__device__ __forceinline__ void load_stage(
    uint32_t sbase, const __half* __restrict__ Ah, const __half* __restrict__ Al,
    const __half* __restrict__ Bh, const __half* __restrict__ Bl,
    int m0, int M, int n0, int N, int K, int k0, int tid)
{
    constexpr int ACH = BM * 4;
    constexpr int BCH = BN * 4;
    constexpr int ATB = BM * RS * 2;
    constexpr int BTB = BN * RS * 2;
    constexpr int CH_TOT = 2 * ACH + 2 * BCH;
    constexpr int PER_T = CH_TOT / 256;
    #pragma unroll
    for (int t = 0; t < PER_T; t++) {
        int ch = tid + t * 256;
        const __half* src; int r0, lim; uint32_t tb; int idx;
        if (ch < ACH)            { src = Ah; r0 = m0; lim = M; tb = 0;           idx = ch; }
        else if (ch < 2*ACH)     { src = Al; r0 = m0; lim = M; tb = ATB;         idx = ch - ACH; }
        else if (ch < 2*ACH+BCH) { src = Bh; r0 = n0; lim = N; tb = 2*ATB;       idx = ch - 2*ACH; }
        else                     { src = Bl; r0 = n0; lim = N; tb = 2*ATB + BTB; idx = ch - 2*ACH - BCH; }
        int row = idx >> 2, c4 = idx & 3;
        int gr = r0 + row;
        uint32_t ss = 16u;
        if (gr >= lim) { gr = lim - 1; ss = 0u; }
        const void* ga = src + (size_t)gr * K + k0 + c4 * 8;
        uint32_t sa = sbase + tb + (uint32_t)(row * RS + c4 * 8) * 2;
        cpa16(sa, ga, ss);
    }
}

#define LDSM_X4(r0, r1, r2, r3, addr) \
    asm volatile("ldmatrix.sync.aligned.m8n8.x4.shared.b16 {%0,%1,%2,%3}, [%4];" \
                 : "=r"(r0), "=r"(r1), "=r"(r2), "=r"(r3) : "r"(addr))

#define MMA16816(c, a, b) \
    asm volatile("mma.sync.aligned.m16n8k16.row.col.f32.f16.f16.f32 " \
                 "{%0,%1,%2,%3}, {%4,%5,%6,%7}, {%8,%9}, {%0,%1,%2,%3};" \
                 : "+f"((c)[0]), "+f"((c)[1]), "+f"((c)[2]), "+f"((c)[3]) \
                 : "r"((a)[0]), "r"((a)[1]), "r"((a)[2]), "r"((a)[3]), \
                   "r"((b)[0]), "r"((b)[1]))

// ep: 0=+bias fp32 | 1=+bias+residual | 2=gelu->fp16 hi/lo | 3=patch embed | 4=fused QKV
template<int BM, int BN, int WROWS, int WCOLS>
__global__ __launch_bounds__(256) void hgemm(
    const __half* __restrict__ Ah, const __half* __restrict__ Al,
    const __half* __restrict__ Bh, const __half* __restrict__ Bl,
    const float* __restrict__ bias, const float* __restrict__ extra,
    float* __restrict__ Cf, __half* __restrict__ Choh, __half* __restrict__ Chol,
    int M, int N, int K, int ep, QKV qkv)
{
    constexpr int WTILE_M = BM / WROWS;
    constexpr int WTM     = WTILE_M / 16;
    constexpr int WTILE_N = BN / WCOLS;
    constexpr int WTN     = WTILE_N / 8;
    constexpr int ATB  = BM * RS * 2;
    constexpr int BTB  = BN * RS * 2;
    constexpr int STGB = 2 * ATB + 2 * BTB;

    extern __shared__ __align__(16) char dsm[];
    uint32_t sb = (uint32_t)__cvta_generic_to_shared(dsm);
    int tid = threadIdx.x, wid = tid >> 5, lane = tid & 31;
    int warp_m = wid / WCOLS, warp_n = wid % WCOLS;
    int m0 = blockIdx.y * BM;
    int n0 = blockIdx.x * BN;
    int Nl = N;
    int epe = ep;
    const __half* Bh_ = Bh; const __half* Bl_ = Bl;
    const float* bias_ = bias; float* Cf_ = Cf;
    if (ep == 4) {
        int seg = n0 / 768;
        Bh_ = qkv.bh[seg]; Bl_ = qkv.bl[seg];
        bias_ = qkv.bias[seg]; Cf_ = qkv.out[seg];
        n0 -= seg * 768; Nl = 768; epe = 0;
    }
    int wrow = warp_m * WTILE_M, wcol = warp_n * WTILE_N;

    float acc[WTM][WTN][4];
    #pragma unroll
    for (int i = 0; i < WTM; i++)
        #pragma unroll
        for (int j = 0; j < WTN; j++)
            #pragma unroll
            for (int r = 0; r < 4; r++) acc[i][j][r] = 0.0f;

    int NC = K >> 5;

    #pragma unroll
    for (int s = 0; s < NST - 1; s++) {
        load_stage<BM,BN>(sb + s * STGB, Ah, Al, Bh_, Bl_, m0, M, n0, Nl, K, s * 32, tid);
        asm volatile("cp.async.commit_group;" ::: "memory");
    }

    int a_off = (wrow + (lane & 15)) * RS + ((lane >> 4) << 3);
    int b_off = (wcol + (lane & 7) + ((lane >> 4) & 1) * 8) * RS
              + ((lane >> 3) & 1) * 8;

    for (int c = 0; c < NC; c++) {
        asm volatile("cp.async.wait_group 1;" ::: "memory");
        __syncthreads();

        int pf = c + NST - 1;
        if (pf < NC) {
            load_stage<BM,BN>(sb + (pf % NST) * STGB, Ah, Al, Bh_, Bl_, m0, M, n0, Nl, K,
                              pf * 32, tid);
        }
        asm volatile("cp.async.commit_group;" ::: "memory");

        uint32_t stg = sb + (c % NST) * STGB;
        uint32_t sAh = stg;
        uint32_t sAl = stg + ATB;
        uint32_t sBh = stg + 2 * ATB;
        uint32_t sBl = stg + 2 * ATB + BTB;

        #pragma unroll
        for (int ks = 0; ks < 2; ks++) {
            uint32_t a[WTM][4], bh[WTN][2], bl[WTN][2];
            #pragma unroll
            for (int mt = 0; mt < WTM; mt++) {
                uint32_t ad = sAh + (uint32_t)(a_off + mt * 16 * RS + ks * 16) * 2;
                LDSM_X4(a[mt][0], a[mt][1], a[mt][2], a[mt][3], ad);
            }
            #pragma unroll
            for (int nb = 0; nb < WTN / 2; nb++) {
                uint32_t bd = sBh + (uint32_t)(b_off + nb * 16 * RS + ks * 16) * 2;
                LDSM_X4(bh[nb*2][0], bh[nb*2][1], bh[nb*2+1][0], bh[nb*2+1][1], bd);
                bd = sBl + (uint32_t)(b_off + nb * 16 * RS + ks * 16) * 2;
                LDSM_X4(bl[nb*2][0], bl[nb*2][1], bl[nb*2+1][0], bl[nb*2+1][1], bd);
            }
            #pragma unroll
            for (int mt = 0; mt < WTM; mt++)
                #pragma unroll
                for (int nt = 0; nt < WTN; nt++) MMA16816(acc[mt][nt], a[mt], bh[nt]);
            #pragma unroll
            for (int mt = 0; mt < WTM; mt++)
                #pragma unroll
                for (int nt = 0; nt < WTN; nt++) MMA16816(acc[mt][nt], a[mt], bl[nt]);
            #pragma unroll
            for (int mt = 0; mt < WTM; mt++) {
                uint32_t ad = sAl + (uint32_t)(a_off + mt * 16 * RS + ks * 16) * 2;
                LDSM_X4(a[mt][0], a[mt][1], a[mt][2], a[mt][3], ad);
            }
            #pragma unroll
            for (int mt = 0; mt < WTM; mt++)
                #pragma unroll
                for (int nt = 0; nt < WTN; nt++) MMA16816(acc[mt][nt], a[mt], bh[nt]);
        }
    }

    // ---------------- epilogue ----------------
    int r  = lane >> 2;
    int c2 = (lane & 3) * 2;
    #pragma unroll
    for (int mt = 0; mt < WTM; mt++) {
        #pragma unroll
        for (int nt = 0; nt < WTN; nt++) {
            int n = n0 + wcol + nt * 8 + c2;
            if (n >= Nl) continue;
            float bn0 = bias_[n], bn1 = bias_[n + 1];
            #pragma unroll
            for (int hh = 0; hh < 2; hh++) {
                int m = m0 + wrow + mt * 16 + r + hh * 8;
                if (m >= M) continue;
                float v0 = acc[mt][nt][hh * 2 + 0] + bn0;
                float v1 = acc[mt][nt][hh * 2 + 1] + bn1;
                if (epe == 0) {
                    *reinterpret_cast<float2*>(&Cf_[(size_t)m * Nl + n]) =
                        make_float2(v0, v1);
                } else if (epe == 1) {
                    float2 e = *reinterpret_cast<const float2*>(&extra[(size_t)m * Nl + n]);
                    *reinterpret_cast<float2*>(&Cf_[(size_t)m * Nl + n]) =
                        make_float2(v0 + e.x, v1 + e.y);
                } else if (epe == 2) {
                    v0 = 0.5f * v0 * (1.0f + erff(v0 * 0.70710678118654752f));
                    v1 = 0.5f * v1 * (1.0f + erff(v1 * 0.70710678118654752f));
                    __half h0 = __float2half_rn(v0), h1 = __float2half_rn(v1);
                    *reinterpret_cast<__half2*>(&Choh[(size_t)m * Nl + n]) =
                        __halves2half2(h0, h1);
                    *reinterpret_cast<__half2*>(&Chol[(size_t)m * Nl + n]) =
                        __halves2half2(__float2half_rn(v0 - __half2float(h0)),
                                       __float2half_rn(v1 - __half2float(h1)));
                } else {
                    int bb = m / NPATCH, p = m % NPATCH;
                    float2 e = *reinterpret_cast<const float2*>(&extra[(size_t)p * DIM + n]);
                    *reinterpret_cast<float2*>(
                        &Cf_[((size_t)(bb * SEQ + p + 1)) * DIM + n]) =
                        make_float2(v0 + e.x, v1 + e.y);
                }
            }
        }
    }
}

// ---------------- fused attention: 4 queries per warp pass --------------------
#define KT_S 200
#define ASMEM ((64*KT_S + SEQ*64 + 32*64 + 32*KT_S) * 4)

__global__ __launch_bounds__(256) void attn_fused(
    const float* __restrict__ q, const float* __restrict__ k,
    const float* __restrict__ v,
    __half* __restrict__ oh, __half* __restrict__ ol) {
    extern __shared__ float sm[];
    float* KsT = sm;                       // [64][200]
    float* Vs  = KsT + 64 * KT_S;          // [197][64]
    float* Qs  = Vs + SEQ * 64;            // [8][4][64]
    float* Sc  = Qs + 32 * 64;             // [8][4][200]
    int bh = blockIdx.x, b = bh / NH, h = bh % NH;
    int tid = threadIdx.x, wid = tid >> 5, lane = tid & 31;

    const float* kb = k + (size_t)b * SEQ * DIM + h * HD;
    const float* vb = v + (size_t)b * SEQ * DIM + h * HD;
    for (int i = tid; i < SEQ * 64; i += 256) {
        int j = i >> 6, e = i & 63;
        KsT[e * KT_S + j] = kb[(size_t)j * DIM + e];
        Vs[j * 64 + e]   = vb[(size_t)j * DIM + e];
    }
    for (int i = tid; i < 64 * 3; i += 256)
        KsT[(i / 3) * KT_S + 197 + (i % 3)] = 0.f;
    __syncthreads();

    float* Qw  = Qs + wid * 4 * 64;
    float* Scw = Sc + wid * 4 * KT_S;
    int j0 = lane * 4;
    int j1 = 128 + lane * 4;
    bool p2 = (lane < 18);

    for (int s0 = wid * 4; s0 < SEQ; s0 += 32) {
        int nq = SEQ - s0; if (nq > 4) nq = 4;
        #pragma unroll
        for (int i = 0; i < 8; i++) {
            int idx = lane + i * 32;
            int qi = idx >> 6, e = idx & 63;
            float val = 0.f;
            if (qi < nq)
                val = q[((size_t)(b * SEQ + s0 + qi)) * DIM + h * HD + e];
            Qw[idx] = val;
        }
        __syncwarp();

        float sc[4][8];
        #pragma unroll
        for (int qi = 0; qi < 4; qi++)
            #pragma unroll
            for (int i = 0; i < 8; i++) sc[qi][i] = 0.f;

        #pragma unroll 4
        for (int e = 0; e < 64; e++) {
            float4 k0 = *reinterpret_cast<float4*>(&KsT[e * KT_S + j0]);
            float4 k1 = make_float4(0.f, 0.f, 0.f, 0.f);
            if (p2) k1 = *reinterpret_cast<float4*>(&KsT[e * KT_S + j1]);
            #pragma unroll
            for (int qi = 0; qi < 4; qi++) {
                float qe = Qw[qi * 64 + e];
                sc[qi][0] += qe * k0.x; sc[qi][1] += qe * k0.y;
                sc[qi][2] += qe * k0.z; sc[qi][3] += qe * k0.w;
                sc[qi][4] += qe * k1.x; sc[qi][5] += qe * k1.y;
                sc[qi][6] += qe * k1.z; sc[qi][7] += qe * k1.w;
            }
        }

        #pragma unroll
        for (int qi = 0; qi < 4; qi++) {
            #pragma unroll
            for (int i = 0; i < 4; i++) sc[qi][i] *= 0.125f;
            #pragma unroll
            for (int i = 0; i < 4; i++)
                sc[qi][4 + i] = (p2 && j1 + i < SEQ) ? sc[qi][4 + i] * 0.125f
                                                     : -3.0e38f;
            float m = sc[qi][0];
            #pragma unroll
            for (int i = 1; i < 8; i++) m = fmaxf(m, sc[qi][i]);
            #pragma unroll
            for (int o = 16; o; o >>= 1)
                m = fmaxf(m, __shfl_xor_sync(0xffffffffu, m, o));
            float ss = 0.f;
            #pragma unroll
            for (int i = 0; i < 8; i++) {
                float p = (sc[qi][i] > -1.0e38f) ? __expf(sc[qi][i] - m) : 0.f;
                sc[qi][i] = p;
                ss += p;
            }
            #pragma unroll
            for (int o = 16; o; o >>= 1) ss += __shfl_xor_sync(0xffffffffu, ss, o);
            float inv = 1.0f / ss;
            *reinterpret_cast<float4*>(&Scw[qi * KT_S + j0]) =
                make_float4(sc[qi][0] * inv, sc[qi][1] * inv,
                            sc[qi][2] * inv, sc[qi][3] * inv);
            if (p2)
                *reinterpret_cast<float4*>(&Scw[qi * KT_S + j1]) =
                    make_float4(sc[qi][4] * inv, sc[qi][5] * inv,
                                sc[qi][6] * inv, sc[qi][7] * inv);
        }
        __syncwarp();

        float a[4][2];
        #pragma unroll
        for (int qi = 0; qi < 4; qi++) { a[qi][0] = 0.f; a[qi][1] = 0.f; }

        for (int j = 0; j < 196; j += 4) {
            float4 p0 = *reinterpret_cast<float4*>(&Scw[0 * KT_S + j]);
            float4 p1 = *reinterpret_cast<float4*>(&Scw[1 * KT_S + j]);
            float4 p2v = *reinterpret_cast<float4*>(&Scw[2 * KT_S + j]);
            float4 p3 = *reinterpret_cast<float4*>(&Scw[3 * KT_S + j]);
            #pragma unroll
            for (int jj = 0; jj < 4; jj++) {
                float v0 = Vs[(j + jj) * 64 + lane];
                float v1 = Vs[(j + jj) * 64 + lane + 32];
                float w0 = (jj == 0) ? p0.x : (jj == 1) ? p0.y : (jj == 2) ? p0.z : p0.w;
                float w1 = (jj == 0) ? p1.x : (jj == 1) ? p1.y : (jj == 2) ? p1.z : p1.w;
                float w2 = (jj == 0) ? p2v.x : (jj == 1) ? p2v.y : (jj == 2) ? p2v.z : p2v.w;
                float w3 = (jj == 0) ? p3.x : (jj == 1) ? p3.y : (jj == 2) ? p3.z : p3.w;
                a[0][0] += w0 * v0; a[0][1] += w0 * v1;
                a[1][0] += w1 * v0; a[1][1] += w1 * v1;
                a[2][0] += w2 * v0; a[2][1] += w2 * v1;
                a[3][0] += w3 * v0; a[3][1] += w3 * v1;
            }
        }
        {
            float v0 = Vs[196 * 64 + lane];
            float v1 = Vs[196 * 64 + lane + 32];
            #pragma unroll
            for (int qi = 0; qi < 4; qi++) {
                float w = Scw[qi * KT_S + 196];
                a[qi][0] += w * v0; a[qi][1] += w * v1;
            }
        }

        #pragma unroll
        for (int qi = 0; qi < 4; qi++) {
            if (qi >= nq) break;
            size_t ob = ((size_t)(b * SEQ + s0 + qi)) * DIM + h * HD;
            __half h0 = __float2half_rn(a[qi][0]);
            oh[ob + lane] = h0;
            ol[ob + lane] = __float2half_rn(a[qi][0] - __half2float(h0));
            __half h1 = __float2half_rn(a[qi][1]);
            oh[ob + lane + 32] = h1;
            ol[ob + lane + 32] = __float2half_rn(a[qi][1] - __half2float(h1));
        }
        __syncwarp();
    }
}

// ---------------- host orchestration ----------------
#define GS_128_128 (NST * (2*128*RS*2 + 2*128*RS*2))   // 122880
#define GS_128_64  (NST * (2*128*RS*2 + 2*64*RS*2))    // 92160

extern "C" void kernel_launch(void* const* d_in, const int* in_sizes, int n_in,
                              void* d_out, int out_size) {
    const float* images    = (const float*)d_in[0];
    const float* patch_W   = (const float*)d_in[1];
    const float* patch_b   = (const float*)d_in[2];
    const float* pos_emb   = (const float*)d_in[3];
    const float* cls       = (const float*)d_in[4];
    const float* ln1_g     = (const float*)d_in[5];
    const float* ln1_b     = (const float*)d_in[6];
    const float* Wq        = (const float*)d_in[7];
    const float* bq        = (const float*)d_in[8];
    const float* Wk        = (const float*)d_in[9];
    const float* bk        = (const float*)d_in[10];
    const float* Wv        = (const float*)d_in[11];
    const float* bv        = (const float*)d_in[12];
    const float* Wo        = (const float*)d_in[13];
    const float* bo        = (const float*)d_in[14];
    const float* ln2_g     = (const float*)d_in[15];
    const float* ln2_b     = (const float*)d_in[16];
    const float* W1        = (const float*)d_in[17];
    const float* b1        = (const float*)d_in[18];
    const float* W2        = (const float*)d_in[19];
    const float* b2        = (const float*)d_in[20];
    const float* head_g    = (const float*)d_in[21];
    const float* head_bn   = (const float*)d_in[22];
    const float* head_W    = (const float*)d_in[23];
    const float* head_bias = (const float*)d_in[24];

    float *x, *q, *k, *v;
    __half *xnh, *xnl, *ooh, *ool, *hh, *hl, *ph, *pl, *ch, *cl;
    __half *wpH, *wpL, *wqH, *wqL, *wkH, *wkL, *wvH, *wvL, *woH, *woL;
    __half *w1H, *w1L, *w2H, *w2L, *whH, *whL;
    cudaGetSymbolAddress((void**)&x,   g_x);
    cudaGetSymbolAddress((void**)&q,   g_q);
    cudaGetSymbolAddress((void**)&k,   g_k);
    cudaGetSymbolAddress((void**)&v,   g_v);
    cudaGetSymbolAddress((void**)&xnh, g_xn_h); cudaGetSymbolAddress((void**)&xnl, g_xn_l);
    cudaGetSymbolAddress((void**)&ooh, g_o_h);  cudaGetSymbolAddress((void**)&ool, g_o_l);
    cudaGetSymbolAddress((void**)&hh,  g_h_h);  cudaGetSymbolAddress((void**)&hl,  g_h_l);
    cudaGetSymbolAddress((void**)&ph,  g_p_h);  cudaGetSymbolAddress((void**)&pl,  g_p_l);
    cudaGetSymbolAddress((void**)&ch,  g_cls_h);cudaGetSymbolAddress((void**)&cl,  g_cls_l);
    cudaGetSymbolAddress((void**)&wpH, w_pat_h);cudaGetSymbolAddress((void**)&wpL, w_pat_l);
    cudaGetSymbolAddress((void**)&wqH, w_q_h);  cudaGetSymbolAddress((void**)&wqL, w_q_l);
    cudaGetSymbolAddress((void**)&wkH, w_k_h);  cudaGetSymbolAddress((void**)&wkL, w_k_l);
    cudaGetSymbolAddress((void**)&wvH, w_v_h);  cudaGetSymbolAddress((void**)&wvL, w_v_l);
    cudaGetSymbolAddress((void**)&woH, w_o_h);  cudaGetSymbolAddress((void**)&woL, w_o_l);
    cudaGetSymbolAddress((void**)&w1H, w_1_h);  cudaGetSymbolAddress((void**)&w1L, w_1_l);
    cudaGetSymbolAddress((void**)&w2H, w_2_h);  cudaGetSymbolAddress((void**)&w2L, w_2_l);
    cudaGetSymbolAddress((void**)&whH, w_hd_h); cudaGetSymbolAddress((void**)&whL, w_hd_l);

    cudaFuncSetAttribute(hgemm<128,128,2,4>, cudaFuncAttributeMaxDynamicSharedMemorySize, GS_128_128);
    cudaFuncSetAttribute(hgemm<128,64,2,4>,  cudaFuncAttributeMaxDynamicSharedMemorySize, GS_128_64);
    cudaFuncSetAttribute(attn_fused, cudaFuncAttributeMaxDynamicSharedMemorySize, ASMEM);

    QKV dummy = {};

    dim3 tblk(32, 8);
    wprep<<<dim3(24, 24, 1),   tblk>>>(patch_W, wpH, wpL, DIM, DIM);
    wprep<<<dim3(2, 24, 144),  tblk>>>(Wq, wqH, wqL, DIM, HD);
    wprep<<<dim3(2, 24, 144),  tblk>>>(Wk, wkH, wkL, DIM, HD);
    wprep<<<dim3(2, 24, 144),  tblk>>>(Wv, wvH, wvL, DIM, HD);
    wprep<<<dim3(24, 24, 12),  tblk>>>(Wo, woH, woL, DIM, DIM);
    wprep<<<dim3(96, 24, 12),  tblk>>>(W1, w1H, w1L, DIM, FF);
    wprep<<<dim3(24, 96, 12),  tblk>>>(W2, w2H, w2L, FF, DIM);
    wprep<<<dim3(32, 24, 1),   tblk>>>(head_W, whH, whL, DIM, NCLS);

    patch_extract<<<(PTOK * DIM + 255) / 256, 256>>>(images, ph, pl);
    hgemm<128,128,2,4><<<dim3(6, 49), 256, GS_128_128>>>(
        ph, pl, wpH, wpL, patch_b, pos_emb, x, nullptr, nullptr,
        PTOK, DIM, DIM, 3, dummy);
    cls_fill<<<(BB * DIM + 255) / 256, 256>>>(cls, x);

    for (int l = 0; l < NL; l++) {
        size_t wo768 = (size_t)l * DIM * DIM;
        size_t woff  = (size_t)l * DIM * FF;

        ln_kernel<<<TOK, 256>>>(x, ln1_g + l * DIM, ln1_b + l * DIM, xnh, xnl, DIM, DIM);

        QKV qk;
        qk.bh[0] = wqH + wo768; qk.bh[1] = wkH + wo768; qk.bh[2] = wvH + wo768;
        qk.bl[0] = wqL + wo768; qk.bl[1] = wkL + wo768; qk.bl[2] = wvL + wo768;
        qk.bias[0] = bq + l * DIM; qk.bias[1] = bk + l * DIM; qk.bias[2] = bv + l * DIM;
        qk.out[0] = q; qk.out[1] = k; qk.out[2] = v;
        hgemm<128,128,2,4><<<dim3(18, 50), 256, GS_128_128>>>(
            xnh, xnl, nullptr, nullptr, nullptr, nullptr, nullptr, nullptr, nullptr,
            TOK, 2304, DIM, 4, qk);

        attn_fused<<<BB * NH, 256, ASMEM>>>(q, k, v, ooh, ool);

        hgemm<128,64,2,4><<<dim3(12, 50), 256, GS_128_64>>>(
            ooh, ool, woH + wo768, woL + wo768, bo + l * DIM, x, x, nullptr, nullptr,
            TOK, DIM, DIM, 1, dummy);

        ln_kernel<<<TOK, 256>>>(x, ln2_g + l * DIM, ln2_b + l * DIM, xnh, xnl, DIM, DIM);

        hgemm<128,128,2,4><<<dim3(24, 50), 256, GS_128_128>>>(
            xnh, xnl, w1H + woff, w1L + woff, b1 + l * FF, nullptr, nullptr,
            hh, hl, TOK, FF, DIM, 2, dummy);
        hgemm<128,64,2,4><<<dim3(12, 50), 256, GS_128_64>>>(
            hh, hl, w2H + woff, w2L + woff, b2 + l * DIM, x, x, nullptr, nullptr,
            TOK, DIM, FF, 1, dummy);
    }

    ln_kernel<<<BB, 256>>>(x, head_g, head_bn, ch, cl, (long long)SEQ * DIM, DIM);
    hgemm<128,128,2,4><<<dim3(8, 1), 256, GS_128_128>>>(
        ch, cl, whH, whL, head_bias, nullptr, (float*)d_out, nullptr, nullptr,
        BB, NCLS, DIM, 0, dummy);
}

// round 10
// speedup vs baseline: 1.3512x; 1.3512x over previous
#include <cuda_runtime.h>
#include <cuda_fp16.h>
#include <cstdint>

#define BB 32
#define IMGSZ 224
#define PSZ 16
#define NSIDE 14
#define NPATCH 196
#define SEQ 197
#define DIM 768
#define NH 12
#define HD 64
#define FF 3072
#define NL 12
#define NCLS 1000
#define TOK (BB*SEQ)     // 6304
#define PTOK (BB*NPATCH) // 6272

// ---------------- scratch (device globals: allocation-free) ----------------
__device__ float  g_x[TOK*DIM];
__device__ float  g_q[TOK*DIM];
__device__ float  g_k[TOK*DIM];
__device__ float  g_v[TOK*DIM];

__device__ __half g_xn[TOK*DIM];
__device__ __half g_o[TOK*DIM];
__device__ __half g_h[(size_t)TOK*FF];
__device__ __half g_p[(size_t)PTOK*DIM];
__device__ __half g_cls16[BB*DIM];

// transposed fp16 hi/lo weights: [N][K] layout per layer
__device__ __half w_pat_h[589824],  w_pat_l[589824];
__device__ __half w_q_h[7077888],   w_q_l[7077888];
__device__ __half w_k_h[7077888],   w_k_l[7077888];
__device__ __half w_v_h[7077888],   w_v_l[7077888];
__device__ __half w_o_h[7077888],   w_o_l[7077888];
__device__ __half w_1_h[28311552],  w_1_l[28311552];
__device__ __half w_2_h[28311552],  w_2_l[28311552];
__device__ __half w_hd_h[768000],   w_hd_l[768000];

struct QKV {
    const __half* bh[3];
    const __half* bl[3];
    const float*  bias[3];
    float*        out[3];
};

// ---------------- weight transpose + hi/lo split ----------------
__global__ void wprep(const float* __restrict__ in, __half* __restrict__ oh,
                      __half* __restrict__ ol, int K, int ng) {
    __shared__ float t[32][33];
    int g = blockIdx.z;
    int e0 = blockIdx.x * 32, k0 = blockIdx.y * 32;
    int tx = threadIdx.x, ty = threadIdx.y;  // 32x8
    const float* gin = in + (size_t)g * K * ng;
    #pragma unroll
    for (int i = 0; i < 4; i++) {
        int kk = k0 + ty + i * 8;
        int e  = e0 + tx;
        float v = 0.f;
        if (e < ng) v = gin[(size_t)kk * ng + e];
        t[ty + i * 8][tx] = v;
    }
    __syncthreads();
    __half* goh = oh + (size_t)g * ng * K;
    __half* gol = ol + (size_t)g * ng * K;
    #pragma unroll
    for (int i = 0; i < 4; i++) {
        int e  = e0 + ty + i * 8;
        int kk = k0 + tx;
        if (e < ng) {
            float v = t[tx][ty + i * 8];
            __half hv = __float2half_rn(v);
            goh[(size_t)e * K + kk] = hv;
            gol[(size_t)e * K + kk] = __float2half_rn(v - __half2float(hv));
        }
    }
}

// ---------------- patch extraction (fp16) ----------------
__global__ void patch_extract(const float* __restrict__ img,
                              __half* __restrict__ oh) {
    int idx = blockIdx.x * 256 + threadIdx.x;
    if (idx >= PTOK * DIM) return;
    int kcol = idx % DIM;
    int row  = idx / DIM;
    int b  = row / NPATCH;
    int p  = row % NPATCH;
    int pr = p / NSIDE, pc = p % NSIDE;
    int c  = kcol % 3;
    int t  = kcol / 3;
    int py = t / PSZ, px = t % PSZ;
    float v = img[(((size_t)(b*IMGSZ + pr*PSZ + py) * IMGSZ) + pc*PSZ + px) * 3 + c];
    oh[idx] = __float2half_rn(v);
}

__global__ void cls_fill(const float* __restrict__ cls, float* __restrict__ x) {
    int i = blockIdx.x * 256 + threadIdx.x;
    if (i < BB * DIM) x[(size_t)(i / DIM) * SEQ * DIM + (i % DIM)] = cls[i % DIM];
}

// ---------------- LayerNorm (fp32 in, fp16 out) ----------------
__global__ void ln_kernel(const float* __restrict__ x, const float* __restrict__ g,
                          const float* __restrict__ bt,
                          __half* __restrict__ yh,
                          long long in_stride, long long out_stride) {
    int row = blockIdx.x;
    int tid = threadIdx.x;
    const float* xr = x + (size_t)row * in_stride;
    float v0 = xr[tid], v1 = xr[tid + 256], v2 = xr[tid + 512];

    __shared__ float red1[8];
    __shared__ float red2[8];

    float s = v0 + v1 + v2;
    #pragma unroll
    for (int o = 16; o; o >>= 1) s += __shfl_xor_sync(0xffffffffu, s, o);
    if ((tid & 31) == 0) red1[tid >> 5] = s;
    __syncthreads();
    if (tid == 0) {
        float t = red1[0];
        #pragma unroll
        for (int i = 1; i < 8; i++) t += red1[i];
        red1[0] = t;
    }
    __syncthreads();
    float mean = red1[0] * (1.0f / 768.0f);

    float d0 = v0 - mean, d1 = v1 - mean, d2 = v2 - mean;
    float q = d0*d0 + d1*d1 + d2*d2;
    #pragma unroll
    for (int o = 16; o; o >>= 1) q += __shfl_xor_sync(0xffffffffu, q, o);
    if ((tid & 31) == 0) red2[tid >> 5] = q;
    __syncthreads();
    if (tid == 0) {
        float t = red2[0];
        #pragma unroll
        for (int i = 1; i < 8; i++) t += red2[i];
        red2[0] = t;
    }
    __syncthreads();
    float var = red2[0] * (1.0f / 768.0f);
    float r = rsqrtf(var + 1e-5f);

    size_t ob = (size_t)row * out_stride;
    #pragma unroll
    for (int c = 0; c < 3; c++) {
        float dd = (c == 0 ? d0 : (c == 1 ? d1 : d2));
        int col = tid + c * 256;
        yh[ob + col] = __float2half_rn(dd * r * g[col] + bt[col]);
    }
}

// ---------------- pipelined HMMA GEMM: 2-term (A fp16, B hi/lo) ----------------
#define RS 40                   // padded row stride (halfs): 80B
#define NST 3

__device__ __forceinline__ void cpa16(uint32_t sa, const void* ga, uint32_t ss) {
    asm volatile("cp.async.cg.shared.global [%0], [%1], 16, %2;"
                 :: "r"(sa), "l"(ga), "r"(ss) : "memory");
}

template<int BM>
__device__ __forceinline__ void load_stage(
    uint32_t sbase, const __half* __restrict__ A,
    const __half* __restrict__ Bh, const __half* __restrict__ Bl,
    int m0, int M, int n0, int N, int K, int k0, int tid)
{
    constexpr int ACH = BM * 4;
    constexpr int ATB = BM * RS * 2;
    constexpr int BTB = 128 * RS * 2;
    constexpr int CH_TOT = ACH + 1024;
    constexpr int PER_T = CH_TOT / 256;
    #pragma unroll
    for (int t = 0; t < PER_T; t++) {
        int ch = tid + t * 256;
        const __half* src; int r0, lim; uint32_t tb; int idx;
        if (ch < ACH)            { src = A;  r0 = m0; lim = M; tb = 0;         idx = ch; }
        else if (ch < ACH + 512) { src = Bh; r0 = n0; lim = N; tb = ATB;       idx = ch - ACH; }
        else                     { src = Bl; r0 = n0; lim = N; tb = ATB + BTB; idx = ch - ACH - 512; }
        int row = idx >> 2, c4 = idx & 3;
        int gr = r0 + row;
        uint32_t ss = 16u;
        if (gr >= lim) { gr = lim - 1; ss = 0u; }
        const void* ga = src + (size_t)gr * K + k0 + c4 * 8;
        uint32_t sa = sbase + tb + (uint32_t)(row * RS + c4 * 8) * 2;
        cpa16(sa, ga, ss);
    }
}

#define LDSM_X4(r0, r1, r2, r3, addr) \
    asm volatile("ldmatrix.sync.aligned.m8n8.x4.shared.b16 {%0,%1,%2,%3}, [%4];" \
                 : "=r"(r0), "=r"(r1), "=r"(r2), "=r"(r3) : "r"(addr))

#define MMA16816(c, a, b) \
    asm volatile("mma.sync.aligned.m16n8k16.row.col.f32.f16.f16.f32 " \
                 "{%0,%1,%2,%3}, {%4,%5,%6,%7}, {%8,%9}, {%0,%1,%2,%3};" \
                 : "+f"((c)[0]), "+f"((c)[1]), "+f"((c)[2]), "+f"((c)[3]) \
                 : "r"((a)[0]), "r"((a)[1]), "r"((a)[2]), "r"((a)[3]), \
                   "r"((b)[0]), "r"((b)[1]))

// ep: 0=+bias fp32 | 1=+bias+residual | 2=gelu->fp16 | 3=patch embed | 4=fused QKV
template<int BM, int WROWS, int WCOLS>
__global__ __launch_bounds__(256) void hgemm(
    const __half* __restrict__ A,
    const __half* __restrict__ Bh, const __half* __restrict__ Bl,
    const float* __restrict__ bias, const float* __restrict__ extra,
    float* __restrict__ Cf, __half* __restrict__ Choh,
    int M, int N, int K, int ep, QKV qkv)
{
    constexpr int WTILE_M = BM / WROWS;
    constexpr int WTM     = WTILE_M / 16;
    constexpr int WTILE_N = 128 / WCOLS;
    constexpr int WTN     = WTILE_N / 8;
    constexpr int ATB  = BM * RS * 2;
    constexpr int BTB  = 128 * RS * 2;
    constexpr int STGB = ATB + 2 * BTB;

    extern __shared__ __align__(16) char dsm[];
    uint32_t sb = (uint32_t)__cvta_generic_to_shared(dsm);
    int tid = threadIdx.x, wid = tid >> 5, lane = tid & 31;
    int warp_m = wid / WCOLS, warp_n = wid % WCOLS;
    int m0 = blockIdx.y * BM;
    int n0 = blockIdx.x * 128;
    int Nl = N;
    int epe = ep;
    const __half* Bh_ = Bh; const __half* Bl_ = Bl;
    const float* bias_ = bias; float* Cf_ = Cf;
    if (ep == 4) {
        int seg = n0 / 768;
        Bh_ = qkv.bh[seg]; Bl_ = qkv.bl[seg];
        bias_ = qkv.bias[seg]; Cf_ = qkv.out[seg];
        n0 -= seg * 768; Nl = 768; epe = 0;
    }
    int wrow = warp_m * WTILE_M, wcol = warp_n * WTILE_N;

    float acc[WTM][WTN][4];
    #pragma unroll
    for (int i = 0; i < WTM; i++)
        #pragma unroll
        for (int j = 0; j < WTN; j++)
            #pragma unroll
            for (int r = 0; r < 4; r++) acc[i][j][r] = 0.0f;

    int NC = K >> 5;

    #pragma unroll
    for (int s = 0; s < NST - 1; s++) {
        load_stage<BM>(sb + s * STGB, A, Bh_, Bl_, m0, M, n0, Nl, K, s * 32, tid);
        asm volatile("cp.async.commit_group;" ::: "memory");
    }

    int a_off = (wrow + (lane & 15)) * RS + ((lane >> 4) << 3);
    int b_off = (wcol + (lane & 7) + ((lane >> 4) & 1) * 8) * RS
              + ((lane >> 3) & 1) * 8;

    for (int c = 0; c < NC; c++) {
        asm volatile("cp.async.wait_group 1;" ::: "memory");
        __syncthreads();

        int pf = c + NST - 1;
        if (pf < NC) {
            load_stage<BM>(sb + (pf % NST) * STGB, A, Bh_, Bl_, m0, M, n0, Nl, K,
                           pf * 32, tid);
        }
        asm volatile("cp.async.commit_group;" ::: "memory");

        uint32_t stg = sb + (c % NST) * STGB;
        uint32_t sA  = stg;
        uint32_t sBh = stg + ATB;
        uint32_t sBl = stg + ATB + BTB;

        #pragma unroll
        for (int ks = 0; ks < 2; ks++) {
            uint32_t a[WTM][4], bh[WTN][2], bl[WTN][2];
            #pragma unroll
            for (int mt = 0; mt < WTM; mt++) {
                uint32_t ad = sA + (uint32_t)(a_off + mt * 16 * RS + ks * 16) * 2;
                LDSM_X4(a[mt][0], a[mt][1], a[mt][2], a[mt][3], ad);
            }
            #pragma unroll
            for (int nb = 0; nb < WTN / 2; nb++) {
                uint32_t bd = sBh + (uint32_t)(b_off + nb * 16 * RS + ks * 16) * 2;
                LDSM_X4(bh[nb*2][0], bh[nb*2][1], bh[nb*2+1][0], bh[nb*2+1][1], bd);
                bd = sBl + (uint32_t)(b_off + nb * 16 * RS + ks * 16) * 2;
                LDSM_X4(bl[nb*2][0], bl[nb*2][1], bl[nb*2+1][0], bl[nb*2+1][1], bd);
            }
            #pragma unroll
            for (int mt = 0; mt < WTM; mt++)
                #pragma unroll
                for (int nt = 0; nt < WTN; nt++) MMA16816(acc[mt][nt], a[mt], bh[nt]);
            #pragma unroll
            for (int mt = 0; mt < WTM; mt++)
                #pragma unroll
                for (int nt = 0; nt < WTN; nt++) MMA16816(acc[mt][nt], a[mt], bl[nt]);
        }
    }

    // ---------------- epilogue ----------------
    int r  = lane >> 2;
    int c2 = (lane & 3) * 2;
    #pragma unroll
    for (int mt = 0; mt < WTM; mt++) {
        #pragma unroll
        for (int nt = 0; nt < WTN; nt++) {
            int n = n0 + wcol + nt * 8 + c2;
            if (n >= Nl) continue;
            float bn0 = bias_[n], bn1 = bias_[n + 1];
            #pragma unroll
            for (int hh = 0; hh < 2; hh++) {
                int m = m0 + wrow + mt * 16 + r + hh * 8;
                if (m >= M) continue;
                float v0 = acc[mt][nt][hh * 2 + 0] + bn0;
                float v1 = acc[mt][nt][hh * 2 + 1] + bn1;
                if (epe == 0) {
                    *reinterpret_cast<float2*>(&Cf_[(size_t)m * Nl + n]) =
                        make_float2(v0, v1);
                } else if (epe == 1) {
                    float2 e = *reinterpret_cast<const float2*>(&extra[(size_t)m * Nl + n]);
                    *reinterpret_cast<float2*>(&Cf_[(size_t)m * Nl + n]) =
                        make_float2(v0 + e.x, v1 + e.y);
                } else if (epe == 2) {
                    v0 = 0.5f * v0 * (1.0f + erff(v0 * 0.70710678118654752f));
                    v1 = 0.5f * v1 * (1.0f + erff(v1 * 0.70710678118654752f));
                    *reinterpret_cast<__half2*>(&Choh[(size_t)m * Nl + n]) =
                        __halves2half2(__float2half_rn(v0), __float2half_rn(v1));
                } else {
                    int bb = m / NPATCH, p = m % NPATCH;
                    float2 e = *reinterpret_cast<const float2*>(&extra[(size_t)p * DIM + n]);
                    *reinterpret_cast<float2*>(
                        &Cf_[((size_t)(bb * SEQ + p + 1)) * DIM + n]) =
                        make_float2(v0 + e.x, v1 + e.y);
                }
            }
        }
    }
}

// ---------------- fused attention: 4 queries per warp pass --------------------
#define KT_S 200
#define ASMEM ((64*KT_S + SEQ*64 + 32*64 + 32*KT_S) * 4)

__global__ __launch_bounds__(256) void attn_fused(
    const float* __restrict__ q, const float* __restrict__ k,
    const float* __restrict__ v, __half* __restrict__ oh) {
    extern __shared__ float sm[];
    float* KsT = sm;                       // [64][200]
    float* Vs  = KsT + 64 * KT_S;          // [197][64]
    float* Qs  = Vs + SEQ * 64;            // [8][4][64]
    float* Sc  = Qs + 32 * 64;             // [8][4][200]
    int bh = blockIdx.x, b = bh / NH, h = bh % NH;
    int tid = threadIdx.x, wid = tid >> 5, lane = tid & 31;

    const float* kb = k + (size_t)b * SEQ * DIM + h * HD;
    const float* vb = v + (size_t)b * SEQ * DIM + h * HD;
    for (int i = tid; i < SEQ * 64; i += 256) {
        int j = i >> 6, e = i & 63;
        KsT[e * KT_S + j] = kb[(size_t)j * DIM + e];
        Vs[j * 64 + e]   = vb[(size_t)j * DIM + e];
    }
    for (int i = tid; i < 64 * 3; i += 256)
        KsT[(i / 3) * KT_S + 197 + (i % 3)] = 0.f;
    __syncthreads();

    float* Qw  = Qs + wid * 4 * 64;
    float* Scw = Sc + wid * 4 * KT_S;
    int j0 = lane * 4;
    int j1 = 128 + lane * 4;
    bool p2 = (lane < 18);

    for (int s0 = wid * 4; s0 < SEQ; s0 += 32) {
        int nq = SEQ - s0; if (nq > 4) nq = 4;
        #pragma unroll
        for (int i = 0; i < 8; i++) {
            int idx = lane + i * 32;
            int qi = idx >> 6, e = idx & 63;
            float val = 0.f;
            if (qi < nq)
                val = q[((size_t)(b * SEQ + s0 + qi)) * DIM + h * HD + e];
            Qw[idx] = val;
        }
        __syncwarp();

        float sc[4][8];
        #pragma unroll
        for (int qi = 0; qi < 4; qi++)
            #pragma unroll
            for (int i = 0; i < 8; i++) sc[qi][i] = 0.f;

        #pragma unroll 4
        for (int e = 0; e < 64; e++) {
            float4 k0 = *reinterpret_cast<float4*>(&KsT[e * KT_S + j0]);
            float4 k1 = make_float4(0.f, 0.f, 0.f, 0.f);
            if (p2) k1 = *reinterpret_cast<float4*>(&KsT[e * KT_S + j1]);
            #pragma unroll
            for (int qi = 0; qi < 4; qi++) {
                float qe = Qw[qi * 64 + e];
                sc[qi][0] += qe * k0.x; sc[qi][1] += qe * k0.y;
                sc[qi][2] += qe * k0.z; sc[qi][3] += qe * k0.w;
                sc[qi][4] += qe * k1.x; sc[qi][5] += qe * k1.y;
                sc[qi][6] += qe * k1.z; sc[qi][7] += qe * k1.w;
            }
        }

        #pragma unroll
        for (int qi = 0; qi < 4; qi++) {
            #pragma unroll
            for (int i = 0; i < 4; i++) sc[qi][i] *= 0.125f;
            #pragma unroll
            for (int i = 0; i < 4; i++)
                sc[qi][4 + i] = (p2 && j1 + i < SEQ) ? sc[qi][4 + i] * 0.125f
                                                     : -3.0e38f;
            float m = sc[qi][0];
            #pragma unroll
            for (int i = 1; i < 8; i++) m = fmaxf(m, sc[qi][i]);
            #pragma unroll
            for (int o = 16; o; o >>= 1)
                m = fmaxf(m, __shfl_xor_sync(0xffffffffu, m, o));
            float ss = 0.f;
            #pragma unroll
            for (int i = 0; i < 8; i++) {
                float p = (sc[qi][i] > -1.0e38f) ? __expf(sc[qi][i] - m) : 0.f;
                sc[qi][i] = p;
                ss += p;
            }
            #pragma unroll
            for (int o = 16; o; o >>= 1) ss += __shfl_xor_sync(0xffffffffu, ss, o);
            float inv = 1.0f / ss;
            *reinterpret_cast<float4*>(&Scw[qi * KT_S + j0]) =
                make_float4(sc[qi][0] * inv, sc[qi][1] * inv,
                            sc[qi][2] * inv, sc[qi][3] * inv);
            if (p2)
                *reinterpret_cast<float4*>(&Scw[qi * KT_S + j1]) =
                    make_float4(sc[qi][4] * inv, sc[qi][5] * inv,
                                sc[qi][6] * inv, sc[qi][7] * inv);
        }
        __syncwarp();

        float a[4][2];
        #pragma unroll
        for (int qi = 0; qi < 4; qi++) { a[qi][0] = 0.f; a[qi][1] = 0.f; }

        for (int j = 0; j < 196; j += 4) {
            float4 p0 = *reinterpret_cast<float4*>(&Scw[0 * KT_S + j]);
            float4 p1 = *reinterpret_cast<float4*>(&Scw[1 * KT_S + j]);
            float4 p2v = *reinterpret_cast<float4*>(&Scw[2 * KT_S + j]);
            float4 p3 = *reinterpret_cast<float4*>(&Scw[3 * KT_S + j]);
            #pragma unroll
            for (int jj = 0; jj < 4; jj++) {
                float v0 = Vs[(j + jj) * 64 + lane];
                float v1 = Vs[(j + jj) * 64 + lane + 32];
                float w0 = (jj == 0) ? p0.x : (jj == 1) ? p0.y : (jj == 2) ? p0.z : p0.w;
                float w1 = (jj == 0) ? p1.x : (jj == 1) ? p1.y : (jj == 2) ? p1.z : p1.w;
                float w2 = (jj == 0) ? p2v.x : (jj == 1) ? p2v.y : (jj == 2) ? p2v.z : p2v.w;
                float w3 = (jj == 0) ? p3.x : (jj == 1) ? p3.y : (jj == 2) ? p3.z : p3.w;
                a[0][0] += w0 * v0; a[0][1] += w0 * v1;
                a[1][0] += w1 * v0; a[1][1] += w1 * v1;
                a[2][0] += w2 * v0; a[2][1] += w2 * v1;
                a[3][0] += w3 * v0; a[3][1] += w3 * v1;
            }
        }
        {
            float v0 = Vs[196 * 64 + lane];
            float v1 = Vs[196 * 64 + lane + 32];
            #pragma unroll
            for (int qi = 0; qi < 4; qi++) {
                float w = Scw[qi * KT_S + 196];
                a[qi][0] += w * v0; a[qi][1] += w * v1;
            }
        }

        #pragma unroll
        for (int qi = 0; qi < 4; qi++) {
            if (qi >= nq) break;
            size_t ob = ((size_t)(b * SEQ + s0 + qi)) * DIM + h * HD;
            oh[ob + lane]      = __float2half_rn(a[qi][0]);
            oh[ob + lane + 32] = __float2half_rn(a[qi][1]);
        }
        __syncwarp();
    }
}

// ---------------- host orchestration ----------------
#define GS256 (NST * (256*RS*2 + 2*128*RS*2))   // 122880
#define GS128 (NST * (128*RS*2 + 2*128*RS*2))   // 92160

extern "C" void kernel_launch(void* const* d_in, const int* in_sizes, int n_in,
                              void* d_out, int out_size) {
    const float* images    = (const float*)d_in[0];
    const float* patch_W   = (const float*)d_in[1];
    const float* patch_b   = (const float*)d_in[2];
    const float* pos_emb   = (const float*)d_in[3];
    const float* cls       = (const float*)d_in[4];
    const float* ln1_g     = (const float*)d_in[5];
    const float* ln1_b     = (const float*)d_in[6];
    const float* Wq        = (const float*)d_in[7];
    const float* bq        = (const float*)d_in[8];
    const float* Wk        = (const float*)d_in[9];
    const float* bk        = (const float*)d_in[10];
    const float* Wv        = (const float*)d_in[11];
    const float* bv        = (const float*)d_in[12];
    const float* Wo        = (const float*)d_in[13];
    const float* bo        = (const float*)d_in[14];
    const float* ln2_g     = (const float*)d_in[15];
    const float* ln2_b     = (const float*)d_in[16];
    const float* W1        = (const float*)d_in[17];
    const float* b1        = (const float*)d_in[18];
    const float* W2        = (const float*)d_in[19];
    const float* b2        = (const float*)d_in[20];
    const float* head_g    = (const float*)d_in[21];
    const float* head_bn   = (const float*)d_in[22];
    const float* head_W    = (const float*)d_in[23];
    const float* head_bias = (const float*)d_in[24];

    float *x, *q, *k, *v;
    __half *xn, *oo, *hbuf, *pbuf, *cls16;
    __half *wpH, *wpL, *wqH, *wqL, *wkH, *wkL, *wvH, *wvL, *woH, *woL;
    __half *w1H, *w1L, *w2H, *w2L, *whH, *whL;
    cudaGetSymbolAddress((void**)&x,     g_x);
    cudaGetSymbolAddress((void**)&q,     g_q);
    cudaGetSymbolAddress((void**)&k,     g_k);
    cudaGetSymbolAddress((void**)&v,     g_v);
    cudaGetSymbolAddress((void**)&xn,    g_xn);
    cudaGetSymbolAddress((void**)&oo,    g_o);
    cudaGetSymbolAddress((void**)&hbuf,  g_h);
    cudaGetSymbolAddress((void**)&pbuf,  g_p);
    cudaGetSymbolAddress((void**)&cls16, g_cls16);
    cudaGetSymbolAddress((void**)&wpH, w_pat_h);cudaGetSymbolAddress((void**)&wpL, w_pat_l);
    cudaGetSymbolAddress((void**)&wqH, w_q_h);  cudaGetSymbolAddress((void**)&wqL, w_q_l);
    cudaGetSymbolAddress((void**)&wkH, w_k_h);  cudaGetSymbolAddress((void**)&wkL, w_k_l);
    cudaGetSymbolAddress((void**)&wvH, w_v_h);  cudaGetSymbolAddress((void**)&wvL, w_v_l);
    cudaGetSymbolAddress((void**)&woH, w_o_h);  cudaGetSymbolAddress((void**)&woL, w_o_l);
    cudaGetSymbolAddress((void**)&w1H, w_1_h);  cudaGetSymbolAddress((void**)&w1L, w_1_l);
    cudaGetSymbolAddress((void**)&w2H, w_2_h);  cudaGetSymbolAddress((void**)&w2L, w_2_l);
    cudaGetSymbolAddress((void**)&whH, w_hd_h); cudaGetSymbolAddress((void**)&whL, w_hd_l);

    cudaFuncSetAttribute(hgemm<256,4,2>, cudaFuncAttributeMaxDynamicSharedMemorySize, GS256);
    cudaFuncSetAttribute(hgemm<128,2,4>, cudaFuncAttributeMaxDynamicSharedMemorySize, GS128);
    cudaFuncSetAttribute(attn_fused, cudaFuncAttributeMaxDynamicSharedMemorySize, ASMEM);

    QKV dummy = {};

    dim3 tblk(32, 8);
    wprep<<<dim3(24, 24, 1),   tblk>>>(patch_W, wpH, wpL, DIM, DIM);
    wprep<<<dim3(2, 24, 144),  tblk>>>(Wq, wqH, wqL, DIM, HD);
    wprep<<<dim3(2, 24, 144),  tblk>>>(Wk, wkH, wkL, DIM, HD);
    wprep<<<dim3(2, 24, 144),  tblk>>>(Wv, wvH, wvL, DIM, HD);
    wprep<<<dim3(24, 24, 12),  tblk>>>(Wo, woH, woL, DIM, DIM);
    wprep<<<dim3(96, 24, 12),  tblk>>>(W1, w1H, w1L, DIM, FF);
    wprep<<<dim3(24, 96, 12),  tblk>>>(W2, w2H, w2L, FF, DIM);
    wprep<<<dim3(32, 24, 1),   tblk>>>(head_W, whH, whL, DIM, NCLS);

    patch_extract<<<(PTOK * DIM + 255) / 256, 256>>>(images, pbuf);
    hgemm<128,2,4><<<dim3(6, 49), 256, GS128>>>(
        pbuf, wpH, wpL, patch_b, pos_emb, x, nullptr,
        PTOK, DIM, DIM, 3, dummy);
    cls_fill<<<(BB * DIM + 255) / 256, 256>>>(cls, x);

    for (int l = 0; l < NL; l++) {
        size_t wo768 = (size_t)l * DIM * DIM;
        size_t woff  = (size_t)l * DIM * FF;

        ln_kernel<<<TOK, 256>>>(x, ln1_g + l * DIM, ln1_b + l * DIM, xn, DIM, DIM);

        QKV qk;
        qk.bh[0] = wqH + wo768; qk.bh[1] = wkH + wo768; qk.bh[2] = wvH + wo768;
        qk.bl[0] = wqL + wo768; qk.bl[1] = wkL + wo768; qk.bl[2] = wvL + wo768;
        qk.bias[0] = bq + l * DIM; qk.bias[1] = bk + l * DIM; qk.bias[2] = bv + l * DIM;
        qk.out[0] = q; qk.out[1] = k; qk.out[2] = v;
        hgemm<256,4,2><<<dim3(18, 25), 256, GS256>>>(
            xn, nullptr, nullptr, nullptr, nullptr, nullptr, nullptr,
            TOK, 2304, DIM, 4, qk);

        attn_fused<<<BB * NH, 256, ASMEM>>>(q, k, v, oo);

        hgemm<128,2,4><<<dim3(6, 50), 256, GS128>>>(
            oo, woH + wo768, woL + wo768, bo + l * DIM, x, x, nullptr,
            TOK, DIM, DIM, 1, dummy);

        ln_kernel<<<TOK, 256>>>(x, ln2_g + l * DIM, ln2_b + l * DIM, xn, DIM, DIM);

        hgemm<256,4,2><<<dim3(24, 25), 256, GS256>>>(
            xn, w1H + woff, w1L + woff, b1 + l * FF, nullptr, nullptr,
            hbuf, TOK, FF, DIM, 2, dummy);
        hgemm<128,2,4><<<dim3(6, 50), 256, GS128>>>(
            hbuf, w2H + woff, w2L + woff, b2 + l * DIM, x, x, nullptr,
            TOK, DIM, FF, 1, dummy);
    }

    ln_kernel<<<BB, 256>>>(x, head_g, head_bn, cls16, (long long)SEQ * DIM, DIM);
    hgemm<128,2,4><<<dim3(8, 1), 256, GS128>>>(
        cls16, whH, whL, head_bias, nullptr, (float*)d_out, nullptr,
        BB, NCLS, DIM, 0, dummy);
}

// round 11
// speedup vs baseline: 1.5111x; 1.1183x over previous
#include <cuda_runtime.h>
#include <cuda_fp16.h>
#include <cstdint>

#define BB 32
#define IMGSZ 224
#define PSZ 16
#define NSIDE 14
#define NPATCH 196
#define SEQ 197
#define DIM 768
#define NH 12
#define HD 64
#define FF 3072
#define NL 12
#define NCLS 1000
#define TOK (BB*SEQ)     // 6304
#define PTOK (BB*NPATCH) // 6272

// ---------------- scratch (device globals: allocation-free) ----------------
__device__ float  g_x[TOK*DIM];
__device__ __half g_q[TOK*DIM];
__device__ __half g_k[TOK*DIM];
__device__ __half g_v[TOK*DIM];

__device__ __half g_xn[TOK*DIM];
__device__ __half g_o[TOK*DIM];
__device__ __half g_h[(size_t)TOK*FF];
__device__ __half g_p[(size_t)PTOK*DIM];
__device__ __half g_cls16[BB*DIM];

// transposed fp16 hi/lo weights: [N][K] layout per layer
__device__ __half w_pat_h[589824],  w_pat_l[589824];
__device__ __half w_q_h[7077888],   w_q_l[7077888];
__device__ __half w_k_h[7077888],   w_k_l[7077888];
__device__ __half w_v_h[7077888],   w_v_l[7077888];
__device__ __half w_o_h[7077888],   w_o_l[7077888];
__device__ __half w_1_h[28311552],  w_1_l[28311552];
__device__ __half w_2_h[28311552],  w_2_l[28311552];
__device__ __half w_hd_h[768000],   w_hd_l[768000];

struct QKV {
    const __half* bh[3];
    const __half* bl[3];
    const float*  bias[3];
    __half*       out[3];
};

// ---------------- weight transpose + hi/lo split ----------------
__global__ void wprep(const float* __restrict__ in, __half* __restrict__ oh,
                      __half* __restrict__ ol, int K, int ng) {
    __shared__ float t[32][33];
    int g = blockIdx.z;
    int e0 = blockIdx.x * 32, k0 = blockIdx.y * 32;
    int tx = threadIdx.x, ty = threadIdx.y;  // 32x8
    const float* gin = in + (size_t)g * K * ng;
    #pragma unroll
    for (int i = 0; i < 4; i++) {
        int kk = k0 + ty + i * 8;
        int e  = e0 + tx;
        float v = 0.f;
        if (e < ng) v = gin[(size_t)kk * ng + e];
        t[ty + i * 8][tx] = v;
    }
    __syncthreads();
    __half* goh = oh + (size_t)g * ng * K;
    __half* gol = ol + (size_t)g * ng * K;
    #pragma unroll
    for (int i = 0; i < 4; i++) {
        int e  = e0 + ty + i * 8;
        int kk = k0 + tx;
        if (e < ng) {
            float v = t[tx][ty + i * 8];
            __half hv = __float2half_rn(v);
            goh[(size_t)e * K + kk] = hv;
            gol[(size_t)e * K + kk] = __float2half_rn(v - __half2float(hv));
        }
    }
}

// ---------------- patch extraction (fp16) ----------------
__global__ void patch_extract(const float* __restrict__ img,
                              __half* __restrict__ oh) {
    int idx = blockIdx.x * 256 + threadIdx.x;
    if (idx >= PTOK * DIM) return;
    int kcol = idx % DIM;
    int row  = idx / DIM;
    int b  = row / NPATCH;
    int p  = row % NPATCH;
    int pr = p / NSIDE, pc = p % NSIDE;
    int c  = kcol % 3;
    int t  = kcol / 3;
    int py = t / PSZ, px = t % PSZ;
    float v = img[(((size_t)(b*IMGSZ + pr*PSZ + py) * IMGSZ) + pc*PSZ + px) * 3 + c];
    oh[idx] = __float2half_rn(v);
}

__global__ void cls_fill(const float* __restrict__ cls, float* __restrict__ x) {
    int i = blockIdx.x * 256 + threadIdx.x;
    if (i < BB * DIM) x[(size_t)(i / DIM) * SEQ * DIM + (i % DIM)] = cls[i % DIM];
}

// ---------------- LayerNorm (fp32 in, fp16 out) ----------------
__global__ void ln_kernel(const float* __restrict__ x, const float* __restrict__ g,
                          const float* __restrict__ bt,
                          __half* __restrict__ yh,
                          long long in_stride, long long out_stride) {
    int row = blockIdx.x;
    int tid = threadIdx.x;
    const float* xr = x + (size_t)row * in_stride;
    float v0 = xr[tid], v1 = xr[tid + 256], v2 = xr[tid + 512];

    __shared__ float red1[8];
    __shared__ float red2[8];

    float s = v0 + v1 + v2;
    #pragma unroll
    for (int o = 16; o; o >>= 1) s += __shfl_xor_sync(0xffffffffu, s, o);
    if ((tid & 31) == 0) red1[tid >> 5] = s;
    __syncthreads();
    if (tid == 0) {
        float t = red1[0];
        #pragma unroll
        for (int i = 1; i < 8; i++) t += red1[i];
        red1[0] = t;
    }
    __syncthreads();
    float mean = red1[0] * (1.0f / 768.0f);

    float d0 = v0 - mean, d1 = v1 - mean, d2 = v2 - mean;
    float q = d0*d0 + d1*d1 + d2*d2;
    #pragma unroll
    for (int o = 16; o; o >>= 1) q += __shfl_xor_sync(0xffffffffu, q, o);
    if ((tid & 31) == 0) red2[tid >> 5] = q;
    __syncthreads();
    if (tid == 0) {
        float t = red2[0];
        #pragma unroll
        for (int i = 1; i < 8; i++) t += red2[i];
        red2[0] = t;
    }
    __syncthreads();
    float var = red2[0] * (1.0f / 768.0f);
    float r = rsqrtf(var + 1e-5f);

    size_t ob = (size_t)row * out_stride;
    #pragma unroll
    for (int c = 0; c < 3; c++) {
        float dd = (c == 0 ? d0 : (c == 1 ? d1 : d2));
        int col = tid + c * 256;
        yh[ob + col] = __float2half_rn(dd * r * g[col] + bt[col]);
    }
}

// ---------------- pipelined HMMA GEMM: 2-term (A fp16, B hi/lo) ----------------
#define RS 40                   // padded row stride (halfs): 80B
#define NST 3

__device__ __forceinline__ void cpa16(uint32_t sa, const void* ga, uint32_t ss) {
    asm volatile("cp.async.cg.shared.global [%0], [%1], 16, %2;"
                 :: "r"(sa), "l"(ga), "r"(ss) : "memory");
}

template<int BM>
__device__ __forceinline__ void load_stage(
    uint32_t sbase, const __half* __restrict__ A,
    const __half* __restrict__ Bh, const __half* __restrict__ Bl,
    int m0, int M, int n0, int N, int K, int k0, int tid)
{
    constexpr int ACH = BM * 4;
    constexpr int ATB = BM * RS * 2;
    constexpr int BTB = 128 * RS * 2;
    constexpr int CH_TOT = ACH + 1024;
    constexpr int PER_T = CH_TOT / 256;
    #pragma unroll
    for (int t = 0; t < PER_T; t++) {
        int ch = tid + t * 256;
        const __half* src; int r0, lim; uint32_t tb; int idx;
        if (ch < ACH)            { src = A;  r0 = m0; lim = M; tb = 0;         idx = ch; }
        else if (ch < ACH + 512) { src = Bh; r0 = n0; lim = N; tb = ATB;       idx = ch - ACH; }
        else                     { src = Bl; r0 = n0; lim = N; tb = ATB + BTB; idx = ch - ACH - 512; }
        int row = idx >> 2, c4 = idx & 3;
        int gr = r0 + row;
        uint32_t ss = 16u;
        if (gr >= lim) { gr = lim - 1; ss = 0u; }
        const void* ga = src + (size_t)gr * K + k0 + c4 * 8;
        uint32_t sa = sbase + tb + (uint32_t)(row * RS + c4 * 8) * 2;
        cpa16(sa, ga, ss);
    }
}

#define LDSM_X4(r0, r1, r2, r3, addr) \
    asm volatile("ldmatrix.sync.aligned.m8n8.x4.shared.b16 {%0,%1,%2,%3}, [%4];" \
                 : "=r"(r0), "=r"(r1), "=r"(r2), "=r"(r3) : "r"(addr))

#define LDSM_X2(r0, r1, addr) \
    asm volatile("ldmatrix.sync.aligned.m8n8.x2.shared.b16 {%0,%1}, [%2];" \
                 : "=r"(r0), "=r"(r1) : "r"(addr))

#define MMA16816(c, a, b) \
    asm volatile("mma.sync.aligned.m16n8k16.row.col.f32.f16.f16.f32 " \
                 "{%0,%1,%2,%3}, {%4,%5,%6,%7}, {%8,%9}, {%0,%1,%2,%3};" \
                 : "+f"((c)[0]), "+f"((c)[1]), "+f"((c)[2]), "+f"((c)[3]) \
                 : "r"((a)[0]), "r"((a)[1]), "r"((a)[2]), "r"((a)[3]), \
                   "r"((b)[0]), "r"((b)[1]))

// ep: 0=+bias fp32 | 1=+bias+residual | 2=gelu->fp16 | 3=patch embed | 4=fused QKV (fp16 out)
template<int BM, int WROWS, int WCOLS>
__global__ __launch_bounds__(256) void hgemm(
    const __half* __restrict__ A,
    const __half* __restrict__ Bh, const __half* __restrict__ Bl,
    const float* __restrict__ bias, const float* __restrict__ extra,
    float* __restrict__ Cf, __half* __restrict__ Choh,
    int M, int N, int K, int ep, QKV qkv)
{
    constexpr int WTILE_M = BM / WROWS;
    constexpr int WTM     = WTILE_M / 16;
    constexpr int WTILE_N = 128 / WCOLS;
    constexpr int WTN     = WTILE_N / 8;
    constexpr int ATB  = BM * RS * 2;
    constexpr int BTB  = 128 * RS * 2;
    constexpr int STGB = ATB + 2 * BTB;

    extern __shared__ __align__(16) char dsm[];
    uint32_t sb = (uint32_t)__cvta_generic_to_shared(dsm);
    int tid = threadIdx.x, wid = tid >> 5, lane = tid & 31;
    int warp_m = wid / WCOLS, warp_n = wid % WCOLS;
    int m0 = blockIdx.y * BM;
    int n0 = blockIdx.x * 128;
    int Nl = N;
    int epe = ep;
    const __half* Bh_ = Bh; const __half* Bl_ = Bl;
    const float* bias_ = bias; float* Cf_ = Cf; __half* Ch_ = Choh;
    if (ep == 4) {
        int seg = n0 / 768;
        Bh_ = qkv.bh[seg]; Bl_ = qkv.bl[seg];
        bias_ = qkv.bias[seg]; Ch_ = qkv.out[seg];
        n0 -= seg * 768; Nl = 768; epe = 6;
    }
    int wrow = warp_m * WTILE_M, wcol = warp_n * WTILE_N;

    float acc[WTM][WTN][4];
    #pragma unroll
    for (int i = 0; i < WTM; i++)
        #pragma unroll
        for (int j = 0; j < WTN; j++)
            #pragma unroll
            for (int r = 0; r < 4; r++) acc[i][j][r] = 0.0f;

    int NC = K >> 5;

    #pragma unroll
    for (int s = 0; s < NST - 1; s++) {
        load_stage<BM>(sb + s * STGB, A, Bh_, Bl_, m0, M, n0, Nl, K, s * 32, tid);
        asm volatile("cp.async.commit_group;" ::: "memory");
    }

    int a_off = (wrow + (lane & 15)) * RS + ((lane >> 4) << 3);
    int b_off = (wcol + (lane & 7) + ((lane >> 4) & 1) * 8) * RS
              + ((lane >> 3) & 1) * 8;

    for (int c = 0; c < NC; c++) {
        asm volatile("cp.async.wait_group 1;" ::: "memory");
        __syncthreads();

        int pf = c + NST - 1;
        if (pf < NC) {
            load_stage<BM>(sb + (pf % NST) * STGB, A, Bh_, Bl_, m0, M, n0, Nl, K,
                           pf * 32, tid);
        }
        asm volatile("cp.async.commit_group;" ::: "memory");

        uint32_t stg = sb + (c % NST) * STGB;
        uint32_t sA  = stg;
        uint32_t sBh = stg + ATB;
        uint32_t sBl = stg + ATB + BTB;

        #pragma unroll
        for (int ks = 0; ks < 2; ks++) {
            uint32_t a[WTM][4], bh[WTN][2], bl[WTN][2];
            #pragma unroll
            for (int mt = 0; mt < WTM; mt++) {
                uint32_t ad = sA + (uint32_t)(a_off + mt * 16 * RS + ks * 16) * 2;
                LDSM_X4(a[mt][0], a[mt][1], a[mt][2], a[mt][3], ad);
            }
            #pragma unroll
            for (int nb = 0; nb < WTN / 2; nb++) {
                uint32_t bd = sBh + (uint32_t)(b_off + nb * 16 * RS + ks * 16) * 2;
                LDSM_X4(bh[nb*2][0], bh[nb*2][1], bh[nb*2+1][0], bh[nb*2+1][1], bd);
                bd = sBl + (uint32_t)(b_off + nb * 16 * RS + ks * 16) * 2;
                LDSM_X4(bl[nb*2][0], bl[nb*2][1], bl[nb*2+1][0], bl[nb*2+1][1], bd);
            }
            #pragma unroll
            for (int mt = 0; mt < WTM; mt++)
                #pragma unroll
                for (int nt = 0; nt < WTN; nt++) MMA16816(acc[mt][nt], a[mt], bh[nt]);
            #pragma unroll
            for (int mt = 0; mt < WTM; mt++)
                #pragma unroll
                for (int nt = 0; nt < WTN; nt++) MMA16816(acc[mt][nt], a[mt], bl[nt]);
        }
    }

    // ---------------- epilogue ----------------
    int r  = lane >> 2;
    int c2 = (lane & 3) * 2;
    #pragma unroll
    for (int mt = 0; mt < WTM; mt++) {
        #pragma unroll
        for (int nt = 0; nt < WTN; nt++) {
            int n = n0 + wcol + nt * 8 + c2;
            if (n >= Nl) continue;
            float bn0 = bias_[n], bn1 = bias_[n + 1];
            #pragma unroll
            for (int hh = 0; hh < 2; hh++) {
                int m = m0 + wrow + mt * 16 + r + hh * 8;
                if (m >= M) continue;
                float v0 = acc[mt][nt][hh * 2 + 0] + bn0;
                float v1 = acc[mt][nt][hh * 2 + 1] + bn1;
                if (epe == 0) {
                    *reinterpret_cast<float2*>(&Cf_[(size_t)m * Nl + n]) =
                        make_float2(v0, v1);
                } else if (epe == 6) {
                    *reinterpret_cast<__half2*>(&Ch_[(size_t)m * Nl + n]) =
                        __halves2half2(__float2half_rn(v0), __float2half_rn(v1));
                } else if (epe == 1) {
                    float2 e = *reinterpret_cast<const float2*>(&extra[(size_t)m * Nl + n]);
                    *reinterpret_cast<float2*>(&Cf_[(size_t)m * Nl + n]) =
                        make_float2(v0 + e.x, v1 + e.y);
                } else if (epe == 2) {
                    v0 = 0.5f * v0 * (1.0f + erff(v0 * 0.70710678118654752f));
                    v1 = 0.5f * v1 * (1.0f + erff(v1 * 0.70710678118654752f));
                    *reinterpret_cast<__half2*>(&Ch_[(size_t)m * Nl + n]) =
                        __halves2half2(__float2half_rn(v0), __float2half_rn(v1));
                } else {
                    int bb = m / NPATCH, p = m % NPATCH;
                    float2 e = *reinterpret_cast<const float2*>(&extra[(size_t)p * DIM + n]);
                    *reinterpret_cast<float2*>(
                        &Cf_[((size_t)(bb * SEQ + p + 1)) * DIM + n]) =
                        make_float2(v0 + e.x, v1 + e.y);
                }
            }
        }
    }
}

// ---------------- tensor-core attention ----------------
// per (b,h) CTA: S = QK^T (mma, fp32 acc) -> smem fp32 -> softmax -> P fp16 -> O = P V^T (mma)
#define SP 208
#define QK_RS 72     // Qs/Ks row stride (halfs), 144B
#define PT_RS 216    // P/VT row stride (halfs), 432B
#define S_RS 212     // S row stride (floats), 848B
#define MPASS 96
#define QS_OFF 0
#define KS_OFF 29952
#define VT_OFF 59904
#define S_OFF  87552
#define P_OFF  168960
#define AMEM   210432

__global__ __launch_bounds__(256) void attn_mma(
    const __half* __restrict__ q, const __half* __restrict__ k,
    const __half* __restrict__ v, __half* __restrict__ oh)
{
    extern __shared__ __align__(16) char dsm[];
    uint32_t sb = (uint32_t)__cvta_generic_to_shared(dsm);
    int bh = blockIdx.x, b = bh / NH, h = bh % NH;
    int tid = threadIdx.x, wid = tid >> 5, lane = tid & 31;

    const __half* qg = q + (size_t)b * SEQ * DIM + h * HD;
    const __half* kg = k + (size_t)b * SEQ * DIM + h * HD;
    const __half* vg = v + (size_t)b * SEQ * DIM + h * HD;

    // Q,K -> smem (16B chunks), zero pad rows 197..207
    for (int ch = tid; ch < SP * 8; ch += 256) {
        int row = ch >> 3, c8 = (ch & 7) * 8;
        uint32_t qa = sb + QS_OFF + (uint32_t)(row * QK_RS + c8) * 2;
        uint32_t ka = sb + KS_OFF + (uint32_t)(row * QK_RS + c8) * 2;
        if (row < SEQ) {
            cpa16(qa, qg + (size_t)row * DIM + c8, 16);
            cpa16(ka, kg + (size_t)row * DIM + c8, 16);
        } else {
            asm volatile("st.shared.v4.b32 [%0], {%1,%1,%1,%1};"
                         :: "r"(qa), "r"(0) : "memory");
            asm volatile("st.shared.v4.b32 [%0], {%1,%1,%1,%1};"
                         :: "r"(ka), "r"(0) : "memory");
        }
    }
    asm volatile("cp.async.commit_group;" ::: "memory");
    // V transposed: VT[e][j]
    for (int i = tid; i < SP * 64; i += 256) {
        int e = i & 63, j = i >> 6;
        __half val = (j < SEQ) ? vg[(size_t)j * DIM + e] : __ushort_as_half((uint16_t)0);
        uint16_t bits = __half_as_ushort(val);
        asm volatile("st.shared.u16 [%0], %1;"
                     :: "r"(sb + VT_OFF + (uint32_t)(e * PT_RS + j) * 2), "h"(bits)
                     : "memory");
    }
    asm volatile("cp.async.wait_group 0;" ::: "memory");
    __syncthreads();

    // key pair assignment: 13 pairs of 16 cols over 8 warps
    int p0   = (wid < 5) ? 2 * wid : 10 + (wid - 5);
    int pcnt = (wid < 5) ? 2 : 1;
    int r4 = lane >> 2, c2 = (lane & 3) * 2;

    for (int m0 = 0; m0 < SEQ; m0 += MPASS) {
        int mt_cnt = (SEQ - m0 + 15) >> 4; if (mt_cnt > 6) mt_cnt = 6;

        // ---- S = Q K^T ----
        float acc[6][4][4];
        #pragma unroll
        for (int i = 0; i < 6; i++)
            #pragma unroll
            for (int j = 0; j < 4; j++)
                #pragma unroll
                for (int r = 0; r < 4; r++) acc[i][j][r] = 0.f;
        #pragma unroll
        for (int ks = 0; ks < 4; ks++) {
            uint32_t a[6][4];
            for (int mt = 0; mt < mt_cnt; mt++) {
                uint32_t ad = sb + QS_OFF + (uint32_t)(
                    (m0 + mt * 16 + (lane & 15)) * QK_RS + ((lane >> 4) << 3) + ks * 16) * 2;
                LDSM_X4(a[mt][0], a[mt][1], a[mt][2], a[mt][3], ad);
            }
            for (int p = 0; p < pcnt; p++) {
                uint32_t b0[2], b1[2];
                uint32_t bd = sb + KS_OFF + (uint32_t)(
                    ((p0 + p) * 16 + (lane & 7) + ((lane >> 4) & 1) * 8) * QK_RS
                    + ((lane >> 3) & 1) * 8 + ks * 16) * 2;
                LDSM_X4(b0[0], b0[1], b1[0], b1[1], bd);
                for (int mt = 0; mt < mt_cnt; mt++) {
                    MMA16816(acc[mt][p * 2 + 0], a[mt], b0);
                    MMA16816(acc[mt][p * 2 + 1], a[mt], b1);
                }
            }
        }
        // write S to smem
        for (int mt = 0; mt < mt_cnt; mt++)
            for (int p = 0; p < pcnt; p++)
                #pragma unroll
                for (int t = 0; t < 2; t++) {
                    int col = (p0 + p) * 16 + t * 8 + c2;
                    #pragma unroll
                    for (int hh = 0; hh < 2; hh++) {
                        int row = mt * 16 + r4 + hh * 8;
                        *reinterpret_cast<float2*>(
                            dsm + S_OFF + ((size_t)row * S_RS + col) * 4) =
                            make_float2(acc[mt][p*2+t][hh*2], acc[mt][p*2+t][hh*2+1]);
                    }
                }
        __syncthreads();

        // ---- softmax rows ----
        int rows = mt_cnt * 16;
        for (int r = wid; r < rows; r += 8) {
            const float* Srow = reinterpret_cast<const float*>(dsm + S_OFF + (size_t)r * S_RS * 4);
            float mx = -3.0e38f;
            for (int c = lane; c < SEQ; c += 32)
                mx = fmaxf(mx, Srow[c] * 0.125f);
            #pragma unroll
            for (int o = 16; o; o >>= 1) mx = fmaxf(mx, __shfl_xor_sync(0xffffffffu, mx, o));
            float pv[7];
            int cnt = 0;
            float sum = 0.f;
            for (int c = lane; c < SEQ; c += 32) {
                float p = __expf(Srow[c] * 0.125f - mx);
                pv[cnt++] = p; sum += p;
            }
            #pragma unroll
            for (int o = 16; o; o >>= 1) sum += __shfl_xor_sync(0xffffffffu, sum, o);
            float inv = 1.0f / sum;
            __half* Prow = reinterpret_cast<__half*>(dsm + P_OFF + (size_t)r * PT_RS * 2);
            cnt = 0;
            for (int c = lane; c < PT_RS; c += 32) {
                __half val;
                if (c < SEQ) { val = __float2half_rn(pv[cnt] * inv); cnt++; }
                else val = __ushort_as_half((uint16_t)0);
                Prow[c] = val;
            }
        }
        __syncthreads();

        // ---- O = P V^T  (warp = 8 output cols) ----
        float oacc[6][4];
        #pragma unroll
        for (int i = 0; i < 6; i++)
            #pragma unroll
            for (int r = 0; r < 4; r++) oacc[i][r] = 0.f;
        int l = lane & 15;
        for (int ks = 0; ks < 13; ks++) {
            uint32_t a[6][4];
            for (int mt = 0; mt < mt_cnt; mt++) {
                uint32_t ad = sb + P_OFF + (uint32_t)(
                    (mt * 16 + (lane & 15)) * PT_RS + ((lane >> 4) << 3) + ks * 16) * 2;
                LDSM_X4(a[mt][0], a[mt][1], a[mt][2], a[mt][3], ad);
            }
            uint32_t bfr[2];
            uint32_t bd = sb + VT_OFF + (uint32_t)(
                (wid * 8 + (l & 7)) * PT_RS + ((l >> 3) & 1) * 8 + ks * 16) * 2;
            LDSM_X2(bfr[0], bfr[1], bd);
            for (int mt = 0; mt < mt_cnt; mt++)
                MMA16816(oacc[mt], a[mt], bfr);
        }
        // write O
        for (int mt = 0; mt < mt_cnt; mt++)
            #pragma unroll
            for (int hh = 0; hh < 2; hh++) {
                int gr = m0 + mt * 16 + r4 + hh * 8;
                if (gr >= SEQ) continue;
                *reinterpret_cast<__half2*>(
                    &oh[((size_t)(b * SEQ + gr)) * DIM + h * HD + wid * 8 + c2]) =
                    __halves2half2(__float2half_rn(oacc[mt][hh*2]),
                                   __float2half_rn(oacc[mt][hh*2+1]));
            }
        __syncthreads();
    }
}

// ---------------- host orchestration ----------------
#define GS256 (NST * (256*RS*2 + 2*128*RS*2))   // 122880
#define GS128 (NST * (128*RS*2 + 2*128*RS*2))   // 92160

extern "C" void kernel_launch(void* const* d_in, const int* in_sizes, int n_in,
                              void* d_out, int out_size) {
    const float* images    = (const float*)d_in[0];
    const float* patch_W   = (const float*)d_in[1];
    const float* patch_b   = (const float*)d_in[2];
    const float* pos_emb   = (const float*)d_in[3];
    const float* cls       = (const float*)d_in[4];
    const float* ln1_g     = (const float*)d_in[5];
    const float* ln1_b     = (const float*)d_in[6];
    const float* Wq        = (const float*)d_in[7];
    const float* bq        = (const float*)d_in[8];
    const float* Wk        = (const float*)d_in[9];
    const float* bk        = (const float*)d_in[10];
    const float* Wv        = (const float*)d_in[11];
    const float* bv        = (const float*)d_in[12];
    const float* Wo        = (const float*)d_in[13];
    const float* bo        = (const float*)d_in[14];
    const float* ln2_g     = (const float*)d_in[15];
    const float* ln2_b     = (const float*)d_in[16];
    const float* W1        = (const float*)d_in[17];
    const float* b1        = (const float*)d_in[18];
    const float* W2        = (const float*)d_in[19];
    const float* b2        = (const float*)d_in[20];
    const float* head_g    = (const float*)d_in[21];
    const float* head_bn   = (const float*)d_in[22];
    const float* head_W    = (const float*)d_in[23];
    const float* head_bias = (const float*)d_in[24];

    float *x;
    __half *q16, *k16, *v16;
    __half *xn, *oo, *hbuf, *pbuf, *cls16;
    __half *wpH, *wpL, *wqH, *wqL, *wkH, *wkL, *wvH, *wvL, *woH, *woL;
    __half *w1H, *w1L, *w2H, *w2L, *whH, *whL;
    cudaGetSymbolAddress((void**)&x,     g_x);
    cudaGetSymbolAddress((void**)&q16,   g_q);
    cudaGetSymbolAddress((void**)&k16,   g_k);
    cudaGetSymbolAddress((void**)&v16,   g_v);
    cudaGetSymbolAddress((void**)&xn,    g_xn);
    cudaGetSymbolAddress((void**)&oo,    g_o);
    cudaGetSymbolAddress((void**)&hbuf,  g_h);
    cudaGetSymbolAddress((void**)&pbuf,  g_p);
    cudaGetSymbolAddress((void**)&cls16, g_cls16);
    cudaGetSymbolAddress((void**)&wpH, w_pat_h);cudaGetSymbolAddress((void**)&wpL, w_pat_l);
    cudaGetSymbolAddress((void**)&wqH, w_q_h);  cudaGetSymbolAddress((void**)&wqL, w_q_l);
    cudaGetSymbolAddress((void**)&wkH, w_k_h);  cudaGetSymbolAddress((void**)&wkL, w_k_l);
    cudaGetSymbolAddress((void**)&wvH, w_v_h);  cudaGetSymbolAddress((void**)&wvL, w_v_l);
    cudaGetSymbolAddress((void**)&woH, w_o_h);  cudaGetSymbolAddress((void**)&woL, w_o_l);
    cudaGetSymbolAddress((void**)&w1H, w_1_h);  cudaGetSymbolAddress((void**)&w1L, w_1_l);
    cudaGetSymbolAddress((void**)&w2H, w_2_h);  cudaGetSymbolAddress((void**)&w2L, w_2_l);
    cudaGetSymbolAddress((void**)&whH, w_hd_h); cudaGetSymbolAddress((void**)&whL, w_hd_l);

    cudaFuncSetAttribute(hgemm<256,4,2>, cudaFuncAttributeMaxDynamicSharedMemorySize, GS256);
    cudaFuncSetAttribute(hgemm<128,2,4>, cudaFuncAttributeMaxDynamicSharedMemorySize, GS128);
    cudaFuncSetAttribute(attn_mma, cudaFuncAttributeMaxDynamicSharedMemorySize, AMEM);

    QKV dummy = {};

    dim3 tblk(32, 8);
    wprep<<<dim3(24, 24, 1),   tblk>>>(patch_W, wpH, wpL, DIM, DIM);
    wprep<<<dim3(2, 24, 144),  tblk>>>(Wq, wqH, wqL, DIM, HD);
    wprep<<<dim3(2, 24, 144),  tblk>>>(Wk, wkH, wkL, DIM, HD);
    wprep<<<dim3(2, 24, 144),  tblk>>>(Wv, wvH, wvL, DIM, HD);
    wprep<<<dim3(24, 24, 12),  tblk>>>(Wo, woH, woL, DIM, DIM);
    wprep<<<dim3(96, 24, 12),  tblk>>>(W1, w1H, w1L, DIM, FF);
    wprep<<<dim3(24, 96, 12),  tblk>>>(W2, w2H, w2L, FF, DIM);
    wprep<<<dim3(32, 24, 1),   tblk>>>(head_W, whH, whL, DIM, NCLS);

    patch_extract<<<(PTOK * DIM + 255) / 256, 256>>>(images, pbuf);
    hgemm<128,2,4><<<dim3(6, 49), 256, GS128>>>(
        pbuf, wpH, wpL, patch_b, pos_emb, x, nullptr,
        PTOK, DIM, DIM, 3, dummy);
    cls_fill<<<(BB * DIM + 255) / 256, 256>>>(cls, x);

    for (int l = 0; l < NL; l++) {
        size_t wo768 = (size_t)l * DIM * DIM;
        size_t woff  = (size_t)l * DIM * FF;

        ln_kernel<<<TOK, 256>>>(x, ln1_g + l * DIM, ln1_b + l * DIM, xn, DIM, DIM);

        QKV qk;
        qk.bh[0] = wqH + wo768; qk.bh[1] = wkH + wo768; qk.bh[2] = wvH + wo768;
        qk.bl[0] = wqL + wo768; qk.bl[1] = wkL + wo768; qk.bl[2] = wvL + wo768;
        qk.bias[0] = bq + l * DIM; qk.bias[1] = bk + l * DIM; qk.bias[2] = bv + l * DIM;
        qk.out[0] = q16; qk.out[1] = k16; qk.out[2] = v16;
        hgemm<256,4,2><<<dim3(18, 25), 256, GS256>>>(
            xn, nullptr, nullptr, nullptr, nullptr, nullptr, nullptr,
            TOK, 2304, DIM, 4, qk);

        attn_mma<<<BB * NH, 256, AMEM>>>(q16, k16, v16, oo);

        hgemm<128,2,4><<<dim3(6, 50), 256, GS128>>>(
            oo, woH + wo768, woL + wo768, bo + l * DIM, x, x, nullptr,
            TOK, DIM, DIM, 1, dummy);

        ln_kernel<<<TOK, 256>>>(x, ln2_g + l * DIM, ln2_b + l * DIM, xn, DIM, DIM);

        hgemm<256,4,2><<<dim3(24, 25), 256, GS256>>>(
            xn, w1H + woff, w1L + woff, b1 + l * FF, nullptr, nullptr,
            hbuf, TOK, FF, DIM, 2, dummy);
        hgemm<128,2,4><<<dim3(6, 50), 256, GS128>>>(
            hbuf, w2H + woff, w2L + woff, b2 + l * DIM, x, x, nullptr,
            TOK, DIM, FF, 1, dummy);
    }

    ln_kernel<<<BB, 256>>>(x, head_g, head_bn, cls16, (long long)SEQ * DIM, DIM);
    hgemm<128,2,4><<<dim3(8, 1), 256, GS128>>>(
        cls16, whH, whL, head_bias, nullptr, (float*)d_out, nullptr,
        BB, NCLS, DIM, 0, dummy);
}

// round 12
// speedup vs baseline: 1.5178x; 1.0044x over previous
#include <cuda_runtime.h>
#include <cuda_fp16.h>
#include <cstdint>

#define BB 32
#define IMGSZ 224
#define PSZ 16
#define NSIDE 14
#define NPATCH 196
#define SEQ 197
#define DIM 768
#define NH 12
#define HD 64
#define FF 3072
#define NL 12
#define NCLS 1000
#define TOK (BB*SEQ)     // 6304
#define PTOK (BB*NPATCH) // 6272

// ---------------- scratch (device globals: allocation-free) ----------------
__device__ float  g_x[TOK*DIM];
__device__ __half g_q[TOK*DIM];
__device__ __half g_k[TOK*DIM];
__device__ __half g_v[TOK*DIM];

__device__ __half g_xn[TOK*DIM];
__device__ __half g_o[TOK*DIM];
__device__ __half g_h[(size_t)TOK*FF];
__device__ __half g_p[(size_t)PTOK*DIM];
__device__ __half g_cls16[BB*DIM];

// transposed fp16 hi/lo weights: [N][K] layout per layer
__device__ __half w_pat_h[589824],  w_pat_l[589824];
__device__ __half w_q_h[7077888],   w_q_l[7077888];
__device__ __half w_k_h[7077888],   w_k_l[7077888];
__device__ __half w_v_h[7077888],   w_v_l[7077888];
__device__ __half w_o_h[7077888],   w_o_l[7077888];
__device__ __half w_1_h[28311552],  w_1_l[28311552];
__device__ __half w_2_h[28311552],  w_2_l[28311552];
__device__ __half w_hd_h[768000],   w_hd_l[768000];

struct QKV {
    const __half* bh[3];
    const __half* bl[3];
    const float*  bias[3];
    __half*       out[3];
};

// ---------------- weight transpose + hi/lo split ----------------
__global__ void wprep(const float* __restrict__ in, __half* __restrict__ oh,
                      __half* __restrict__ ol, int K, int ng) {
    __shared__ float t[32][33];
    int g = blockIdx.z;
    int e0 = blockIdx.x * 32, k0 = blockIdx.y * 32;
    int tx = threadIdx.x, ty = threadIdx.y;  // 32x8
    const float* gin = in + (size_t)g * K * ng;
    #pragma unroll
    for (int i = 0; i < 4; i++) {
        int kk = k0 + ty + i * 8;
        int e  = e0 + tx;
        float v = 0.f;
        if (e < ng) v = gin[(size_t)kk * ng + e];
        t[ty + i * 8][tx] = v;
    }
    __syncthreads();
    __half* goh = oh + (size_t)g * ng * K;
    __half* gol = ol + (size_t)g * ng * K;
    #pragma unroll
    for (int i = 0; i < 4; i++) {
        int e  = e0 + ty + i * 8;
        int kk = k0 + tx;
        if (e < ng) {
            float v = t[tx][ty + i * 8];
            __half hv = __float2half_rn(v);
            goh[(size_t)e * K + kk] = hv;
            gol[(size_t)e * K + kk] = __float2half_rn(v - __half2float(hv));
        }
    }
}

// ---------------- patch extraction (fp16) ----------------
__global__ void patch_extract(const float* __restrict__ img,
                              __half* __restrict__ oh) {
    int idx = blockIdx.x * 256 + threadIdx.x;
    if (idx >= PTOK * DIM) return;
    int kcol = idx % DIM;
    int row  = idx / DIM;
    int b  = row / NPATCH;
    int p  = row % NPATCH;
    int pr = p / NSIDE, pc = p % NSIDE;
    int c  = kcol % 3;
    int t  = kcol / 3;
    int py = t / PSZ, px = t % PSZ;
    float v = img[(((size_t)(b*IMGSZ + pr*PSZ + py) * IMGSZ) + pc*PSZ + px) * 3 + c];
    oh[idx] = __float2half_rn(v);
}

__global__ void cls_fill(const float* __restrict__ cls, float* __restrict__ x) {
    int i = blockIdx.x * 256 + threadIdx.x;
    if (i < BB * DIM) x[(size_t)(i / DIM) * SEQ * DIM + (i % DIM)] = cls[i % DIM];
}

// ---------------- LayerNorm (fp32 in, fp16 out) ----------------
__global__ void ln_kernel(const float* __restrict__ x, const float* __restrict__ g,
                          const float* __restrict__ bt,
                          __half* __restrict__ yh,
                          long long in_stride, long long out_stride) {
    int row = blockIdx.x;
    int tid = threadIdx.x;
    const float* xr = x + (size_t)row * in_stride;
    float v0 = xr[tid], v1 = xr[tid + 256], v2 = xr[tid + 512];

    __shared__ float red1[8];
    __shared__ float red2[8];

    float s = v0 + v1 + v2;
    #pragma unroll
    for (int o = 16; o; o >>= 1) s += __shfl_xor_sync(0xffffffffu, s, o);
    if ((tid & 31) == 0) red1[tid >> 5] = s;
    __syncthreads();
    if (tid == 0) {
        float t = red1[0];
        #pragma unroll
        for (int i = 1; i < 8; i++) t += red1[i];
        red1[0] = t;
    }
    __syncthreads();
    float mean = red1[0] * (1.0f / 768.0f);

    float d0 = v0 - mean, d1 = v1 - mean, d2 = v2 - mean;
    float q = d0*d0 + d1*d1 + d2*d2;
    #pragma unroll
    for (int o = 16; o; o >>= 1) q += __shfl_xor_sync(0xffffffffu, q, o);
    if ((tid & 31) == 0) red2[tid >> 5] = q;
    __syncthreads();
    if (tid == 0) {
        float t = red2[0];
        #pragma unroll
        for (int i = 1; i < 8; i++) t += red2[i];
        red2[0] = t;
    }
    __syncthreads();
    float var = red2[0] * (1.0f / 768.0f);
    float r = rsqrtf(var + 1e-5f);

    size_t ob = (size_t)row * out_stride;
    #pragma unroll
    for (int c = 0; c < 3; c++) {
        float dd = (c == 0 ? d0 : (c == 1 ? d1 : d2));
        int col = tid + c * 256;
        yh[ob + col] = __float2half_rn(dd * r * g[col] + bt[col]);
    }
}

// ---------------- pipelined HMMA GEMM: 2-term (A fp16, B hi/lo) ----------------
#define RS 40                   // padded row stride (halfs): 80B
#define NST 3

__device__ __forceinline__ void cpa16(uint32_t sa, const void* ga, uint32_t ss) {
    asm volatile("cp.async.cg.shared.global [%0], [%1], 16, %2;"
                 :: "r"(sa), "l"(ga), "r"(ss) : "memory");
}

template<int BM, int BN>
__device__ __forceinline__ void load_stage(
    uint32_t sbase, const __half* __restrict__ A,
    const __half* __restrict__ Bh, const __half* __restrict__ Bl,
    int m0, int M, int n0, int N, int K, int k0, int tid)
{
    constexpr int ACH = BM * 4;
    constexpr int BCH = BN * 4;
    constexpr int ATB = BM * RS * 2;
    constexpr int BTB = BN * RS * 2;
    constexpr int CH_TOT = ACH + 2 * BCH;
    constexpr int PER_T = CH_TOT / 256;
    #pragma unroll
    for (int t = 0; t < PER_T; t++) {
        int ch = tid + t * 256;
        const __half* src; int r0, lim; uint32_t tb; int idx;
        if (ch < ACH)            { src = A;  r0 = m0; lim = M; tb = 0;         idx = ch; }
        else if (ch < ACH + BCH) { src = Bh; r0 = n0; lim = N; tb = ATB;       idx = ch - ACH; }
        else                     { src = Bl; r0 = n0; lim = N; tb = ATB + BTB; idx = ch - ACH - BCH; }
        int row = idx >> 2, c4 = idx & 3;
        int gr = r0 + row;
        uint32_t ss = 16u;
        if (gr >= lim) { gr = lim - 1; ss = 0u; }
        const void* ga = src + (size_t)gr * K + k0 + c4 * 8;
        uint32_t sa = sbase + tb + (uint32_t)(row * RS + c4 * 8) * 2;
        cpa16(sa, ga, ss);
    }
}

#define LDSM_X4(r0, r1, r2, r3, addr) \
    asm volatile("ldmatrix.sync.aligned.m8n8.x4.shared.b16 {%0,%1,%2,%3}, [%4];" \
                 : "=r"(r0), "=r"(r1), "=r"(r2), "=r"(r3) : "r"(addr))

#define LDSM_X2(r0, r1, addr) \
    asm volatile("ldmatrix.sync.aligned.m8n8.x2.shared.b16 {%0,%1}, [%2];" \
                 : "=r"(r0), "=r"(r1) : "r"(addr))

#define MMA16816(c, a, b) \
    asm volatile("mma.sync.aligned.m16n8k16.row.col.f32.f16.f16.f32 " \
                 "{%0,%1,%2,%3}, {%4,%5,%6,%7}, {%8,%9}, {%0,%1,%2,%3};" \
                 : "+f"((c)[0]), "+f"((c)[1]), "+f"((c)[2]), "+f"((c)[3]) \
                 : "r"((a)[0]), "r"((a)[1]), "r"((a)[2]), "r"((a)[3]), \
                   "r"((b)[0]), "r"((b)[1]))

// ep: 0=+bias fp32 | 1=+bias+residual | 2=gelu->fp16 | 3=patch embed | 4=fused QKV (fp16 out)
template<int BM, int BN, int WROWS, int WCOLS>
__global__ __launch_bounds__(256) void hgemm(
    const __half* __restrict__ A,
    const __half* __restrict__ Bh, const __half* __restrict__ Bl,
    const float* __restrict__ bias, const float* __restrict__ extra,
    float* __restrict__ Cf, __half* __restrict__ Choh,
    int M, int N, int K, int ep, QKV qkv)
{
    constexpr int WTILE_M = BM / WROWS;
    constexpr int WTM     = WTILE_M / 16;
    constexpr int WTILE_N = BN / WCOLS;
    constexpr int WTN     = WTILE_N / 8;
    constexpr int ATB  = BM * RS * 2;
    constexpr int BTB  = BN * RS * 2;
    constexpr int STGB = ATB + 2 * BTB;

    extern __shared__ __align__(16) char dsm[];
    uint32_t sb = (uint32_t)__cvta_generic_to_shared(dsm);
    int tid = threadIdx.x, wid = tid >> 5, lane = tid & 31;
    int warp_m = wid / WCOLS, warp_n = wid % WCOLS;
    int m0 = blockIdx.y * BM;
    int n0 = blockIdx.x * BN;
    int Nl = N;
    int epe = ep;
    const __half* Bh_ = Bh; const __half* Bl_ = Bl;
    const float* bias_ = bias; float* Cf_ = Cf; __half* Ch_ = Choh;
    if (ep == 4) {
        int seg = n0 / 768;
        Bh_ = qkv.bh[seg]; Bl_ = qkv.bl[seg];
        bias_ = qkv.bias[seg]; Ch_ = qkv.out[seg];
        n0 -= seg * 768; Nl = 768; epe = 6;
    }
    int wrow = warp_m * WTILE_M, wcol = warp_n * WTILE_N;

    float acc[WTM][WTN][4];
    #pragma unroll
    for (int i = 0; i < WTM; i++)
        #pragma unroll
        for (int j = 0; j < WTN; j++)
            #pragma unroll
            for (int r = 0; r < 4; r++) acc[i][j][r] = 0.0f;

    int NC = K >> 5;

    #pragma unroll
    for (int s = 0; s < NST - 1; s++) {
        load_stage<BM,BN>(sb + s * STGB, A, Bh_, Bl_, m0, M, n0, Nl, K, s * 32, tid);
        asm volatile("cp.async.commit_group;" ::: "memory");
    }

    int a_off = (wrow + (lane & 15)) * RS + ((lane >> 4) << 3);
    int b_off = (wcol + (lane & 7) + ((lane >> 4) & 1) * 8) * RS
              + ((lane >> 3) & 1) * 8;

    for (int c = 0; c < NC; c++) {
        asm volatile("cp.async.wait_group 1;" ::: "memory");
        __syncthreads();

        int pf = c + NST - 1;
        if (pf < NC) {
            load_stage<BM,BN>(sb + (pf % NST) * STGB, A, Bh_, Bl_, m0, M, n0, Nl, K,
                              pf * 32, tid);
        }
        asm volatile("cp.async.commit_group;" ::: "memory");

        uint32_t stg = sb + (c % NST) * STGB;
        uint32_t sA  = stg;
        uint32_t sBh = stg + ATB;
        uint32_t sBl = stg + ATB + BTB;

        #pragma unroll
        for (int ks = 0; ks < 2; ks++) {
            uint32_t a[WTM][4], bh[WTN][2], bl[WTN][2];
            #pragma unroll
            for (int mt = 0; mt < WTM; mt++) {
                uint32_t ad = sA + (uint32_t)(a_off + mt * 16 * RS + ks * 16) * 2;
                LDSM_X4(a[mt][0], a[mt][1], a[mt][2], a[mt][3], ad);
            }
            #pragma unroll
            for (int nb = 0; nb < WTN / 2; nb++) {
                uint32_t bd = sBh + (uint32_t)(b_off + nb * 16 * RS + ks * 16) * 2;
                LDSM_X4(bh[nb*2][0], bh[nb*2][1], bh[nb*2+1][0], bh[nb*2+1][1], bd);
                bd = sBl + (uint32_t)(b_off + nb * 16 * RS + ks * 16) * 2;
                LDSM_X4(bl[nb*2][0], bl[nb*2][1], bl[nb*2+1][0], bl[nb*2+1][1], bd);
            }
            #pragma unroll
            for (int mt = 0; mt < WTM; mt++)
                #pragma unroll
                for (int nt = 0; nt < WTN; nt++) MMA16816(acc[mt][nt], a[mt], bh[nt]);
            #pragma unroll
            for (int mt = 0; mt < WTM; mt++)
                #pragma unroll
                for (int nt = 0; nt < WTN; nt++) MMA16816(acc[mt][nt], a[mt], bl[nt]);
        }
    }

    // ---------------- epilogue ----------------
    int r  = lane >> 2;
    int c2 = (lane & 3) * 2;
    #pragma unroll
    for (int mt = 0; mt < WTM; mt++) {
        #pragma unroll
        for (int nt = 0; nt < WTN; nt++) {
            int n = n0 + wcol + nt * 8 + c2;
            if (n >= Nl) continue;
            float bn0 = bias_[n], bn1 = bias_[n + 1];
            #pragma unroll
            for (int hh = 0; hh < 2; hh++) {
                int m = m0 + wrow + mt * 16 + r + hh * 8;
                if (m >= M) continue;
                float v0 = acc[mt][nt][hh * 2 + 0] + bn0;
                float v1 = acc[mt][nt][hh * 2 + 1] + bn1;
                if (epe == 0) {
                    *reinterpret_cast<float2*>(&Cf_[(size_t)m * Nl + n]) =
                        make_float2(v0, v1);
                } else if (epe == 6) {
                    *reinterpret_cast<__half2*>(&Ch_[(size_t)m * Nl + n]) =
                        __halves2half2(__float2half_rn(v0), __float2half_rn(v1));
                } else if (epe == 1) {
                    float2 e = *reinterpret_cast<const float2*>(&extra[(size_t)m * Nl + n]);
                    *reinterpret_cast<float2*>(&Cf_[(size_t)m * Nl + n]) =
                        make_float2(v0 + e.x, v1 + e.y);
                } else if (epe == 2) {
                    v0 = 0.5f * v0 * (1.0f + erff(v0 * 0.70710678118654752f));
                    v1 = 0.5f * v1 * (1.0f + erff(v1 * 0.70710678118654752f));
                    *reinterpret_cast<__half2*>(&Ch_[(size_t)m * Nl + n]) =
                        __halves2half2(__float2half_rn(v0), __float2half_rn(v1));
                } else {
                    int bb = m / NPATCH, p = m % NPATCH;
                    float2 e = *reinterpret_cast<const float2*>(&extra[(size_t)p * DIM + n]);
                    *reinterpret_cast<float2*>(
                        &Cf_[((size_t)(bb * SEQ + p + 1)) * DIM + n]) =
                        make_float2(v0 + e.x, v1 + e.y);
                }
            }
        }
    }
}

// ---------------- tensor-core attention ----------------
#define SP 208
#define QK_RS 72     // Qs/Ks row stride (halfs), 144B
#define PT_RS 216    // P/VT row stride (halfs), 432B
#define S_RS 212     // S row stride (floats), 848B
#define MPASS 96
#define QS_OFF 0
#define KS_OFF 29952
#define VT_OFF 59904
#define S_OFF  87552
#define P_OFF  168960
#define AMEM   210432

__global__ __launch_bounds__(256) void attn_mma(
    const __half* __restrict__ q, const __half* __restrict__ k,
    const __half* __restrict__ v, __half* __restrict__ oh)
{
    extern __shared__ __align__(16) char dsm[];
    uint32_t sb = (uint32_t)__cvta_generic_to_shared(dsm);
    int bh = blockIdx.x, b = bh / NH, h = bh % NH;
    int tid = threadIdx.x, wid = tid >> 5, lane = tid & 31;

    const __half* qg = q + (size_t)b * SEQ * DIM + h * HD;
    const __half* kg = k + (size_t)b * SEQ * DIM + h * HD;
    const __half* vg = v + (size_t)b * SEQ * DIM + h * HD;

    for (int ch = tid; ch < SP * 8; ch += 256) {
        int row = ch >> 3, c8 = (ch & 7) * 8;
        uint32_t qa = sb + QS_OFF + (uint32_t)(row * QK_RS + c8) * 2;
        uint32_t ka = sb + KS_OFF + (uint32_t)(row * QK_RS + c8) * 2;
        if (row < SEQ) {
            cpa16(qa, qg + (size_t)row * DIM + c8, 16);
            cpa16(ka, kg + (size_t)row * DIM + c8, 16);
        } else {
            asm volatile("st.shared.v4.b32 [%0], {%1,%1,%1,%1};"
                         :: "r"(qa), "r"(0) : "memory");
            asm volatile("st.shared.v4.b32 [%0], {%1,%1,%1,%1};"
                         :: "r"(ka), "r"(0) : "memory");
        }
    }
    asm volatile("cp.async.commit_group;" ::: "memory");
    for (int i = tid; i < SP * 64; i += 256) {
        int e = i & 63, j = i >> 6;
        __half val = (j < SEQ) ? vg[(size_t)j * DIM + e] : __ushort_as_half((uint16_t)0);
        uint16_t bits = __half_as_ushort(val);
        asm volatile("st.shared.u16 [%0], %1;"
                     :: "r"(sb + VT_OFF + (uint32_t)(e * PT_RS + j) * 2), "h"(bits)
                     : "memory");
    }
    asm volatile("cp.async.wait_group 0;" ::: "memory");
    __syncthreads();

    int p0   = (wid < 5) ? 2 * wid : 10 + (wid - 5);
    int pcnt = (wid < 5) ? 2 : 1;
    int r4 = lane >> 2, c2 = (lane & 3) * 2;

    for (int m0 = 0; m0 < SEQ; m0 += MPASS) {
        int mt_cnt = (SEQ - m0 + 15) >> 4; if (mt_cnt > 6) mt_cnt = 6;

        float acc[6][4][4];
        #pragma unroll
        for (int i = 0; i < 6; i++)
            #pragma unroll
            for (int j = 0; j < 4; j++)
                #pragma unroll
                for (int r = 0; r < 4; r++) acc[i][j][r] = 0.f;
        #pragma unroll
        for (int ks = 0; ks < 4; ks++) {
            uint32_t a[6][4];
            for (int mt = 0; mt < mt_cnt; mt++) {
                uint32_t ad = sb + QS_OFF + (uint32_t)(
                    (m0 + mt * 16 + (lane & 15)) * QK_RS + ((lane >> 4) << 3) + ks * 16) * 2;
                LDSM_X4(a[mt][0], a[mt][1], a[mt][2], a[mt][3], ad);
            }
            for (int p = 0; p < pcnt; p++) {
                uint32_t b0[2], b1[2];
                uint32_t bd = sb + KS_OFF + (uint32_t)(
                    ((p0 + p) * 16 + (lane & 7) + ((lane >> 4) & 1) * 8) * QK_RS
                    + ((lane >> 3) & 1) * 8 + ks * 16) * 2;
                LDSM_X4(b0[0], b0[1], b1[0], b1[1], bd);
                for (int mt = 0; mt < mt_cnt; mt++) {
                    MMA16816(acc[mt][p * 2 + 0], a[mt], b0);
                    MMA16816(acc[mt][p * 2 + 1], a[mt], b1);
                }
            }
        }
        for (int mt = 0; mt < mt_cnt; mt++)
            for (int p = 0; p < pcnt; p++)
                #pragma unroll
                for (int t = 0; t < 2; t++) {
                    int col = (p0 + p) * 16 + t * 8 + c2;
                    #pragma unroll
                    for (int hh = 0; hh < 2; hh++) {
                        int row = mt * 16 + r4 + hh * 8;
                        *reinterpret_cast<float2*>(
                            dsm + S_OFF + ((size_t)row * S_RS + col) * 4) =
                            make_float2(acc[mt][p*2+t][hh*2], acc[mt][p*2+t][hh*2+1]);
                    }
                }
        __syncthreads();

        int rows = mt_cnt * 16;
        for (int r = wid; r < rows; r += 8) {
            const float* Srow = reinterpret_cast<const float*>(dsm + S_OFF + (size_t)r * S_RS * 4);
            float mx = -3.0e38f;
            for (int c = lane; c < SEQ; c += 32)
                mx = fmaxf(mx, Srow[c] * 0.125f);
            #pragma unroll
            for (int o = 16; o; o >>= 1) mx = fmaxf(mx, __shfl_xor_sync(0xffffffffu, mx, o));
            float pv[7];
            int cnt = 0;
            float sum = 0.f;
            for (int c = lane; c < SEQ; c += 32) {
                float p = __expf(Srow[c] * 0.125f - mx);
                pv[cnt++] = p; sum += p;
            }
            #pragma unroll
            for (int o = 16; o; o >>= 1) sum += __shfl_xor_sync(0xffffffffu, sum, o);
            float inv = 1.0f / sum;
            __half* Prow = reinterpret_cast<__half*>(dsm + P_OFF + (size_t)r * PT_RS * 2);
            cnt = 0;
            for (int c = lane; c < PT_RS; c += 32) {
                __half val;
                if (c < SEQ) { val = __float2half_rn(pv[cnt] * inv); cnt++; }
                else val = __ushort_as_half((uint16_t)0);
                Prow[c] = val;
            }
        }
        __syncthreads();

        float oacc[6][4];
        #pragma unroll
        for (int i = 0; i < 6; i++)
            #pragma unroll
            for (int r = 0; r < 4; r++) oacc[i][r] = 0.f;
        int l = lane & 15;
        for (int ks = 0; ks < 13; ks++) {
            uint32_t a[6][4];
            for (int mt = 0; mt < mt_cnt; mt++) {
                uint32_t ad = sb + P_OFF + (uint32_t)(
                    (mt * 16 + (lane & 15)) * PT_RS + ((lane >> 4) << 3) + ks * 16) * 2;
                LDSM_X4(a[mt][0], a[mt][1], a[mt][2], a[mt][3], ad);
            }
            uint32_t bfr[2];
            uint32_t bd = sb + VT_OFF + (uint32_t)(
                (wid * 8 + (l & 7)) * PT_RS + ((l >> 3) & 1) * 8 + ks * 16) * 2;
            LDSM_X2(bfr[0], bfr[1], bd);
            for (int mt = 0; mt < mt_cnt; mt++)
                MMA16816(oacc[mt], a[mt], bfr);
        }
        for (int mt = 0; mt < mt_cnt; mt++)
            #pragma unroll
            for (int hh = 0; hh < 2; hh++) {
                int gr = m0 + mt * 16 + r4 + hh * 8;
                if (gr >= SEQ) continue;
                *reinterpret_cast<__half2*>(
                    &oh[((size_t)(b * SEQ + gr)) * DIM + h * HD + wid * 8 + c2]) =
                    __halves2half2(__float2half_rn(oacc[mt][hh*2]),
                                   __float2half_rn(oacc[mt][hh*2+1]));
            }
        __syncthreads();
    }
}

// ---------------- host orchestration ----------------
#define GS_128_128 (NST * (128*RS*2 + 2*128*RS*2))   // 92160
#define GS_128_64  (NST * (128*RS*2 + 2*64*RS*2))    // 61440

extern "C" void kernel_launch(void* const* d_in, const int* in_sizes, int n_in,
                              void* d_out, int out_size) {
    const float* images    = (const float*)d_in[0];
    const float* patch_W   = (const float*)d_in[1];
    const float* patch_b   = (const float*)d_in[2];
    const float* pos_emb   = (const float*)d_in[3];
    const float* cls       = (const float*)d_in[4];
    const float* ln1_g     = (const float*)d_in[5];
    const float* ln1_b     = (const float*)d_in[6];
    const float* Wq        = (const float*)d_in[7];
    const float* bq        = (const float*)d_in[8];
    const float* Wk        = (const float*)d_in[9];
    const float* bk        = (const float*)d_in[10];
    const float* Wv        = (const float*)d_in[11];
    const float* bv        = (const float*)d_in[12];
    const float* Wo        = (const float*)d_in[13];
    const float* bo        = (const float*)d_in[14];
    const float* ln2_g     = (const float*)d_in[15];
    const float* ln2_b     = (const float*)d_in[16];
    const float* W1        = (const float*)d_in[17];
    const float* b1        = (const float*)d_in[18];
    const float* W2        = (const float*)d_in[19];
    const float* b2        = (const float*)d_in[20];
    const float* head_g    = (const float*)d_in[21];
    const float* head_bn   = (const float*)d_in[22];
    const float* head_W    = (const float*)d_in[23];
    const float* head_bias = (const float*)d_in[24];

    float *x;
    __half *q16, *k16, *v16;
    __half *xn, *oo, *hbuf, *pbuf, *cls16;
    __half *wpH, *wpL, *wqH, *wqL, *wkH, *wkL, *wvH, *wvL, *woH, *woL;
    __half *w1H, *w1L, *w2H, *w2L, *whH, *whL;
    cudaGetSymbolAddress((void**)&x,     g_x);
    cudaGetSymbolAddress((void**)&q16,   g_q);
    cudaGetSymbolAddress((void**)&k16,   g_k);
    cudaGetSymbolAddress((void**)&v16,   g_v);
    cudaGetSymbolAddress((void**)&xn,    g_xn);
    cudaGetSymbolAddress((void**)&oo,    g_o);
    cudaGetSymbolAddress((void**)&hbuf,  g_h);
    cudaGetSymbolAddress((void**)&pbuf,  g_p);
    cudaGetSymbolAddress((void**)&cls16, g_cls16);
    cudaGetSymbolAddress((void**)&wpH, w_pat_h);cudaGetSymbolAddress((void**)&wpL, w_pat_l);
    cudaGetSymbolAddress((void**)&wqH, w_q_h);  cudaGetSymbolAddress((void**)&wqL, w_q_l);
    cudaGetSymbolAddress((void**)&wkH, w_k_h);  cudaGetSymbolAddress((void**)&wkL, w_k_l);
    cudaGetSymbolAddress((void**)&wvH, w_v_h);  cudaGetSymbolAddress((void**)&wvL, w_v_l);
    cudaGetSymbolAddress((void**)&woH, w_o_h);  cudaGetSymbolAddress((void**)&woL, w_o_l);
    cudaGetSymbolAddress((void**)&w1H, w_1_h);  cudaGetSymbolAddress((void**)&w1L, w_1_l);
    cudaGetSymbolAddress((void**)&w2H, w_2_h);  cudaGetSymbolAddress((void**)&w2L, w_2_l);
    cudaGetSymbolAddress((void**)&whH, w_hd_h); cudaGetSymbolAddress((void**)&whL, w_hd_l);

    cudaFuncSetAttribute(hgemm<128,128,2,4>, cudaFuncAttributeMaxDynamicSharedMemorySize, GS_128_128);
    cudaFuncSetAttribute(hgemm<128,64,2,4>,  cudaFuncAttributeMaxDynamicSharedMemorySize, GS_128_64);
    cudaFuncSetAttribute(attn_mma, cudaFuncAttributeMaxDynamicSharedMemorySize, AMEM);

    QKV dummy = {};

    dim3 tblk(32, 8);
    wprep<<<dim3(24, 24, 1),   tblk>>>(patch_W, wpH, wpL, DIM, DIM);
    wprep<<<dim3(2, 24, 144),  tblk>>>(Wq, wqH, wqL, DIM, HD);
    wprep<<<dim3(2, 24, 144),  tblk>>>(Wk, wkH, wkL, DIM, HD);
    wprep<<<dim3(2, 24, 144),  tblk>>>(Wv, wvH, wvL, DIM, HD);
    wprep<<<dim3(24, 24, 12),  tblk>>>(Wo, woH, woL, DIM, DIM);
    wprep<<<dim3(96, 24, 12),  tblk>>>(W1, w1H, w1L, DIM, FF);
    wprep<<<dim3(24, 96, 12),  tblk>>>(W2, w2H, w2L, FF, DIM);
    wprep<<<dim3(32, 24, 1),   tblk>>>(head_W, whH, whL, DIM, NCLS);

    patch_extract<<<(PTOK * DIM + 255) / 256, 256>>>(images, pbuf);
    hgemm<128,128,2,4><<<dim3(6, 49), 256, GS_128_128>>>(
        pbuf, wpH, wpL, patch_b, pos_emb, x, nullptr,
        PTOK, DIM, DIM, 3, dummy);
    cls_fill<<<(BB * DIM + 255) / 256, 256>>>(cls, x);

    for (int l = 0; l < NL; l++) {
        size_t wo768 = (size_t)l * DIM * DIM;
        size_t woff  = (size_t)l * DIM * FF;

        ln_kernel<<<TOK, 256>>>(x, ln1_g + l * DIM, ln1_b + l * DIM, xn, DIM, DIM);

        QKV qk;
        qk.bh[0] = wqH + wo768; qk.bh[1] = wkH + wo768; qk.bh[2] = wvH + wo768;
        qk.bl[0] = wqL + wo768; qk.bl[1] = wkL + wo768; qk.bl[2] = wvL + wo768;
        qk.bias[0] = bq + l * DIM; qk.bias[1] = bk + l * DIM; qk.bias[2] = bv + l * DIM;
        qk.out[0] = q16; qk.out[1] = k16; qk.out[2] = v16;
        hgemm<128,128,2,4><<<dim3(18, 50), 256, GS_128_128>>>(
            xn, nullptr, nullptr, nullptr, nullptr, nullptr, nullptr,
            TOK, 2304, DIM, 4, qk);

        attn_mma<<<BB * NH, 256, AMEM>>>(q16, k16, v16, oo);

        hgemm<128,64,2,4><<<dim3(12, 50), 256, GS_128_64>>>(
            oo, woH + wo768, woL + wo768, bo + l * DIM, x, x, nullptr,
            TOK, DIM, DIM, 1, dummy);

        ln_kernel<<<TOK, 256>>>(x, ln2_g + l * DIM, ln2_b + l * DIM, xn, DIM, DIM);

        hgemm<128,128,2,4><<<dim3(24, 50), 256, GS_128_128>>>(
            xn, w1H + woff, w1L + woff, b1 + l * FF, nullptr, nullptr,
            hbuf, TOK, FF, DIM, 2, dummy);
        hgemm<128,64,2,4><<<dim3(12, 50), 256, GS_128_64>>>(
            hbuf, w2H + woff, w2L + woff, b2 + l * DIM, x, x, nullptr,
            TOK, DIM, FF, 1, dummy);
    }

    ln_kernel<<<BB, 256>>>(x, head_g, head_bn, cls16, (long long)SEQ * DIM, DIM);
    hgemm<128,128,2,4><<<dim3(8, 1), 256, GS_128_128>>>(
        cls16, whH, whL, head_bias, nullptr, (float*)d_out, nullptr,
        BB, NCLS, DIM, 0, dummy);
}

// round 13
// speedup vs baseline: 2.0454x; 1.3476x over previous
#include <cuda_runtime.h>
#include <cuda_fp16.h>
#include <cstdint>

#define BB 32
#define IMGSZ 224
#define PSZ 16
#define NSIDE 14
#define NPATCH 196
#define SEQ 197
#define DIM 768
#define NH 12
#define HD 64
#define FF 3072
#define NL 12
#define NCLS 1000
#define TOK (BB*SEQ)     // 6304
#define PTOK (BB*NPATCH) // 6272

// ---------------- scratch (device globals: allocation-free) ----------------
__device__ float  g_x[TOK*DIM];
__device__ __half g_q[TOK*DIM];
__device__ __half g_k[TOK*DIM];
__device__ __half g_v[TOK*DIM];

__device__ __half g_xn[TOK*DIM];
__device__ __half g_o[TOK*DIM];
__device__ __half g_h[(size_t)TOK*FF];
__device__ __half g_p[(size_t)PTOK*DIM];
__device__ __half g_cls16[BB*DIM];

// transposed fp16 hi/lo weights: [N][K] layout per layer
__device__ __half w_pat_h[589824],  w_pat_l[589824];
__device__ __half w_q_h[7077888],   w_q_l[7077888];
__device__ __half w_k_h[7077888],   w_k_l[7077888];
__device__ __half w_v_h[7077888],   w_v_l[7077888];
__device__ __half w_o_h[7077888],   w_o_l[7077888];
__device__ __half w_1_h[28311552],  w_1_l[28311552];
__device__ __half w_2_h[28311552],  w_2_l[28311552];
__device__ __half w_hd_h[768000],   w_hd_l[768000];

struct QKV {
    const __half* bh[3];
    const __half* bl[3];
    const float*  bias[3];
    __half*       out[3];
};

// ---------------- weight transpose + hi/lo split ----------------
__global__ void wprep(const float* __restrict__ in, __half* __restrict__ oh,
                      __half* __restrict__ ol, int K, int ng) {
    __shared__ float t[32][33];
    int g = blockIdx.z;
    int e0 = blockIdx.x * 32, k0 = blockIdx.y * 32;
    int tx = threadIdx.x, ty = threadIdx.y;  // 32x8
    const float* gin = in + (size_t)g * K * ng;
    #pragma unroll
    for (int i = 0; i < 4; i++) {
        int kk = k0 + ty + i * 8;
        int e  = e0 + tx;
        float v = 0.f;
        if (e < ng) v = gin[(size_t)kk * ng + e];
        t[ty + i * 8][tx] = v;
    }
    __syncthreads();
    __half* goh = oh + (size_t)g * ng * K;
    __half* gol = ol + (size_t)g * ng * K;
    #pragma unroll
    for (int i = 0; i < 4; i++) {
        int e  = e0 + ty + i * 8;
        int kk = k0 + tx;
        if (e < ng) {
            float v = t[tx][ty + i * 8];
            __half hv = __float2half_rn(v);
            goh[(size_t)e * K + kk] = hv;
            gol[(size_t)e * K + kk] = __float2half_rn(v - __half2float(hv));
        }
    }
}

// ---------------- patch extraction (fp16) ----------------
__global__ void patch_extract(const float* __restrict__ img,
                              __half* __restrict__ oh) {
    int idx = blockIdx.x * 256 + threadIdx.x;
    if (idx >= PTOK * DIM) return;
    int kcol = idx % DIM;
    int row  = idx / DIM;
    int b  = row / NPATCH;
    int p  = row % NPATCH;
    int pr = p / NSIDE, pc = p % NSIDE;
    int c  = kcol % 3;
    int t  = kcol / 3;
    int py = t / PSZ, px = t % PSZ;
    float v = img[(((size_t)(b*IMGSZ + pr*PSZ + py) * IMGSZ) + pc*PSZ + px) * 3 + c];
    oh[idx] = __float2half_rn(v);
}

__global__ void cls_fill(const float* __restrict__ cls, float* __restrict__ x) {
    int i = blockIdx.x * 256 + threadIdx.x;
    if (i < BB * DIM) x[(size_t)(i / DIM) * SEQ * DIM + (i % DIM)] = cls[i % DIM];
}

// ---------------- LayerNorm (fp32 in, fp16 out) ----------------
__global__ void ln_kernel(const float* __restrict__ x, const float* __restrict__ g,
                          const float* __restrict__ bt,
                          __half* __restrict__ yh,
                          long long in_stride, long long out_stride) {
    int row = blockIdx.x;
    int tid = threadIdx.x;
    const float* xr = x + (size_t)row * in_stride;
    float v0 = xr[tid], v1 = xr[tid + 256], v2 = xr[tid + 512];

    __shared__ float red1[8];
    __shared__ float red2[8];

    float s = v0 + v1 + v2;
    #pragma unroll
    for (int o = 16; o; o >>= 1) s += __shfl_xor_sync(0xffffffffu, s, o);
    if ((tid & 31) == 0) red1[tid >> 5] = s;
    __syncthreads();
    if (tid == 0) {
        float t = red1[0];
        #pragma unroll
        for (int i = 1; i < 8; i++) t += red1[i];
        red1[0] = t;
    }
    __syncthreads();
    float mean = red1[0] * (1.0f / 768.0f);

    float d0 = v0 - mean, d1 = v1 - mean, d2 = v2 - mean;
    float q = d0*d0 + d1*d1 + d2*d2;
    #pragma unroll
    for (int o = 16; o; o >>= 1) q += __shfl_xor_sync(0xffffffffu, q, o);
    if ((tid & 31) == 0) red2[tid >> 5] = q;
    __syncthreads();
    if (tid == 0) {
        float t = red2[0];
        #pragma unroll
        for (int i = 1; i < 8; i++) t += red2[i];
        red2[0] = t;
    }
    __syncthreads();
    float var = red2[0] * (1.0f / 768.0f);
    float r = rsqrtf(var + 1e-5f);

    size_t ob = (size_t)row * out_stride;
    #pragma unroll
    for (int c = 0; c < 3; c++) {
        float dd = (c == 0 ? d0 : (c == 1 ? d1 : d2));
        int col = tid + c * 256;
        yh[ob + col] = __float2half_rn(dd * r * g[col] + bt[col]);
    }
}

// ---------------- pipelined HMMA GEMM: TERMS-term (A fp16, B hi[/lo]) ----------
#define RS 40                   // padded row stride (halfs): 80B
#define NST 3

__device__ __forceinline__ void cpa16(uint32_t sa, const void* ga, uint32_t ss) {
    asm volatile("cp.async.cg.shared.global [%0], [%1], 16, %2;"
                 :: "r"(sa), "l"(ga), "r"(ss) : "memory");
}

template<int BM, int BN, int TERMS>
__device__ __forceinline__ void load_stage(
    uint32_t sbase, const __half* __restrict__ A,
    const __half* __restrict__ Bh, const __half* __restrict__ Bl,
    int m0, int M, int n0, int N, int K, int k0, int tid)
{
    constexpr int ACH = BM * 4;
    constexpr int BCH = BN * 4;
    constexpr int ATB = BM * RS * 2;
    constexpr int BTB = BN * RS * 2;
    constexpr int CH_TOT = ACH + TERMS * BCH;
    constexpr int PER_T = CH_TOT / 256;
    #pragma unroll
    for (int t = 0; t < PER_T; t++) {
        int ch = tid + t * 256;
        const __half* src; int r0, lim; uint32_t tb; int idx;
        if (ch < ACH)            { src = A;  r0 = m0; lim = M; tb = 0;         idx = ch; }
        else if (ch < ACH + BCH) { src = Bh; r0 = n0; lim = N; tb = ATB;       idx = ch - ACH; }
        else                     { src = Bl; r0 = n0; lim = N; tb = ATB + BTB; idx = ch - ACH - BCH; }
        int row = idx >> 2, c4 = idx & 3;
        int gr = r0 + row;
        uint32_t ss = 16u;
        if (gr >= lim) { gr = lim - 1; ss = 0u; }
        const void* ga = src + (size_t)gr * K + k0 + c4 * 8;
        uint32_t sa = sbase + tb + (uint32_t)(row * RS + c4 * 8) * 2;
        cpa16(sa, ga, ss);
    }
}

#define LDSM_X4(r0, r1, r2, r3, addr) \
    asm volatile("ldmatrix.sync.aligned.m8n8.x4.shared.b16 {%0,%1,%2,%3}, [%4];" \
                 : "=r"(r0), "=r"(r1), "=r"(r2), "=r"(r3) : "r"(addr))

#define LDSM_X2(r0, r1, addr) \
    asm volatile("ldmatrix.sync.aligned.m8n8.x2.shared.b16 {%0,%1}, [%2];" \
                 : "=r"(r0), "=r"(r1) : "r"(addr))

#define MMA16816(c, a, b) \
    asm volatile("mma.sync.aligned.m16n8k16.row.col.f32.f16.f16.f32 " \
                 "{%0,%1,%2,%3}, {%4,%5,%6,%7}, {%8,%9}, {%0,%1,%2,%3};" \
                 : "+f"((c)[0]), "+f"((c)[1]), "+f"((c)[2]), "+f"((c)[3]) \
                 : "r"((a)[0]), "r"((a)[1]), "r"((a)[2]), "r"((a)[3]), \
                   "r"((b)[0]), "r"((b)[1]))

// ep: 0=+bias fp32 | 1=+bias+residual | 2=gelu->fp16 | 3=patch embed | 4=fused QKV (fp16 out)
template<int BM, int BN, int TERMS, int WROWS, int WCOLS>
__global__ __launch_bounds__(256) void hgemm(
    const __half* __restrict__ A,
    const __half* __restrict__ Bh, const __half* __restrict__ Bl,
    const float* __restrict__ bias, const float* __restrict__ extra,
    float* __restrict__ Cf, __half* __restrict__ Choh,
    int M, int N, int K, int ep, QKV qkv)
{
    constexpr int WTILE_M = BM / WROWS;
    constexpr int WTM     = WTILE_M / 16;
    constexpr int WTILE_N = BN / WCOLS;
    constexpr int WTN     = WTILE_N / 8;
    constexpr int ATB  = BM * RS * 2;
    constexpr int BTB  = BN * RS * 2;
    constexpr int STGB = ATB + TERMS * BTB;

    extern __shared__ __align__(16) char dsm[];
    uint32_t sb = (uint32_t)__cvta_generic_to_shared(dsm);
    int tid = threadIdx.x, wid = tid >> 5, lane = tid & 31;
    int warp_m = wid / WCOLS, warp_n = wid % WCOLS;
    int m0 = blockIdx.y * BM;
    int n0 = blockIdx.x * BN;
    int Nl = N;
    int epe = ep;
    const __half* Bh_ = Bh; const __half* Bl_ = Bl;
    const float* bias_ = bias; float* Cf_ = Cf; __half* Ch_ = Choh;
    if (ep == 4) {
        int seg = n0 / 768;
        Bh_ = qkv.bh[seg]; Bl_ = qkv.bl[seg];
        bias_ = qkv.bias[seg]; Ch_ = qkv.out[seg];
        n0 -= seg * 768; Nl = 768; epe = 6;
    }
    int wrow = warp_m * WTILE_M, wcol = warp_n * WTILE_N;

    float acc[WTM][WTN][4];
    #pragma unroll
    for (int i = 0; i < WTM; i++)
        #pragma unroll
        for (int j = 0; j < WTN; j++)
            #pragma unroll
            for (int r = 0; r < 4; r++) acc[i][j][r] = 0.0f;

    int NC = K >> 5;

    #pragma unroll
    for (int s = 0; s < NST - 1; s++) {
        load_stage<BM,BN,TERMS>(sb + s * STGB, A, Bh_, Bl_, m0, M, n0, Nl, K, s * 32, tid);
        asm volatile("cp.async.commit_group;" ::: "memory");
    }

    int a_off = (wrow + (lane & 15)) * RS + ((lane >> 4) << 3);
    int b_off = (wcol + (lane & 7) + ((lane >> 4) & 1) * 8) * RS
              + ((lane >> 3) & 1) * 8;

    for (int c = 0; c < NC; c++) {
        asm volatile("cp.async.wait_group 1;" ::: "memory");
        __syncthreads();

        int pf = c + NST - 1;
        if (pf < NC) {
            load_stage<BM,BN,TERMS>(sb + (pf % NST) * STGB, A, Bh_, Bl_, m0, M, n0, Nl, K,
                                    pf * 32, tid);
        }
        asm volatile("cp.async.commit_group;" ::: "memory");

        uint32_t stg = sb + (c % NST) * STGB;
        uint32_t sA  = stg;
        uint32_t sBh = stg + ATB;
        uint32_t sBl = stg + ATB + BTB;

        #pragma unroll
        for (int ks = 0; ks < 2; ks++) {
            uint32_t a[WTM][4], bh[WTN][2], bl[WTN][2];
            #pragma unroll
            for (int mt = 0; mt < WTM; mt++) {
                uint32_t ad = sA + (uint32_t)(a_off + mt * 16 * RS + ks * 16) * 2;
                LDSM_X4(a[mt][0], a[mt][1], a[mt][2], a[mt][3], ad);
            }
            #pragma unroll
            for (int nb = 0; nb < WTN / 2; nb++) {
                uint32_t bd = sBh + (uint32_t)(b_off + nb * 16 * RS + ks * 16) * 2;
                LDSM_X4(bh[nb*2][0], bh[nb*2][1], bh[nb*2+1][0], bh[nb*2+1][1], bd);
                if (TERMS == 2) {
                    bd = sBl + (uint32_t)(b_off + nb * 16 * RS + ks * 16) * 2;
                    LDSM_X4(bl[nb*2][0], bl[nb*2][1], bl[nb*2+1][0], bl[nb*2+1][1], bd);
                }
            }
            #pragma unroll
            for (int mt = 0; mt < WTM; mt++)
                #pragma unroll
                for (int nt = 0; nt < WTN; nt++) MMA16816(acc[mt][nt], a[mt], bh[nt]);
            if (TERMS == 2) {
                #pragma unroll
                for (int mt = 0; mt < WTM; mt++)
                    #pragma unroll
                    for (int nt = 0; nt < WTN; nt++) MMA16816(acc[mt][nt], a[mt], bl[nt]);
            }
        }
    }

    // ---------------- epilogue ----------------
    int r  = lane >> 2;
    int c2 = (lane & 3) * 2;
    #pragma unroll
    for (int mt = 0; mt < WTM; mt++) {
        #pragma unroll
        for (int nt = 0; nt < WTN; nt++) {
            int n = n0 + wcol + nt * 8 + c2;
            if (n >= Nl) continue;
            float bn0 = bias_[n], bn1 = bias_[n + 1];
            #pragma unroll
            for (int hh = 0; hh < 2; hh++) {
                int m = m0 + wrow + mt * 16 + r + hh * 8;
                if (m >= M) continue;
                float v0 = acc[mt][nt][hh * 2 + 0] + bn0;
                float v1 = acc[mt][nt][hh * 2 + 1] + bn1;
                if (epe == 0) {
                    *reinterpret_cast<float2*>(&Cf_[(size_t)m * Nl + n]) =
                        make_float2(v0, v1);
                } else if (epe == 6) {
                    *reinterpret_cast<__half2*>(&Ch_[(size_t)m * Nl + n]) =
                        __halves2half2(__float2half_rn(v0), __float2half_rn(v1));
                } else if (epe == 1) {
                    float2 e = *reinterpret_cast<const float2*>(&extra[(size_t)m * Nl + n]);
                    *reinterpret_cast<float2*>(&Cf_[(size_t)m * Nl + n]) =
                        make_float2(v0 + e.x, v1 + e.y);
                } else if (epe == 2) {
                    v0 = 0.5f * v0 * (1.0f + erff(v0 * 0.70710678118654752f));
                    v1 = 0.5f * v1 * (1.0f + erff(v1 * 0.70710678118654752f));
                    *reinterpret_cast<__half2*>(&Ch_[(size_t)m * Nl + n]) =
                        __halves2half2(__float2half_rn(v0), __float2half_rn(v1));
                } else {
                    int bb = m / NPATCH, p = m % NPATCH;
                    float2 e = *reinterpret_cast<const float2*>(&extra[(size_t)p * DIM + n]);
                    *reinterpret_cast<float2*>(
                        &Cf_[((size_t)(bb * SEQ + p + 1)) * DIM + n]) =
                        make_float2(v0 + e.x, v1 + e.y);
                }
            }
        }
    }
}

// ---------------- tensor-core attention ----------------
#define SP 208
#define QK_RS 72     // Qs/Ks row stride (halfs), 144B
#define PT_RS 216    // P/VT row stride (halfs), 432B
#define S_RS 212     // S row stride (floats), 848B
#define MPASS 96
#define QS_OFF 0
#define KS_OFF 29952
#define VT_OFF 59904
#define S_OFF  87552
#define P_OFF  168960
#define AMEM   210432

__global__ __launch_bounds__(256) void attn_mma(
    const __half* __restrict__ q, const __half* __restrict__ k,
    const __half* __restrict__ v, __half* __restrict__ oh)
{
    extern __shared__ __align__(16) char dsm[];
    uint32_t sb = (uint32_t)__cvta_generic_to_shared(dsm);
    int bh = blockIdx.x, b = bh / NH, h = bh % NH;
    int tid = threadIdx.x, wid = tid >> 5, lane = tid & 31;

    const __half* qg = q + (size_t)b * SEQ * DIM + h * HD;
    const __half* kg = k + (size_t)b * SEQ * DIM + h * HD;
    const __half* vg = v + (size_t)b * SEQ * DIM + h * HD;

    for (int ch = tid; ch < SP * 8; ch += 256) {
        int row = ch >> 3, c8 = (ch & 7) * 8;
        uint32_t qa = sb + QS_OFF + (uint32_t)(row * QK_RS + c8) * 2;
        uint32_t ka = sb + KS_OFF + (uint32_t)(row * QK_RS + c8) * 2;
        if (row < SEQ) {
            cpa16(qa, qg + (size_t)row * DIM + c8, 16);
            cpa16(ka, kg + (size_t)row * DIM + c8, 16);
        } else {
            asm volatile("st.shared.v4.b32 [%0], {%1,%1,%1,%1};"
                         :: "r"(qa), "r"(0) : "memory");
            asm volatile("st.shared.v4.b32 [%0], {%1,%1,%1,%1};"
                         :: "r"(ka), "r"(0) : "memory");
        }
    }
    asm volatile("cp.async.commit_group;" ::: "memory");
    for (int i = tid; i < SP * 64; i += 256) {
        int e = i & 63, j = i >> 6;
        __half val = (j < SEQ) ? vg[(size_t)j * DIM + e] : __ushort_as_half((uint16_t)0);
        uint16_t bits = __half_as_ushort(val);
        asm volatile("st.shared.u16 [%0], %1;"
                     :: "r"(sb + VT_OFF + (uint32_t)(e * PT_RS + j) * 2), "h"(bits)
                     : "memory");
    }
    asm volatile("cp.async.wait_group 0;" ::: "memory");
    __syncthreads();

    int p0   = (wid < 5) ? 2 * wid : 10 + (wid - 5);
    int pcnt = (wid < 5) ? 2 : 1;
    int r4 = lane >> 2, c2 = (lane & 3) * 2;

    for (int m0 = 0; m0 < SEQ; m0 += MPASS) {
        int mt_cnt = (SEQ - m0 + 15) >> 4; if (mt_cnt > 6) mt_cnt = 6;

        float acc[6][4][4];
        #pragma unroll
        for (int i = 0; i < 6; i++)
            #pragma unroll
            for (int j = 0; j < 4; j++)
                #pragma unroll
                for (int r = 0; r < 4; r++) acc[i][j][r] = 0.f;
        #pragma unroll
        for (int ks = 0; ks < 4; ks++) {
            uint32_t a[6][4];
            for (int mt = 0; mt < mt_cnt; mt++) {
                uint32_t ad = sb + QS_OFF + (uint32_t)(
                    (m0 + mt * 16 + (lane & 15)) * QK_RS + ((lane >> 4) << 3) + ks * 16) * 2;
                LDSM_X4(a[mt][0], a[mt][1], a[mt][2], a[mt][3], ad);
            }
            for (int p = 0; p < pcnt; p++) {
                uint32_t b0[2], b1[2];
                uint32_t bd = sb + KS_OFF + (uint32_t)(
                    ((p0 + p) * 16 + (lane & 7) + ((lane >> 4) & 1) * 8) * QK_RS
                    + ((lane >> 3) & 1) * 8 + ks * 16) * 2;
                LDSM_X4(b0[0], b0[1], b1[0], b1[1], bd);
                for (int mt = 0; mt < mt_cnt; mt++) {
                    MMA16816(acc[mt][p * 2 + 0], a[mt], b0);
                    MMA16816(acc[mt][p * 2 + 1], a[mt], b1);
                }
            }
        }
        for (int mt = 0; mt < mt_cnt; mt++)
            for (int p = 0; p < pcnt; p++)
                #pragma unroll
                for (int t = 0; t < 2; t++) {
                    int col = (p0 + p) * 16 + t * 8 + c2;
                    #pragma unroll
                    for (int hh = 0; hh < 2; hh++) {
                        int row = mt * 16 + r4 + hh * 8;
                        *reinterpret_cast<float2*>(
                            dsm + S_OFF + ((size_t)row * S_RS + col) * 4) =
                            make_float2(acc[mt][p*2+t][hh*2], acc[mt][p*2+t][hh*2+1]);
                    }
                }
        __syncthreads();

        int rows = mt_cnt * 16;
        for (int r = wid; r < rows; r += 8) {
            const float* Srow = reinterpret_cast<const float*>(dsm + S_OFF + (size_t)r * S_RS * 4);
            float mx = -3.0e38f;
            for (int c = lane; c < SEQ; c += 32)
                mx = fmaxf(mx, Srow[c] * 0.125f);
            #pragma unroll
            for (int o = 16; o; o >>= 1) mx = fmaxf(mx, __shfl_xor_sync(0xffffffffu, mx, o));
            float pv[7];
            int cnt = 0;
            float sum = 0.f;
            for (int c = lane; c < SEQ; c += 32) {
                float p = __expf(Srow[c] * 0.125f - mx);
                pv[cnt++] = p; sum += p;
            }
            #pragma unroll
            for (int o = 16; o; o >>= 1) sum += __shfl_xor_sync(0xffffffffu, sum, o);
            float inv = 1.0f / sum;
            __half* Prow = reinterpret_cast<__half*>(dsm + P_OFF + (size_t)r * PT_RS * 2);
            cnt = 0;
            for (int c = lane; c < PT_RS; c += 32) {
                __half val;
                if (c < SEQ) { val = __float2half_rn(pv[cnt] * inv); cnt++; }
                else val = __ushort_as_half((uint16_t)0);
                Prow[c] = val;
            }
        }
        __syncthreads();

        float oacc[6][4];
        #pragma unroll
        for (int i = 0; i < 6; i++)
            #pragma unroll
            for (int r = 0; r < 4; r++) oacc[i][r] = 0.f;
        int l = lane & 15;
        for (int ks = 0; ks < 13; ks++) {
            uint32_t a[6][4];
            for (int mt = 0; mt < mt_cnt; mt++) {
                uint32_t ad = sb + P_OFF + (uint32_t)(
                    (mt * 16 + (lane & 15)) * PT_RS + ((lane >> 4) << 3) + ks * 16) * 2;
                LDSM_X4(a[mt][0], a[mt][1], a[mt][2], a[mt][3], ad);
            }
            uint32_t bfr[2];
            uint32_t bd = sb + VT_OFF + (uint32_t)(
                (wid * 8 + (l & 7)) * PT_RS + ((l >> 3) & 1) * 8 + ks * 16) * 2;
            LDSM_X2(bfr[0], bfr[1], bd);
            for (int mt = 0; mt < mt_cnt; mt++)
                MMA16816(oacc[mt], a[mt], bfr);
        }
        for (int mt = 0; mt < mt_cnt; mt++)
            #pragma unroll
            for (int hh = 0; hh < 2; hh++) {
                int gr = m0 + mt * 16 + r4 + hh * 8;
                if (gr >= SEQ) continue;
                *reinterpret_cast<__half2*>(
                    &oh[((size_t)(b * SEQ + gr)) * DIM + h * HD + wid * 8 + c2]) =
                    __halves2half2(__float2half_rn(oacc[mt][hh*2]),
                                   __float2half_rn(oacc[mt][hh*2+1]));
            }
        __syncthreads();
    }
}

// ---------------- host orchestration ----------------
#define GS_2T_128 (NST * (128*RS*2 + 2*128*RS*2))   // 92160
#define GS_2T_64  (NST * (128*RS*2 + 2*64*RS*2))    // 61440
#define GS_1T_128 (NST * (128*RS*2 + 128*RS*2))     // 61440

extern "C" void kernel_launch(void* const* d_in, const int* in_sizes, int n_in,
                              void* d_out, int out_size) {
    const float* images    = (const float*)d_in[0];
    const float* patch_W   = (const float*)d_in[1];
    const float* patch_b   = (const float*)d_in[2];
    const float* pos_emb   = (const float*)d_in[3];
    const float* cls       = (const float*)d_in[4];
    const float* ln1_g     = (const float*)d_in[5];
    const float* ln1_b     = (const float*)d_in[6];
    const float* Wq        = (const float*)d_in[7];
    const float* bq        = (const float*)d_in[8];
    const float* Wk        = (const float*)d_in[9];
    const float* bk        = (const float*)d_in[10];
    const float* Wv        = (const float*)d_in[11];
    const float* bv        = (const float*)d_in[12];
    const float* Wo        = (const float*)d_in[13];
    const float* bo        = (const float*)d_in[14];
    const float* ln2_g     = (const float*)d_in[15];
    const float* ln2_b     = (const float*)d_in[16];
    const float* W1        = (const float*)d_in[17];
    const float* b1        = (const float*)d_in[18];
    const float* W2        = (const float*)d_in[19];
    const float* b2        = (const float*)d_in[20];
    const float* head_g    = (const float*)d_in[21];
    const float* head_bn   = (const float*)d_in[22];
    const float* head_W    = (const float*)d_in[23];
    const float* head_bias = (const float*)d_in[24];

    float *x;
    __half *q16, *k16, *v16;
    __half *xn, *oo, *hbuf, *pbuf, *cls16;
    __half *wpH, *wpL, *wqH, *wqL, *wkH, *wkL, *wvH, *wvL, *woH, *woL;
    __half *w1H, *w1L, *w2H, *w2L, *whH, *whL;
    cudaGetSymbolAddress((void**)&x,     g_x);
    cudaGetSymbolAddress((void**)&q16,   g_q);
    cudaGetSymbolAddress((void**)&k16,   g_k);
    cudaGetSymbolAddress((void**)&v16,   g_v);
    cudaGetSymbolAddress((void**)&xn,    g_xn);
    cudaGetSymbolAddress((void**)&oo,    g_o);
    cudaGetSymbolAddress((void**)&hbuf,  g_h);
    cudaGetSymbolAddress((void**)&pbuf,  g_p);
    cudaGetSymbolAddress((void**)&cls16, g_cls16);
    cudaGetSymbolAddress((void**)&wpH, w_pat_h);cudaGetSymbolAddress((void**)&wpL, w_pat_l);
    cudaGetSymbolAddress((void**)&wqH, w_q_h);  cudaGetSymbolAddress((void**)&wqL, w_q_l);
    cudaGetSymbolAddress((void**)&wkH, w_k_h);  cudaGetSymbolAddress((void**)&wkL, w_k_l);
    cudaGetSymbolAddress((void**)&wvH, w_v_h);  cudaGetSymbolAddress((void**)&wvL, w_v_l);
    cudaGetSymbolAddress((void**)&woH, w_o_h);  cudaGetSymbolAddress((void**)&woL, w_o_l);
    cudaGetSymbolAddress((void**)&w1H, w_1_h);  cudaGetSymbolAddress((void**)&w1L, w_1_l);
    cudaGetSymbolAddress((void**)&w2H, w_2_h);  cudaGetSymbolAddress((void**)&w2L, w_2_l);
    cudaGetSymbolAddress((void**)&whH, w_hd_h); cudaGetSymbolAddress((void**)&whL, w_hd_l);

    cudaFuncSetAttribute(hgemm<128,128,2,2,4>, cudaFuncAttributeMaxDynamicSharedMemorySize, GS_2T_128);
    cudaFuncSetAttribute(hgemm<128,64,2,2,4>,  cudaFuncAttributeMaxDynamicSharedMemorySize, GS_2T_64);
    cudaFuncSetAttribute(hgemm<128,128,1,2,4>, cudaFuncAttributeMaxDynamicSharedMemorySize, GS_1T_128);
    cudaFuncSetAttribute(attn_mma, cudaFuncAttributeMaxDynamicSharedMemorySize, AMEM);

    QKV dummy = {};

    dim3 tblk(32, 8);
    wprep<<<dim3(24, 24, 1),   tblk>>>(patch_W, wpH, wpL, DIM, DIM);
    wprep<<<dim3(2, 24, 144),  tblk>>>(Wq, wqH, wqL, DIM, HD);
    wprep<<<dim3(2, 24, 144),  tblk>>>(Wk, wkH, wkL, DIM, HD);
    wprep<<<dim3(2, 24, 144),  tblk>>>(Wv, wvH, wvL, DIM, HD);
    wprep<<<dim3(24, 24, 12),  tblk>>>(Wo, woH, woL, DIM, DIM);
    wprep<<<dim3(96, 24, 12),  tblk>>>(W1, w1H, w1L, DIM, FF);
    wprep<<<dim3(24, 96, 12),  tblk>>>(W2, w2H, w2L, FF, DIM);
    wprep<<<dim3(32, 24, 1),   tblk>>>(head_W, whH, whL, DIM, NCLS);

    patch_extract<<<(PTOK * DIM + 255) / 256, 256>>>(images, pbuf);
    hgemm<128,128,2,2,4><<<dim3(6, 49), 256, GS_2T_128>>>(
        pbuf, wpH, wpL, patch_b, pos_emb, x, nullptr,
        PTOK, DIM, DIM, 3, dummy);
    cls_fill<<<(BB * DIM + 255) / 256, 256>>>(cls, x);

    for (int l = 0; l < NL; l++) {
        size_t wo768 = (size_t)l * DIM * DIM;
        size_t woff  = (size_t)l * DIM * FF;

        ln_kernel<<<TOK, 256>>>(x, ln1_g + l * DIM, ln1_b + l * DIM, xn, DIM, DIM);

        QKV qk;
        qk.bh[0] = wqH + wo768; qk.bh[1] = wkH + wo768; qk.bh[2] = wvH + wo768;
        qk.bl[0] = wqL + wo768; qk.bl[1] = wkL + wo768; qk.bl[2] = wvL + wo768;
        qk.bias[0] = bq + l * DIM; qk.bias[1] = bk + l * DIM; qk.bias[2] = bv + l * DIM;
        qk.out[0] = q16; qk.out[1] = k16; qk.out[2] = v16;
        hgemm<128,128,2,2,4><<<dim3(18, 50), 256, GS_2T_128>>>(
            xn, nullptr, nullptr, nullptr, nullptr, nullptr, nullptr,
            TOK, 2304, DIM, 4, qk);

        attn_mma<<<BB * NH, 256, AMEM>>>(q16, k16, v16, oo);

        hgemm<128,64,2,2,4><<<dim3(12, 50), 256, GS_2T_64>>>(
            oo, woH + wo768, woL + wo768, bo + l * DIM, x, x, nullptr,
            TOK, DIM, DIM, 1, dummy);

        ln_kernel<<<TOK, 256>>>(x, ln2_g + l * DIM, ln2_b + l * DIM, xn, DIM, DIM);

        hgemm<128,128,1,2,4><<<dim3(24, 50), 256, GS_1T_128>>>(
            xn, w1H + woff, nullptr, b1 + l * FF, nullptr, nullptr,
            hbuf, TOK, FF, DIM, 2, dummy);
        hgemm<128,128,1,2,4><<<dim3(6, 50), 256, GS_1T_128>>>(
            hbuf, w2H + woff, nullptr, b2 + l * DIM, x, x, nullptr,
            TOK, DIM, FF, 1, dummy);
    }

    ln_kernel<<<BB, 256>>>(x, head_g, head_bn, cls16, (long long)SEQ * DIM, DIM);
    hgemm<128,128,2,2,4><<<dim3(8, 1), 256, GS_2T_128>>>(
        cls16, whH, whL, head_bias, nullptr, (float*)d_out, nullptr,
        BB, NCLS, DIM, 0, dummy);
}

// round 14
// speedup vs baseline: 2.0805x; 1.0172x over previous
#include <cuda_runtime.h>
#include <cuda_fp16.h>
#include <cstdint>

#define BB 32
#define IMGSZ 224
#define PSZ 16
#define NSIDE 14
#define NPATCH 196
#define SEQ 197
#define DIM 768
#define NH 12
#define HD 64
#define FF 3072
#define NL 12
#define NCLS 1000
#define TOK (BB*SEQ)     // 6304
#define PTOK (BB*NPATCH) // 6272

// ---------------- scratch (device globals: allocation-free) ----------------
__device__ float  g_x[TOK*DIM];
__device__ __half g_q[TOK*DIM];
__device__ __half g_k[TOK*DIM];
__device__ __half g_v[TOK*DIM];

__device__ __half g_xn[TOK*DIM];
__device__ __half g_o[TOK*DIM];
__device__ __half g_h[(size_t)TOK*FF];
__device__ __half g_p[(size_t)PTOK*DIM];
__device__ __half g_cls16[BB*DIM];

// transposed fp16 hi/lo weights: [N][K] layout per layer (lo only where used)
__device__ __half w_pat_h[589824],  w_pat_l[589824];
__device__ __half w_q_h[7077888],   w_q_l[7077888];
__device__ __half w_k_h[7077888],   w_k_l[7077888];
__device__ __half w_v_h[7077888],   w_v_l[7077888];
__device__ __half w_o_h[7077888],   w_o_l[7077888];
__device__ __half w_1_h[28311552];
__device__ __half w_2_h[28311552];
__device__ __half w_hd_h[768000],   w_hd_l[768000];

struct QKV {
    const __half* bh[3];
    const __half* bl[3];
    const float*  bias[3];
    __half*       out[3];
};

// ---------------- weight transpose + hi[/lo] split ----------------
__global__ void wprep(const float* __restrict__ in, __half* __restrict__ oh,
                      __half* __restrict__ ol, int K, int ng) {
    __shared__ float t[32][33];
    int g = blockIdx.z;
    int e0 = blockIdx.x * 32, k0 = blockIdx.y * 32;
    int tx = threadIdx.x, ty = threadIdx.y;  // 32x8
    const float* gin = in + (size_t)g * K * ng;
    #pragma unroll
    for (int i = 0; i < 4; i++) {
        int kk = k0 + ty + i * 8;
        int e  = e0 + tx;
        float v = 0.f;
        if (e < ng) v = gin[(size_t)kk * ng + e];
        t[ty + i * 8][tx] = v;
    }
    __syncthreads();
    __half* goh = oh + (size_t)g * ng * K;
    __half* gol = (ol != nullptr) ? ol + (size_t)g * ng * K : nullptr;
    #pragma unroll
    for (int i = 0; i < 4; i++) {
        int e  = e0 + ty + i * 8;
        int kk = k0 + tx;
        if (e < ng) {
            float v = t[tx][ty + i * 8];
            __half hv = __float2half_rn(v);
            goh[(size_t)e * K + kk] = hv;
            if (gol != nullptr)
                gol[(size_t)e * K + kk] = __float2half_rn(v - __half2float(hv));
        }
    }
}

// ---------------- patch extraction (fp16) ----------------
__global__ void patch_extract(const float* __restrict__ img,
                              __half* __restrict__ oh) {
    int idx = blockIdx.x * 256 + threadIdx.x;
    if (idx >= PTOK * DIM) return;
    int kcol = idx % DIM;
    int row  = idx / DIM;
    int b  = row / NPATCH;
    int p  = row % NPATCH;
    int pr = p / NSIDE, pc = p % NSIDE;
    int c  = kcol % 3;
    int t  = kcol / 3;
    int py = t / PSZ, px = t % PSZ;
    float v = img[(((size_t)(b*IMGSZ + pr*PSZ + py) * IMGSZ) + pc*PSZ + px) * 3 + c];
    oh[idx] = __float2half_rn(v);
}

__global__ void cls_fill(const float* __restrict__ cls, float* __restrict__ x) {
    int i = blockIdx.x * 256 + threadIdx.x;
    if (i < BB * DIM) x[(size_t)(i / DIM) * SEQ * DIM + (i % DIM)] = cls[i % DIM];
}

// ---------------- LayerNorm (fp32 in, fp16 out), 192 thr x float4 -------------
__global__ void ln_kernel(const float* __restrict__ x, const float* __restrict__ g,
                          const float* __restrict__ bt,
                          __half* __restrict__ yh,
                          long long in_stride, long long out_stride) {
    int row = blockIdx.x;
    int tid = threadIdx.x;          // 0..191
    int wid = tid >> 5, lane = tid & 31;
    const float* xr = x + (size_t)row * in_stride;
    float4 v = *reinterpret_cast<const float4*>(&xr[tid * 4]);

    __shared__ float red1[6];
    __shared__ float red2[6];

    float s = v.x + v.y + v.z + v.w;
    #pragma unroll
    for (int o = 16; o; o >>= 1) s += __shfl_xor_sync(0xffffffffu, s, o);
    if (lane == 0) red1[wid] = s;
    __syncthreads();
    if (tid == 0) {
        float t = red1[0];
        #pragma unroll
        for (int i = 1; i < 6; i++) t += red1[i];
        red1[0] = t;
    }
    __syncthreads();
    float mean = red1[0] * (1.0f / 768.0f);

    float dx = v.x - mean, dy = v.y - mean, dz = v.z - mean, dw = v.w - mean;
    float q = dx*dx + dy*dy + dz*dz + dw*dw;
    #pragma unroll
    for (int o = 16; o; o >>= 1) q += __shfl_xor_sync(0xffffffffu, q, o);
    if (lane == 0) red2[wid] = q;
    __syncthreads();
    if (tid == 0) {
        float t = red2[0];
        #pragma unroll
        for (int i = 1; i < 6; i++) t += red2[i];
        red2[0] = t;
    }
    __syncthreads();
    float var = red2[0] * (1.0f / 768.0f);
    float r = rsqrtf(var + 1e-5f);

    float4 gg = *reinterpret_cast<const float4*>(&g[tid * 4]);
    float4 bb = *reinterpret_cast<const float4*>(&bt[tid * 4]);
    __half2 h01 = __floats2half2_rn(dx * r * gg.x + bb.x, dy * r * gg.y + bb.y);
    __half2 h23 = __floats2half2_rn(dz * r * gg.z + bb.z, dw * r * gg.w + bb.w);
    uint2 packed;
    packed.x = *reinterpret_cast<uint32_t*>(&h01);
    packed.y = *reinterpret_cast<uint32_t*>(&h23);
    *reinterpret_cast<uint2*>(&yh[(size_t)row * out_stride + tid * 4]) = packed;
}

// ---------------- pipelined HMMA GEMM: TERMS-term (A fp16, B hi[/lo]) ----------
#define RS 40                   // padded row stride (halfs): 80B
#define NST 3

__device__ __forceinline__ void cpa16(uint32_t sa, const void* ga, uint32_t ss) {
    asm volatile("cp.async.cg.shared.global [%0], [%1], 16, %2;"
                 :: "r"(sa), "l"(ga), "r"(ss) : "memory");
}

template<int BM, int BN, int TERMS>
__device__ __forceinline__ void load_stage(
    uint32_t sbase, const __half* __restrict__ A,
    const __half* __restrict__ Bh, const __half* __restrict__ Bl,
    int m0, int M, int n0, int N, int K, int k0, int tid)
{
    constexpr int ACH = BM * 4;
    constexpr int BCH = BN * 4;
    constexpr int ATB = BM * RS * 2;
    constexpr int BTB = BN * RS * 2;
    constexpr int CH_TOT = ACH + TERMS * BCH;
    constexpr int PER_T = CH_TOT / 256;
    #pragma unroll
    for (int t = 0; t < PER_T; t++) {
        int ch = tid + t * 256;
        const __half* src; int r0, lim; uint32_t tb; int idx;
        if (ch < ACH)            { src = A;  r0 = m0; lim = M; tb = 0;         idx = ch; }
        else if (ch < ACH + BCH) { src = Bh; r0 = n0; lim = N; tb = ATB;       idx = ch - ACH; }
        else                     { src = Bl; r0 = n0; lim = N; tb = ATB + BTB; idx = ch - ACH - BCH; }
        int row = idx >> 2, c4 = idx & 3;
        int gr = r0 + row;
        uint32_t ss = 16u;
        if (gr >= lim) { gr = lim - 1; ss = 0u; }
        const void* ga = src + (size_t)gr * K + k0 + c4 * 8;
        uint32_t sa = sbase + tb + (uint32_t)(row * RS + c4 * 8) * 2;
        cpa16(sa, ga, ss);
    }
}

#define LDSM_X4(r0, r1, r2, r3, addr) \
    asm volatile("ldmatrix.sync.aligned.m8n8.x4.shared.b16 {%0,%1,%2,%3}, [%4];" \
                 : "=r"(r0), "=r"(r1), "=r"(r2), "=r"(r3) : "r"(addr))

#define LDSM_X2(r0, r1, addr) \
    asm volatile("ldmatrix.sync.aligned.m8n8.x2.shared.b16 {%0,%1}, [%2];" \
                 : "=r"(r0), "=r"(r1) : "r"(addr))

#define MMA16816(c, a, b) \
    asm volatile("mma.sync.aligned.m16n8k16.row.col.f32.f16.f16.f32 " \
                 "{%0,%1,%2,%3}, {%4,%5,%6,%7}, {%8,%9}, {%0,%1,%2,%3};" \
                 : "+f"((c)[0]), "+f"((c)[1]), "+f"((c)[2]), "+f"((c)[3]) \
                 : "r"((a)[0]), "r"((a)[1]), "r"((a)[2]), "r"((a)[3]), \
                   "r"((b)[0]), "r"((b)[1]))

// ep: 0=+bias fp32 | 1=+bias+residual | 2=gelu->fp16 | 3=patch embed | 4=fused QKV (fp16 out)
template<int BM, int BN, int TERMS, int WROWS, int WCOLS>
__global__ __launch_bounds__(256) void hgemm(
    const __half* __restrict__ A,
    const __half* __restrict__ Bh, const __half* __restrict__ Bl,
    const float* __restrict__ bias, const float* __restrict__ extra,
    float* __restrict__ Cf, __half* __restrict__ Choh,
    int M, int N, int K, int ep, QKV qkv)
{
    constexpr int WTILE_M = BM / WROWS;
    constexpr int WTM     = WTILE_M / 16;
    constexpr int WTILE_N = BN / WCOLS;
    constexpr int WTN     = WTILE_N / 8;
    constexpr int ATB  = BM * RS * 2;
    constexpr int BTB  = BN * RS * 2;
    constexpr int STGB = ATB + TERMS * BTB;

    extern __shared__ __align__(16) char dsm[];
    uint32_t sb = (uint32_t)__cvta_generic_to_shared(dsm);
    int tid = threadIdx.x, wid = tid >> 5, lane = tid & 31;
    int warp_m = wid / WCOLS, warp_n = wid % WCOLS;
    int m0 = blockIdx.y * BM;
    int n0 = blockIdx.x * BN;
    int Nl = N;
    int epe = ep;
    const __half* Bh_ = Bh; const __half* Bl_ = Bl;
    const float* bias_ = bias; float* Cf_ = Cf; __half* Ch_ = Choh;
    if (ep == 4) {
        int seg = n0 / 768;
        Bh_ = qkv.bh[seg]; Bl_ = qkv.bl[seg];
        bias_ = qkv.bias[seg]; Ch_ = qkv.out[seg];
        n0 -= seg * 768; Nl = 768; epe = 6;
    }
    int wrow = warp_m * WTILE_M, wcol = warp_n * WTILE_N;

    float acc[WTM][WTN][4];
    #pragma unroll
    for (int i = 0; i < WTM; i++)
        #pragma unroll
        for (int j = 0; j < WTN; j++)
            #pragma unroll
            for (int r = 0; r < 4; r++) acc[i][j][r] = 0.0f;

    int NC = K >> 5;

    #pragma unroll
    for (int s = 0; s < NST - 1; s++) {
        load_stage<BM,BN,TERMS>(sb + s * STGB, A, Bh_, Bl_, m0, M, n0, Nl, K, s * 32, tid);
        asm volatile("cp.async.commit_group;" ::: "memory");
    }

    int a_off = (wrow + (lane & 15)) * RS + ((lane >> 4) << 3);
    int b_off = (wcol + (lane & 7) + ((lane >> 4) & 1) * 8) * RS
              + ((lane >> 3) & 1) * 8;

    for (int c = 0; c < NC; c++) {
        asm volatile("cp.async.wait_group 1;" ::: "memory");
        __syncthreads();

        int pf = c + NST - 1;
        if (pf < NC) {
            load_stage<BM,BN,TERMS>(sb + (pf % NST) * STGB, A, Bh_, Bl_, m0, M, n0, Nl, K,
                                    pf * 32, tid);
        }
        asm volatile("cp.async.commit_group;" ::: "memory");

        uint32_t stg = sb + (c % NST) * STGB;
        uint32_t sA  = stg;
        uint32_t sBh = stg + ATB;
        uint32_t sBl = stg + ATB + BTB;

        #pragma unroll
        for (int ks = 0; ks < 2; ks++) {
            uint32_t a[WTM][4], bh[WTN][2], bl[WTN][2];
            #pragma unroll
            for (int mt = 0; mt < WTM; mt++) {
                uint32_t ad = sA + (uint32_t)(a_off + mt * 16 * RS + ks * 16) * 2;
                LDSM_X4(a[mt][0], a[mt][1], a[mt][2], a[mt][3], ad);
            }
            #pragma unroll
            for (int nb = 0; nb < WTN / 2; nb++) {
                uint32_t bd = sBh + (uint32_t)(b_off + nb * 16 * RS + ks * 16) * 2;
                LDSM_X4(bh[nb*2][0], bh[nb*2][1], bh[nb*2+1][0], bh[nb*2+1][1], bd);
                if (TERMS == 2) {
                    bd = sBl + (uint32_t)(b_off + nb * 16 * RS + ks * 16) * 2;
                    LDSM_X4(bl[nb*2][0], bl[nb*2][1], bl[nb*2+1][0], bl[nb*2+1][1], bd);
                }
            }
            #pragma unroll
            for (int mt = 0; mt < WTM; mt++)
                #pragma unroll
                for (int nt = 0; nt < WTN; nt++) MMA16816(acc[mt][nt], a[mt], bh[nt]);
            if (TERMS == 2) {
                #pragma unroll
                for (int mt = 0; mt < WTM; mt++)
                    #pragma unroll
                    for (int nt = 0; nt < WTN; nt++) MMA16816(acc[mt][nt], a[mt], bl[nt]);
            }
        }
    }

    // ---------------- epilogue ----------------
    int r  = lane >> 2;
    int c2 = (lane & 3) * 2;
    #pragma unroll
    for (int mt = 0; mt < WTM; mt++) {
        #pragma unroll
        for (int nt = 0; nt < WTN; nt++) {
            int n = n0 + wcol + nt * 8 + c2;
            if (n >= Nl) continue;
            float bn0 = bias_[n], bn1 = bias_[n + 1];
            #pragma unroll
            for (int hh = 0; hh < 2; hh++) {
                int m = m0 + wrow + mt * 16 + r + hh * 8;
                if (m >= M) continue;
                float v0 = acc[mt][nt][hh * 2 + 0] + bn0;
                float v1 = acc[mt][nt][hh * 2 + 1] + bn1;
                if (epe == 0) {
                    *reinterpret_cast<float2*>(&Cf_[(size_t)m * Nl + n]) =
                        make_float2(v0, v1);
                } else if (epe == 6) {
                    *reinterpret_cast<__half2*>(&Ch_[(size_t)m * Nl + n]) =
                        __halves2half2(__float2half_rn(v0), __float2half_rn(v1));
                } else if (epe == 1) {
                    float2 e = *reinterpret_cast<const float2*>(&extra[(size_t)m * Nl + n]);
                    *reinterpret_cast<float2*>(&Cf_[(size_t)m * Nl + n]) =
                        make_float2(v0 + e.x, v1 + e.y);
                } else if (epe == 2) {
                    v0 = 0.5f * v0 * (1.0f + erff(v0 * 0.70710678118654752f));
                    v1 = 0.5f * v1 * (1.0f + erff(v1 * 0.70710678118654752f));
                    *reinterpret_cast<__half2*>(&Ch_[(size_t)m * Nl + n]) =
                        __halves2half2(__float2half_rn(v0), __float2half_rn(v1));
                } else {
                    int bb = m / NPATCH, p = m % NPATCH;
                    float2 e = *reinterpret_cast<const float2*>(&extra[(size_t)p * DIM + n]);
                    *reinterpret_cast<float2*>(
                        &Cf_[((size_t)(bb * SEQ + p + 1)) * DIM + n]) =
                        make_float2(v0 + e.x, v1 + e.y);
                }
            }
        }
    }
}

// ---------------- tensor-core attention ----------------
#define SP 208
#define QK_RS 72     // Qs/Ks row stride (halfs), 144B
#define PT_RS 216    // P/VT row stride (halfs), 432B
#define S_RS 212     // S row stride (floats), 848B
#define MPASS 96
#define QS_OFF 0
#define KS_OFF 29952
#define VT_OFF 59904
#define S_OFF  87552
#define P_OFF  168960
#define AMEM   210432

__global__ __launch_bounds__(256) void attn_mma(
    const __half* __restrict__ q, const __half* __restrict__ k,
    const __half* __restrict__ v, __half* __restrict__ oh)
{
    extern __shared__ __align__(16) char dsm[];
    uint32_t sb = (uint32_t)__cvta_generic_to_shared(dsm);
    int bh = blockIdx.x, b = bh / NH, h = bh % NH;
    int tid = threadIdx.x, wid = tid >> 5, lane = tid & 31;

    const __half* qg = q + (size_t)b * SEQ * DIM + h * HD;
    const __half* kg = k + (size_t)b * SEQ * DIM + h * HD;
    const __half* vg = v + (size_t)b * SEQ * DIM + h * HD;

    for (int ch = tid; ch < SP * 8; ch += 256) {
        int row = ch >> 3, c8 = (ch & 7) * 8;
        uint32_t qa = sb + QS_OFF + (uint32_t)(row * QK_RS + c8) * 2;
        uint32_t ka = sb + KS_OFF + (uint32_t)(row * QK_RS + c8) * 2;
        if (row < SEQ) {
            cpa16(qa, qg + (size_t)row * DIM + c8, 16);
            cpa16(ka, kg + (size_t)row * DIM + c8, 16);
        } else {
            asm volatile("st.shared.v4.b32 [%0], {%1,%1,%1,%1};"
                         :: "r"(qa), "r"(0) : "memory");
            asm volatile("st.shared.v4.b32 [%0], {%1,%1,%1,%1};"
                         :: "r"(ka), "r"(0) : "memory");
        }
    }
    asm volatile("cp.async.commit_group;" ::: "memory");
    // V transposed (vectorized gmem reads: 2 e-values per thread)
    for (int i = tid; i < SP * 32; i += 256) {
        int e2 = (i & 31) * 2, j = i >> 5;
        __half2 val = (j < SEQ)
            ? *reinterpret_cast<const __half2*>(&vg[(size_t)j * DIM + e2])
            : __halves2half2(__ushort_as_half(0), __ushort_as_half(0));
        uint16_t b0 = __half_as_ushort(__low2half(val));
        uint16_t b1 = __half_as_ushort(__high2half(val));
        asm volatile("st.shared.u16 [%0], %1;"
                     :: "r"(sb + VT_OFF + (uint32_t)(e2 * PT_RS + j) * 2), "h"(b0)
                     : "memory");
        asm volatile("st.shared.u16 [%0], %1;"
                     :: "r"(sb + VT_OFF + (uint32_t)((e2 + 1) * PT_RS + j) * 2), "h"(b1)
                     : "memory");
    }
    asm volatile("cp.async.wait_group 0;" ::: "memory");
    __syncthreads();

    int p0   = (wid < 5) ? 2 * wid : 10 + (wid - 5);
    int pcnt = (wid < 5) ? 2 : 1;
    int r4 = lane >> 2, c2 = (lane & 3) * 2;

    for (int m0 = 0; m0 < SEQ; m0 += MPASS) {
        int mt_cnt = (SEQ - m0 + 15) >> 4; if (mt_cnt > 6) mt_cnt = 6;

        float acc[6][4][4];
        #pragma unroll
        for (int i = 0; i < 6; i++)
            #pragma unroll
            for (int j = 0; j < 4; j++)
                #pragma unroll
                for (int r = 0; r < 4; r++) acc[i][j][r] = 0.f;
        #pragma unroll
        for (int ks = 0; ks < 4; ks++) {
            uint32_t a[6][4];
            for (int mt = 0; mt < mt_cnt; mt++) {
                uint32_t ad = sb + QS_OFF + (uint32_t)(
                    (m0 + mt * 16 + (lane & 15)) * QK_RS + ((lane >> 4) << 3) + ks * 16) * 2;
                LDSM_X4(a[mt][0], a[mt][1], a[mt][2], a[mt][3], ad);
            }
            for (int p = 0; p < pcnt; p++) {
                uint32_t b0[2], b1[2];
                uint32_t bd = sb + KS_OFF + (uint32_t)(
                    ((p0 + p) * 16 + (lane & 7) + ((lane >> 4) & 1) * 8) * QK_RS
                    + ((lane >> 3) & 1) * 8 + ks * 16) * 2;
                LDSM_X4(b0[0], b0[1], b1[0], b1[1], bd);
                for (int mt = 0; mt < mt_cnt; mt++) {
                    MMA16816(acc[mt][p * 2 + 0], a[mt], b0);
                    MMA16816(acc[mt][p * 2 + 1], a[mt], b1);
                }
            }
        }
        for (int mt = 0; mt < mt_cnt; mt++)
            for (int p = 0; p < pcnt; p++)
                #pragma unroll
                for (int t = 0; t < 2; t++) {
                    int col = (p0 + p) * 16 + t * 8 + c2;
                    #pragma unroll
                    for (int hh = 0; hh < 2; hh++) {
                        int row = mt * 16 + r4 + hh * 8;
                        *reinterpret_cast<float2*>(
                            dsm + S_OFF + ((size_t)row * S_RS + col) * 4) =
                            make_float2(acc[mt][p*2+t][hh*2], acc[mt][p*2+t][hh*2+1]);
                    }
                }
        __syncthreads();

        int rows = mt_cnt * 16;
        for (int r = wid; r < rows; r += 8) {
            const float* Srow = reinterpret_cast<const float*>(dsm + S_OFF + (size_t)r * S_RS * 4);
            float mx = -3.0e38f;
            for (int c = lane; c < SEQ; c += 32)
                mx = fmaxf(mx, Srow[c] * 0.125f);
            #pragma unroll
            for (int o = 16; o; o >>= 1) mx = fmaxf(mx, __shfl_xor_sync(0xffffffffu, mx, o));
            float pv[7];
            int cnt = 0;
            float sum = 0.f;
            for (int c = lane; c < SEQ; c += 32) {
                float p = __expf(Srow[c] * 0.125f - mx);
                pv[cnt++] = p; sum += p;
            }
            #pragma unroll
            for (int o = 16; o; o >>= 1) sum += __shfl_xor_sync(0xffffffffu, sum, o);
            float inv = 1.0f / sum;
            __half* Prow = reinterpret_cast<__half*>(dsm + P_OFF + (size_t)r * PT_RS * 2);
            cnt = 0;
            for (int c = lane; c < PT_RS; c += 32) {
                __half val;
                if (c < SEQ) { val = __float2half_rn(pv[cnt] * inv); cnt++; }
                else val = __ushort_as_half((uint16_t)0);
                Prow[c] = val;
            }
        }
        __syncthreads();

        float oacc[6][4];
        #pragma unroll
        for (int i = 0; i < 6; i++)
            #pragma unroll
            for (int r = 0; r < 4; r++) oacc[i][r] = 0.f;
        int l = lane & 15;
        for (int ks = 0; ks < 13; ks++) {
            uint32_t a[6][4];
            for (int mt = 0; mt < mt_cnt; mt++) {
                uint32_t ad = sb + P_OFF + (uint32_t)(
                    (mt * 16 + (lane & 15)) * PT_RS + ((lane >> 4) << 3) + ks * 16) * 2;
                LDSM_X4(a[mt][0], a[mt][1], a[mt][2], a[mt][3], ad);
            }
            uint32_t bfr[2];
            uint32_t bd = sb + VT_OFF + (uint32_t)(
                (wid * 8 + (l & 7)) * PT_RS + ((l >> 3) & 1) * 8 + ks * 16) * 2;
            LDSM_X2(bfr[0], bfr[1], bd);
            for (int mt = 0; mt < mt_cnt; mt++)
                MMA16816(oacc[mt], a[mt], bfr);
        }
        for (int mt = 0; mt < mt_cnt; mt++)
            #pragma unroll
            for (int hh = 0; hh < 2; hh++) {
                int gr = m0 + mt * 16 + r4 + hh * 8;
                if (gr >= SEQ) continue;
                *reinterpret_cast<__half2*>(
                    &oh[((size_t)(b * SEQ + gr)) * DIM + h * HD + wid * 8 + c2]) =
                    __halves2half2(__float2half_rn(oacc[mt][hh*2]),
                                   __float2half_rn(oacc[mt][hh*2+1]));
            }
        __syncthreads();
    }
}

// ---------------- host orchestration ----------------
#define GS_2T_128 (NST * (128*RS*2 + 2*128*RS*2))   // 92160
#define GS_2T_64  (NST * (128*RS*2 + 2*64*RS*2))    // 61440
#define GS_1T_128 (NST * (128*RS*2 + 128*RS*2))     // 61440

extern "C" void kernel_launch(void* const* d_in, const int* in_sizes, int n_in,
                              void* d_out, int out_size) {
    const float* images    = (const float*)d_in[0];
    const float* patch_W   = (const float*)d_in[1];
    const float* patch_b   = (const float*)d_in[2];
    const float* pos_emb   = (const float*)d_in[3];
    const float* cls       = (const float*)d_in[4];
    const float* ln1_g     = (const float*)d_in[5];
    const float* ln1_b     = (const float*)d_in[6];
    const float* Wq        = (const float*)d_in[7];
    const float* bq        = (const float*)d_in[8];
    const float* Wk        = (const float*)d_in[9];
    const float* bk        = (const float*)d_in[10];
    const float* Wv        = (const float*)d_in[11];
    const float* bv        = (const float*)d_in[12];
    const float* Wo        = (const float*)d_in[13];
    const float* bo        = (const float*)d_in[14];
    const float* ln2_g     = (const float*)d_in[15];
    const float* ln2_b     = (const float*)d_in[16];
    const float* W1        = (const float*)d_in[17];
    const float* b1        = (const float*)d_in[18];
    const float* W2        = (const float*)d_in[19];
    const float* b2        = (const float*)d_in[20];
    const float* head_g    = (const float*)d_in[21];
    const float* head_bn   = (const float*)d_in[22];
    const float* head_W    = (const float*)d_in[23];
    const float* head_bias = (const float*)d_in[24];

    float *x;
    __half *q16, *k16, *v16;
    __half *xn, *oo, *hbuf, *pbuf, *cls16;
    __half *wpH, *wpL, *wqH, *wqL, *wkH, *wkL, *wvH, *wvL, *woH, *woL;
    __half *w1H, *w2H, *whH, *whL;
    cudaGetSymbolAddress((void**)&x,     g_x);
    cudaGetSymbolAddress((void**)&q16,   g_q);
    cudaGetSymbolAddress((void**)&k16,   g_k);
    cudaGetSymbolAddress((void**)&v16,   g_v);
    cudaGetSymbolAddress((void**)&xn,    g_xn);
    cudaGetSymbolAddress((void**)&oo,    g_o);
    cudaGetSymbolAddress((void**)&hbuf,  g_h);
    cudaGetSymbolAddress((void**)&pbuf,  g_p);
    cudaGetSymbolAddress((void**)&cls16, g_cls16);
    cudaGetSymbolAddress((void**)&wpH, w_pat_h);cudaGetSymbolAddress((void**)&wpL, w_pat_l);
    cudaGetSymbolAddress((void**)&wqH, w_q_h);  cudaGetSymbolAddress((void**)&wqL, w_q_l);
    cudaGetSymbolAddress((void**)&wkH, w_k_h);  cudaGetSymbolAddress((void**)&wkL, w_k_l);
    cudaGetSymbolAddress((void**)&wvH, w_v_h);  cudaGetSymbolAddress((void**)&wvL, w_v_l);
    cudaGetSymbolAddress((void**)&woH, w_o_h);  cudaGetSymbolAddress((void**)&woL, w_o_l);
    cudaGetSymbolAddress((void**)&w1H, w_1_h);
    cudaGetSymbolAddress((void**)&w2H, w_2_h);
    cudaGetSymbolAddress((void**)&whH, w_hd_h); cudaGetSymbolAddress((void**)&whL, w_hd_l);

    cudaFuncSetAttribute(hgemm<128,128,2,2,4>, cudaFuncAttributeMaxDynamicSharedMemorySize, GS_2T_128);
    cudaFuncSetAttribute(hgemm<128,64,2,2,4>,  cudaFuncAttributeMaxDynamicSharedMemorySize, GS_2T_64);
    cudaFuncSetAttribute(hgemm<128,128,1,2,4>, cudaFuncAttributeMaxDynamicSharedMemorySize, GS_1T_128);
    cudaFuncSetAttribute(attn_mma, cudaFuncAttributeMaxDynamicSharedMemorySize, AMEM);

    QKV dummy = {};

    dim3 tblk(32, 8);
    wprep<<<dim3(24, 24, 1),   tblk>>>(patch_W, wpH, wpL, DIM, DIM);
    wprep<<<dim3(2, 24, 144),  tblk>>>(Wq, wqH, wqL, DIM, HD);
    wprep<<<dim3(2, 24, 144),  tblk>>>(Wk, wkH, wkL, DIM, HD);
    wprep<<<dim3(2, 24, 144),  tblk>>>(Wv, wvH, wvL, DIM, HD);
    wprep<<<dim3(24, 24, 12),  tblk>>>(Wo, woH, woL, DIM, DIM);
    wprep<<<dim3(96, 24, 12),  tblk>>>(W1, w1H, nullptr, DIM, FF);
    wprep<<<dim3(24, 96, 12),  tblk>>>(W2, w2H, nullptr, FF, DIM);
    wprep<<<dim3(32, 24, 1),   tblk>>>(head_W, whH, whL, DIM, NCLS);

    patch_extract<<<(PTOK * DIM + 255) / 256, 256>>>(images, pbuf);
    hgemm<128,128,2,2,4><<<dim3(6, 49), 256, GS_2T_128>>>(
        pbuf, wpH, wpL, patch_b, pos_emb, x, nullptr,
        PTOK, DIM, DIM, 3, dummy);
    cls_fill<<<(BB * DIM + 255) / 256, 256>>>(cls, x);

    for (int l = 0; l < NL; l++) {
        size_t wo768 = (size_t)l * DIM * DIM;
        size_t woff  = (size_t)l * DIM * FF;

        ln_kernel<<<TOK, 192>>>(x, ln1_g + l * DIM, ln1_b + l * DIM, xn, DIM, DIM);

        QKV qk;
        qk.bh[0] = wqH + wo768; qk.bh[1] = wkH + wo768; qk.bh[2] = wvH + wo768;
        qk.bl[0] = wqL + wo768; qk.bl[1] = wkL + wo768; qk.bl[2] = wvL + wo768;
        qk.bias[0] = bq + l * DIM; qk.bias[1] = bk + l * DIM; qk.bias[2] = bv + l * DIM;
        qk.out[0] = q16; qk.out[1] = k16; qk.out[2] = v16;
        hgemm<128,128,2,2,4><<<dim3(18, 50), 256, GS_2T_128>>>(
            xn, nullptr, nullptr, nullptr, nullptr, nullptr, nullptr,
            TOK, 2304, DIM, 4, qk);

        attn_mma<<<BB * NH, 256, AMEM>>>(q16, k16, v16, oo);

        hgemm<128,64,2,2,4><<<dim3(12, 50), 256, GS_2T_64>>>(
            oo, woH + wo768, woL + wo768, bo + l * DIM, x, x, nullptr,
            TOK, DIM, DIM, 1, dummy);

        ln_kernel<<<TOK, 192>>>(x, ln2_g + l * DIM, ln2_b + l * DIM, xn, DIM, DIM);

        hgemm<128,128,1,2,4><<<dim3(24, 50), 256, GS_1T_128>>>(
            xn, w1H + woff, nullptr, b1 + l * FF, nullptr, nullptr,
            hbuf, TOK, FF, DIM, 2, dummy);
        hgemm<128,128,1,2,4><<<dim3(6, 50), 256, GS_1T_128>>>(
            hbuf, w2H + woff, nullptr, b2 + l * DIM, x, x, nullptr,
            TOK, DIM, FF, 1, dummy);
    }

    ln_kernel<<<BB, 192>>>(x, head_g, head_bn, cls16, (long long)SEQ * DIM, DIM);
    hgemm<128,128,2,2,4><<<dim3(8, 1), 256, GS_2T_128>>>(
        cls16, whH, whL, head_bias, nullptr, (float*)d_out, nullptr,
        BB, NCLS, DIM, 0, dummy);
}

// round 15
// speedup vs baseline: 2.0924x; 1.0057x over previous
#include <cuda_runtime.h>
#include <cuda_fp16.h>
#include <cstdint>

#define BB 32
#define IMGSZ 224
#define PSZ 16
#define NSIDE 14
#define NPATCH 196
#define SEQ 197
#define DIM 768
#define NH 12
#define HD 64
#define FF 3072
#define NL 12
#define NCLS 1000
#define TOK (BB*SEQ)     // 6304
#define PTOK (BB*NPATCH) // 6272

// PDL: wait for upstream grids (no-op if launched without programmatic dep)
__device__ __forceinline__ void pdl_sync() {
#if defined(__CUDA_ARCH__) && (__CUDA_ARCH__ >= 900)
    cudaGridDependencySynchronize();
#endif
}

// ---------------- scratch (device globals: allocation-free) ----------------
__device__ float  g_x[TOK*DIM];
__device__ __half g_q[TOK*DIM];
__device__ __half g_k[TOK*DIM];
__device__ __half g_v[TOK*DIM];

__device__ __half g_xn[TOK*DIM];
__device__ __half g_o[TOK*DIM];
__device__ __half g_h[(size_t)TOK*FF];
__device__ __half g_p[(size_t)PTOK*DIM];
__device__ __half g_cls16[BB*DIM];

// transposed fp16 hi/lo weights: [N][K] layout per layer (lo only where used)
__device__ __half w_pat_h[589824],  w_pat_l[589824];
__device__ __half w_q_h[7077888],   w_q_l[7077888];
__device__ __half w_k_h[7077888],   w_k_l[7077888];
__device__ __half w_v_h[7077888],   w_v_l[7077888];
__device__ __half w_o_h[7077888],   w_o_l[7077888];
__device__ __half w_1_h[28311552];
__device__ __half w_2_h[28311552];
__device__ __half w_hd_h[768000],   w_hd_l[768000];

struct QKV {
    const __half* bh[3];
    const __half* bl[3];
    const float*  bias[3];
    __half*       out[3];
};

// ---------------- weight transpose + hi[/lo] split ----------------
__global__ void wprep(const float* __restrict__ in, __half* __restrict__ oh,
                      __half* __restrict__ ol, int K, int ng) {
    __shared__ float t[32][33];
    int g = blockIdx.z;
    int e0 = blockIdx.x * 32, k0 = blockIdx.y * 32;
    int tx = threadIdx.x, ty = threadIdx.y;  // 32x8
    const float* gin = in + (size_t)g * K * ng;
    #pragma unroll
    for (int i = 0; i < 4; i++) {
        int kk = k0 + ty + i * 8;
        int e  = e0 + tx;
        float v = 0.f;
        if (e < ng) v = gin[(size_t)kk * ng + e];
        t[ty + i * 8][tx] = v;
    }
    __syncthreads();
    __half* goh = oh + (size_t)g * ng * K;
    __half* gol = (ol != nullptr) ? ol + (size_t)g * ng * K : nullptr;
    #pragma unroll
    for (int i = 0; i < 4; i++) {
        int e  = e0 + ty + i * 8;
        int kk = k0 + tx;
        if (e < ng) {
            float v = t[tx][ty + i * 8];
            __half hv = __float2half_rn(v);
            goh[(size_t)e * K + kk] = hv;
            if (gol != nullptr)
                gol[(size_t)e * K + kk] = __float2half_rn(v - __half2float(hv));
        }
    }
}

// ---------------- patch extraction (fp16) ----------------
__global__ void patch_extract(const float* __restrict__ img,
                              __half* __restrict__ oh) {
    int idx = blockIdx.x * 256 + threadIdx.x;
    if (idx >= PTOK * DIM) return;
    int kcol = idx % DIM;
    int row  = idx / DIM;
    int b  = row / NPATCH;
    int p  = row % NPATCH;
    int pr = p / NSIDE, pc = p % NSIDE;
    int c  = kcol % 3;
    int t  = kcol / 3;
    int py = t / PSZ, px = t % PSZ;
    float v = img[(((size_t)(b*IMGSZ + pr*PSZ + py) * IMGSZ) + pc*PSZ + px) * 3 + c];
    oh[idx] = __float2half_rn(v);
}

__global__ void cls_fill(const float* __restrict__ cls, float* __restrict__ x) {
    int i = blockIdx.x * 256 + threadIdx.x;
    if (i < BB * DIM) x[(size_t)(i / DIM) * SEQ * DIM + (i % DIM)] = cls[i % DIM];
}

// ---------------- LayerNorm (fp32 in, fp16 out), 192 thr x float4 -------------
__global__ void ln_kernel(const float* __restrict__ x, const float* __restrict__ g,
                          const float* __restrict__ bt,
                          __half* __restrict__ yh,
                          long long in_stride, long long out_stride) {
    int row = blockIdx.x;
    int tid = threadIdx.x;          // 0..191
    int wid = tid >> 5, lane = tid & 31;
    pdl_sync();
    const float* xr = x + (size_t)row * in_stride;
    float4 v = *reinterpret_cast<const float4*>(&xr[tid * 4]);

    __shared__ float red1[6];
    __shared__ float red2[6];

    float s = v.x + v.y + v.z + v.w;
    #pragma unroll
    for (int o = 16; o; o >>= 1) s += __shfl_xor_sync(0xffffffffu, s, o);
    if (lane == 0) red1[wid] = s;
    __syncthreads();
    if (tid == 0) {
        float t = red1[0];
        #pragma unroll
        for (int i = 1; i < 6; i++) t += red1[i];
        red1[0] = t;
    }
    __syncthreads();
    float mean = red1[0] * (1.0f / 768.0f);

    float dx = v.x - mean, dy = v.y - mean, dz = v.z - mean, dw = v.w - mean;
    float q = dx*dx + dy*dy + dz*dz + dw*dw;
    #pragma unroll
    for (int o = 16; o; o >>= 1) q += __shfl_xor_sync(0xffffffffu, q, o);
    if (lane == 0) red2[wid] = q;
    __syncthreads();
    if (tid == 0) {
        float t = red2[0];
        #pragma unroll
        for (int i = 1; i < 6; i++) t += red2[i];
        red2[0] = t;
    }
    __syncthreads();
    float var = red2[0] * (1.0f / 768.0f);
    float r = rsqrtf(var + 1e-5f);

    float4 gg = *reinterpret_cast<const float4*>(&g[tid * 4]);
    float4 bb = *reinterpret_cast<const float4*>(&bt[tid * 4]);
    __half2 h01 = __floats2half2_rn(dx * r * gg.x + bb.x, dy * r * gg.y + bb.y);
    __half2 h23 = __floats2half2_rn(dz * r * gg.z + bb.z, dw * r * gg.w + bb.w);
    uint2 packed;
    packed.x = *reinterpret_cast<uint32_t*>(&h01);
    packed.y = *reinterpret_cast<uint32_t*>(&h23);
    *reinterpret_cast<uint2*>(&yh[(size_t)row * out_stride + tid * 4]) = packed;
}

// ---------------- pipelined HMMA GEMM: TERMS-term (A fp16, B hi[/lo]) ----------
#define RS 40                   // padded row stride (halfs): 80B
#define NST 3

__device__ __forceinline__ void cpa16(uint32_t sa, const void* ga, uint32_t ss) {
    asm volatile("cp.async.cg.shared.global [%0], [%1], 16, %2;"
                 :: "r"(sa), "l"(ga), "r"(ss) : "memory");
}

template<int BM, int BN, int TERMS>
__device__ __forceinline__ void load_stage(
    uint32_t sbase, const __half* __restrict__ A,
    const __half* __restrict__ Bh, const __half* __restrict__ Bl,
    int m0, int M, int n0, int N, int K, int k0, int tid)
{
    constexpr int ACH = BM * 4;
    constexpr int BCH = BN * 4;
    constexpr int ATB = BM * RS * 2;
    constexpr int BTB = BN * RS * 2;
    constexpr int CH_TOT = ACH + TERMS * BCH;
    constexpr int PER_T = CH_TOT / 256;
    #pragma unroll
    for (int t = 0; t < PER_T; t++) {
        int ch = tid + t * 256;
        const __half* src; int r0, lim; uint32_t tb; int idx;
        if (ch < ACH)            { src = A;  r0 = m0; lim = M; tb = 0;         idx = ch; }
        else if (ch < ACH + BCH) { src = Bh; r0 = n0; lim = N; tb = ATB;       idx = ch - ACH; }
        else                     { src = Bl; r0 = n0; lim = N; tb = ATB + BTB; idx = ch - ACH - BCH; }
        int row = idx >> 2, c4 = idx & 3;
        int gr = r0 + row;
        uint32_t ss = 16u;
        if (gr >= lim) { gr = lim - 1; ss = 0u; }
        const void* ga = src + (size_t)gr * K + k0 + c4 * 8;
        uint32_t sa = sbase + tb + (uint32_t)(row * RS + c4 * 8) * 2;
        cpa16(sa, ga, ss);
    }
}

#define LDSM_X4(r0, r1, r2, r3, addr) \
    asm volatile("ldmatrix.sync.aligned.m8n8.x4.shared.b16 {%0,%1,%2,%3}, [%4];" \
                 : "=r"(r0), "=r"(r1), "=r"(r2), "=r"(r3) : "r"(addr))

#define LDSM_X2(r0, r1, addr) \
    asm volatile("ldmatrix.sync.aligned.m8n8.x2.shared.b16 {%0,%1}, [%2];" \
                 : "=r"(r0), "=r"(r1) : "r"(addr))

#define MMA16816(c, a, b) \
    asm volatile("mma.sync.aligned.m16n8k16.row.col.f32.f16.f16.f32 " \
                 "{%0,%1,%2,%3}, {%4,%5,%6,%7}, {%8,%9}, {%0,%1,%2,%3};" \
                 : "+f"((c)[0]), "+f"((c)[1]), "+f"((c)[2]), "+f"((c)[3]) \
                 : "r"((a)[0]), "r"((a)[1]), "r"((a)[2]), "r"((a)[3]), \
                   "r"((b)[0]), "r"((b)[1]))

// ep: 0=+bias fp32 | 1=+bias+residual | 2=gelu->fp16 | 3=patch embed | 4=fused QKV (fp16 out)
template<int BM, int BN, int TERMS, int WROWS, int WCOLS>
__global__ __launch_bounds__(256) void hgemm(
    const __half* __restrict__ A,
    const __half* __restrict__ Bh, const __half* __restrict__ Bl,
    const float* __restrict__ bias, const float* __restrict__ extra,
    float* __restrict__ Cf, __half* __restrict__ Choh,
    int M, int N, int K, int ep, QKV qkv)
{
    constexpr int WTILE_M = BM / WROWS;
    constexpr int WTM     = WTILE_M / 16;
    constexpr int WTILE_N = BN / WCOLS;
    constexpr int WTN     = WTILE_N / 8;
    constexpr int ATB  = BM * RS * 2;
    constexpr int BTB  = BN * RS * 2;
    constexpr int STGB = ATB + TERMS * BTB;

    extern __shared__ __align__(16) char dsm[];
    uint32_t sb = (uint32_t)__cvta_generic_to_shared(dsm);
    int tid = threadIdx.x, wid = tid >> 5, lane = tid & 31;
    int warp_m = wid / WCOLS, warp_n = wid % WCOLS;
    int m0 = blockIdx.y * BM;
    int n0 = blockIdx.x * BN;
    int Nl = N;
    int epe = ep;
    const __half* Bh_ = Bh; const __half* Bl_ = Bl;
    const float* bias_ = bias; float* Cf_ = Cf; __half* Ch_ = Choh;
    if (ep == 4) {
        int seg = n0 / 768;
        Bh_ = qkv.bh[seg]; Bl_ = qkv.bl[seg];
        bias_ = qkv.bias[seg]; Ch_ = qkv.out[seg];
        n0 -= seg * 768; Nl = 768; epe = 6;
    }
    int wrow = warp_m * WTILE_M, wcol = warp_n * WTILE_N;

    float acc[WTM][WTN][4];
    #pragma unroll
    for (int i = 0; i < WTM; i++)
        #pragma unroll
        for (int j = 0; j < WTN; j++)
            #pragma unroll
            for (int r = 0; r < 4; r++) acc[i][j][r] = 0.0f;

    int NC = K >> 5;

    pdl_sync();   // wait on producer before first global read

    #pragma unroll
    for (int s = 0; s < NST - 1; s++) {
        load_stage<BM,BN,TERMS>(sb + s * STGB, A, Bh_, Bl_, m0, M, n0, Nl, K, s * 32, tid);
        asm volatile("cp.async.commit_group;" ::: "memory");
    }

    int a_off = (wrow + (lane & 15)) * RS + ((lane >> 4) << 3);
    int b_off = (wcol + (lane & 7) + ((lane >> 4) & 1) * 8) * RS
              + ((lane >> 3) & 1) * 8;

    for (int c = 0; c < NC; c++) {
        asm volatile("cp.async.wait_group 1;" ::: "memory");
        __syncthreads();

        int pf = c + NST - 1;
        if (pf < NC) {
            load_stage<BM,BN,TERMS>(sb + (pf % NST) * STGB, A, Bh_, Bl_, m0, M, n0, Nl, K,
                                    pf * 32, tid);
        }
        asm volatile("cp.async.commit_group;" ::: "memory");

        uint32_t stg = sb + (c % NST) * STGB;
        uint32_t sA  = stg;
        uint32_t sBh = stg + ATB;
        uint32_t sBl = stg + ATB + BTB;

        #pragma unroll
        for (int ks = 0; ks < 2; ks++) {
            uint32_t a[WTM][4], bh[WTN][2], bl[WTN][2];
            #pragma unroll
            for (int mt = 0; mt < WTM; mt++) {
                uint32_t ad = sA + (uint32_t)(a_off + mt * 16 * RS + ks * 16) * 2;
                LDSM_X4(a[mt][0], a[mt][1], a[mt][2], a[mt][3], ad);
            }
            #pragma unroll
            for (int nb = 0; nb < WTN / 2; nb++) {
                uint32_t bd = sBh + (uint32_t)(b_off + nb * 16 * RS + ks * 16) * 2;
                LDSM_X4(bh[nb*2][0], bh[nb*2][1], bh[nb*2+1][0], bh[nb*2+1][1], bd);
                if (TERMS == 2) {
                    bd = sBl + (uint32_t)(b_off + nb * 16 * RS + ks * 16) * 2;
                    LDSM_X4(bl[nb*2][0], bl[nb*2][1], bl[nb*2+1][0], bl[nb*2+1][1], bd);
                }
            }
            #pragma unroll
            for (int mt = 0; mt < WTM; mt++)
                #pragma unroll
                for (int nt = 0; nt < WTN; nt++) MMA16816(acc[mt][nt], a[mt], bh[nt]);
            if (TERMS == 2) {
                #pragma unroll
                for (int mt = 0; mt < WTM; mt++)
                    #pragma unroll
                    for (int nt = 0; nt < WTN; nt++) MMA16816(acc[mt][nt], a[mt], bl[nt]);
            }
        }
    }

    // ---------------- epilogue ----------------
    int r  = lane >> 2;
    int c2 = (lane & 3) * 2;
    #pragma unroll
    for (int mt = 0; mt < WTM; mt++) {
        #pragma unroll
        for (int nt = 0; nt < WTN; nt++) {
            int n = n0 + wcol + nt * 8 + c2;
            if (n >= Nl) continue;
            float bn0 = bias_[n], bn1 = bias_[n + 1];
            #pragma unroll
            for (int hh = 0; hh < 2; hh++) {
                int m = m0 + wrow + mt * 16 + r + hh * 8;
                if (m >= M) continue;
                float v0 = acc[mt][nt][hh * 2 + 0] + bn0;
                float v1 = acc[mt][nt][hh * 2 + 1] + bn1;
                if (epe == 0) {
                    *reinterpret_cast<float2*>(&Cf_[(size_t)m * Nl + n]) =
                        make_float2(v0, v1);
                } else if (epe == 6) {
                    *reinterpret_cast<__half2*>(&Ch_[(size_t)m * Nl + n]) =
                        __halves2half2(__float2half_rn(v0), __float2half_rn(v1));
                } else if (epe == 1) {
                    float2 e = *reinterpret_cast<const float2*>(&extra[(size_t)m * Nl + n]);
                    *reinterpret_cast<float2*>(&Cf_[(size_t)m * Nl + n]) =
                        make_float2(v0 + e.x, v1 + e.y);
                } else if (epe == 2) {
                    v0 = 0.5f * v0 * (1.0f + erff(v0 * 0.70710678118654752f));
                    v1 = 0.5f * v1 * (1.0f + erff(v1 * 0.70710678118654752f));
                    *reinterpret_cast<__half2*>(&Ch_[(size_t)m * Nl + n]) =
                        __halves2half2(__float2half_rn(v0), __float2half_rn(v1));
                } else {
                    int bb = m / NPATCH, p = m % NPATCH;
                    float2 e = *reinterpret_cast<const float2*>(&extra[(size_t)p * DIM + n]);
                    *reinterpret_cast<float2*>(
                        &Cf_[((size_t)(bb * SEQ + p + 1)) * DIM + n]) =
                        make_float2(v0 + e.x, v1 + e.y);
                }
            }
        }
    }
}

// ---------------- tensor-core attention ----------------
#define SP 208
#define QK_RS 72     // Qs/Ks row stride (halfs), 144B
#define PT_RS 216    // P/VT row stride (halfs), 432B
#define S_RS 212     // S row stride (floats), 848B
#define MPASS 96
#define QS_OFF 0
#define KS_OFF 29952
#define VT_OFF 59904
#define S_OFF  87552
#define P_OFF  168960
#define AMEM   210432

__global__ __launch_bounds__(256) void attn_mma(
    const __half* __restrict__ q, const __half* __restrict__ k,
    const __half* __restrict__ v, __half* __restrict__ oh)
{
    extern __shared__ __align__(16) char dsm[];
    uint32_t sb = (uint32_t)__cvta_generic_to_shared(dsm);
    int bh = blockIdx.x, b = bh / NH, h = bh % NH;
    int tid = threadIdx.x, wid = tid >> 5, lane = tid & 31;

    const __half* qg = q + (size_t)b * SEQ * DIM + h * HD;
    const __half* kg = k + (size_t)b * SEQ * DIM + h * HD;
    const __half* vg = v + (size_t)b * SEQ * DIM + h * HD;

    pdl_sync();

    for (int ch = tid; ch < SP * 8; ch += 256) {
        int row = ch >> 3, c8 = (ch & 7) * 8;
        uint32_t qa = sb + QS_OFF + (uint32_t)(row * QK_RS + c8) * 2;
        uint32_t ka = sb + KS_OFF + (uint32_t)(row * QK_RS + c8) * 2;
        if (row < SEQ) {
            cpa16(qa, qg + (size_t)row * DIM + c8, 16);
            cpa16(ka, kg + (size_t)row * DIM + c8, 16);
        } else {
            asm volatile("st.shared.v4.b32 [%0], {%1,%1,%1,%1};"
                         :: "r"(qa), "r"(0) : "memory");
            asm volatile("st.shared.v4.b32 [%0], {%1,%1,%1,%1};"
                         :: "r"(ka), "r"(0) : "memory");
        }
    }
    asm volatile("cp.async.commit_group;" ::: "memory");
    for (int i = tid; i < SP * 32; i += 256) {
        int e2 = (i & 31) * 2, j = i >> 5;
        __half2 val = (j < SEQ)
            ? *reinterpret_cast<const __half2*>(&vg[(size_t)j * DIM + e2])
            : __halves2half2(__ushort_as_half(0), __ushort_as_half(0));
        uint16_t b0 = __half_as_ushort(__low2half(val));
        uint16_t b1 = __half_as_ushort(__high2half(val));
        asm volatile("st.shared.u16 [%0], %1;"
                     :: "r"(sb + VT_OFF + (uint32_t)(e2 * PT_RS + j) * 2), "h"(b0)
                     : "memory");
        asm volatile("st.shared.u16 [%0], %1;"
                     :: "r"(sb + VT_OFF + (uint32_t)((e2 + 1) * PT_RS + j) * 2), "h"(b1)
                     : "memory");
    }
    asm volatile("cp.async.wait_group 0;" ::: "memory");
    __syncthreads();

    int p0   = (wid < 5) ? 2 * wid : 10 + (wid - 5);
    int pcnt = (wid < 5) ? 2 : 1;
    int r4 = lane >> 2, c2 = (lane & 3) * 2;

    for (int m0 = 0; m0 < SEQ; m0 += MPASS) {
        int mt_cnt = (SEQ - m0 + 15) >> 4; if (mt_cnt > 6) mt_cnt = 6;

        float acc[6][4][4];
        #pragma unroll
        for (int i = 0; i < 6; i++)
            #pragma unroll
            for (int j = 0; j < 4; j++)
                #pragma unroll
                for (int r = 0; r < 4; r++) acc[i][j][r] = 0.f;
        #pragma unroll
        for (int ks = 0; ks < 4; ks++) {
            uint32_t a[6][4];
            for (int mt = 0; mt < mt_cnt; mt++) {
                uint32_t ad = sb + QS_OFF + (uint32_t)(
                    (m0 + mt * 16 + (lane & 15)) * QK_RS + ((lane >> 4) << 3) + ks * 16) * 2;
                LDSM_X4(a[mt][0], a[mt][1], a[mt][2], a[mt][3], ad);
            }
            for (int p = 0; p < pcnt; p++) {
                uint32_t b0[2], b1[2];
                uint32_t bd = sb + KS_OFF + (uint32_t)(
                    ((p0 + p) * 16 + (lane & 7) + ((lane >> 4) & 1) * 8) * QK_RS
                    + ((lane >> 3) & 1) * 8 + ks * 16) * 2;
                LDSM_X4(b0[0], b0[1], b1[0], b1[1], bd);
                for (int mt = 0; mt < mt_cnt; mt++) {
                    MMA16816(acc[mt][p * 2 + 0], a[mt], b0);
                    MMA16816(acc[mt][p * 2 + 1], a[mt], b1);
                }
            }
        }
        for (int mt = 0; mt < mt_cnt; mt++)
            for (int p = 0; p < pcnt; p++)
                #pragma unroll
                for (int t = 0; t < 2; t++) {
                    int col = (p0 + p) * 16 + t * 8 + c2;
                    #pragma unroll
                    for (int hh = 0; hh < 2; hh++) {
                        int row = mt * 16 + r4 + hh * 8;
                        *reinterpret_cast<float2*>(
                            dsm + S_OFF + ((size_t)row * S_RS + col) * 4) =
                            make_float2(acc[mt][p*2+t][hh*2], acc[mt][p*2+t][hh*2+1]);
                    }
                }
        __syncthreads();

        int rows = mt_cnt * 16;
        for (int r = wid; r < rows; r += 8) {
            const float* Srow = reinterpret_cast<const float*>(dsm + S_OFF + (size_t)r * S_RS * 4);
            float mx = -3.0e38f;
            for (int c = lane; c < SEQ; c += 32)
                mx = fmaxf(mx, Srow[c] * 0.125f);
            #pragma unroll
            for (int o = 16; o; o >>= 1) mx = fmaxf(mx, __shfl_xor_sync(0xffffffffu, mx, o));
            float pv[7];
            int cnt = 0;
            float sum = 0.f;
            for (int c = lane; c < SEQ; c += 32) {
                float p = __expf(Srow[c] * 0.125f - mx);
                pv[cnt++] = p; sum += p;
            }
            #pragma unroll
            for (int o = 16; o; o >>= 1) sum += __shfl_xor_sync(0xffffffffu, sum, o);
            float inv = 1.0f / sum;
            __half* Prow = reinterpret_cast<__half*>(dsm + P_OFF + (size_t)r * PT_RS * 2);
            cnt = 0;
            for (int c = lane; c < PT_RS; c += 32) {
                __half val;
                if (c < SEQ) { val = __float2half_rn(pv[cnt] * inv); cnt++; }
                else val = __ushort_as_half((uint16_t)0);
                Prow[c] = val;
            }
        }
        __syncthreads();

        float oacc[6][4];
        #pragma unroll
        for (int i = 0; i < 6; i++)
            #pragma unroll
            for (int r = 0; r < 4; r++) oacc[i][r] = 0.f;
        int l = lane & 15;
        for (int ks = 0; ks < 13; ks++) {
            uint32_t a[6][4];
            for (int mt = 0; mt < mt_cnt; mt++) {
                uint32_t ad = sb + P_OFF + (uint32_t)(
                    (mt * 16 + (lane & 15)) * PT_RS + ((lane >> 4) << 3) + ks * 16) * 2;
                LDSM_X4(a[mt][0], a[mt][1], a[mt][2], a[mt][3], ad);
            }
            uint32_t bfr[2];
            uint32_t bd = sb + VT_OFF + (uint32_t)(
                (wid * 8 + (l & 7)) * PT_RS + ((l >> 3) & 1) * 8 + ks * 16) * 2;
            LDSM_X2(bfr[0], bfr[1], bd);
            for (int mt = 0; mt < mt_cnt; mt++)
                MMA16816(oacc[mt], a[mt], bfr);
        }
        for (int mt = 0; mt < mt_cnt; mt++)
            #pragma unroll
            for (int hh = 0; hh < 2; hh++) {
                int gr = m0 + mt * 16 + r4 + hh * 8;
                if (gr >= SEQ) continue;
                *reinterpret_cast<__half2*>(
                    &oh[((size_t)(b * SEQ + gr)) * DIM + h * HD + wid * 8 + c2]) =
                    __halves2half2(__float2half_rn(oacc[mt][hh*2]),
                                   __float2half_rn(oacc[mt][hh*2+1]));
            }
        __syncthreads();
    }
}

// ---------------- host orchestration ----------------
#define GS_2T_128 (NST * (128*RS*2 + 2*128*RS*2))   // 92160
#define GS_2T_64  (NST * (128*RS*2 + 2*64*RS*2))    // 61440
#define GS_1T_128 (NST * (128*RS*2 + 128*RS*2))     // 61440

template<typename F, typename... Args>
static void pdl_launch(F func, dim3 grid, dim3 block, size_t smem, Args... args) {
    cudaLaunchConfig_t cfg = {};
    cfg.gridDim = grid;
    cfg.blockDim = block;
    cfg.dynamicSmemBytes = smem;
    cudaLaunchAttribute attr[1];
    attr[0].id = cudaLaunchAttributeProgrammaticStreamSerialization;
    attr[0].val.programmaticStreamSerializationAllowed = 1;
    cfg.attrs = attr;
    cfg.numAttrs = 1;
    cudaLaunchKernelEx(&cfg, func, args...);
}

extern "C" void kernel_launch(void* const* d_in, const int* in_sizes, int n_in,
                              void* d_out, int out_size) {
    const float* images    = (const float*)d_in[0];
    const float* patch_W   = (const float*)d_in[1];
    const float* patch_b   = (const float*)d_in[2];
    const float* pos_emb   = (const float*)d_in[3];
    const float* cls       = (const float*)d_in[4];
    const float* ln1_g     = (const float*)d_in[5];
    const float* ln1_b     = (const float*)d_in[6];
    const float* Wq        = (const float*)d_in[7];
    const float* bq        = (const float*)d_in[8];
    const float* Wk        = (const float*)d_in[9];
    const float* bk        = (const float*)d_in[10];
    const float* Wv        = (const float*)d_in[11];
    const float* bv        = (const float*)d_in[12];
    const float* Wo        = (const float*)d_in[13];
    const float* bo        = (const float*)d_in[14];
    const float* ln2_g     = (const float*)d_in[15];
    const float* ln2_b     = (const float*)d_in[16];
    const float* W1        = (const float*)d_in[17];
    const float* b1        = (const float*)d_in[18];
    const float* W2        = (const float*)d_in[19];
    const float* b2        = (const float*)d_in[20];
    const float* head_g    = (const float*)d_in[21];
    const float* head_bn   = (const float*)d_in[22];
    const float* head_W    = (const float*)d_in[23];
    const float* head_bias = (const float*)d_in[24];

    float *x;
    __half *q16, *k16, *v16;
    __half *xn, *oo, *hbuf, *pbuf, *cls16;
    __half *wpH, *wpL, *wqH, *wqL, *wkH, *wkL, *wvH, *wvL, *woH, *woL;
    __half *w1H, *w2H, *whH, *whL;
    cudaGetSymbolAddress((void**)&x,     g_x);
    cudaGetSymbolAddress((void**)&q16,   g_q);
    cudaGetSymbolAddress((void**)&k16,   g_k);
    cudaGetSymbolAddress((void**)&v16,   g_v);
    cudaGetSymbolAddress((void**)&xn,    g_xn);
    cudaGetSymbolAddress((void**)&oo,    g_o);
    cudaGetSymbolAddress((void**)&hbuf,  g_h);
    cudaGetSymbolAddress((void**)&pbuf,  g_p);
    cudaGetSymbolAddress((void**)&cls16, g_cls16);
    cudaGetSymbolAddress((void**)&wpH, w_pat_h);cudaGetSymbolAddress((void**)&wpL, w_pat_l);
    cudaGetSymbolAddress((void**)&wqH, w_q_h);  cudaGetSymbolAddress((void**)&wqL, w_q_l);
    cudaGetSymbolAddress((void**)&wkH, w_k_h);  cudaGetSymbolAddress((void**)&wkL, w_k_l);
    cudaGetSymbolAddress((void**)&wvH, w_v_h);  cudaGetSymbolAddress((void**)&wvL, w_v_l);
    cudaGetSymbolAddress((void**)&woH, w_o_h);  cudaGetSymbolAddress((void**)&woL, w_o_l);
    cudaGetSymbolAddress((void**)&w1H, w_1_h);
    cudaGetSymbolAddress((void**)&w2H, w_2_h);
    cudaGetSymbolAddress((void**)&whH, w_hd_h); cudaGetSymbolAddress((void**)&whL, w_hd_l);

    cudaFuncSetAttribute(hgemm<128,128,2,2,4>, cudaFuncAttributeMaxDynamicSharedMemorySize, GS_2T_128);
    cudaFuncSetAttribute(hgemm<128,64,2,2,4>,  cudaFuncAttributeMaxDynamicSharedMemorySize, GS_2T_64);
    cudaFuncSetAttribute(hgemm<128,128,1,2,4>, cudaFuncAttributeMaxDynamicSharedMemorySize, GS_1T_128);
    cudaFuncSetAttribute(attn_mma, cudaFuncAttributeMaxDynamicSharedMemorySize, AMEM);

    QKV dummy = {};

    dim3 tblk(32, 8);
    wprep<<<dim3(24, 24, 1),   tblk>>>(patch_W, wpH, wpL, DIM, DIM);
    wprep<<<dim3(2, 24, 144),  tblk>>>(Wq, wqH, wqL, DIM, HD);
    wprep<<<dim3(2, 24, 144),  tblk>>>(Wk, wkH, wkL, DIM, HD);
    wprep<<<dim3(2, 24, 144),  tblk>>>(Wv, wvH, wvL, DIM, HD);
    wprep<<<dim3(24, 24, 12),  tblk>>>(Wo, woH, woL, DIM, DIM);
    wprep<<<dim3(96, 24, 12),  tblk>>>(W1, w1H, nullptr, DIM, FF);
    wprep<<<dim3(24, 96, 12),  tblk>>>(W2, w2H, nullptr, FF, DIM);
    wprep<<<dim3(32, 24, 1),   tblk>>>(head_W, whH, whL, DIM, NCLS);

    patch_extract<<<(PTOK * DIM + 255) / 256, 256>>>(images, pbuf);
    pdl_launch(hgemm<128,128,2,2,4>, dim3(6, 49), dim3(256), GS_2T_128,
               (const __half*)pbuf, (const __half*)wpH, (const __half*)wpL,
               patch_b, pos_emb, x, (__half*)nullptr,
               PTOK, DIM, DIM, 3, dummy);
    cls_fill<<<(BB * DIM + 255) / 256, 256>>>(cls, x);

    for (int l = 0; l < NL; l++) {
        size_t wo768 = (size_t)l * DIM * DIM;
        size_t woff  = (size_t)l * DIM * FF;

        pdl_launch(ln_kernel, dim3(TOK), dim3(192), 0,
                   (const float*)x, ln1_g + l * DIM, ln1_b + l * DIM, xn,
                   (long long)DIM, (long long)DIM);

        QKV qk;
        qk.bh[0] = wqH + wo768; qk.bh[1] = wkH + wo768; qk.bh[2] = wvH + wo768;
        qk.bl[0] = wqL + wo768; qk.bl[1] = wkL + wo768; qk.bl[2] = wvL + wo768;
        qk.bias[0] = bq + l * DIM; qk.bias[1] = bk + l * DIM; qk.bias[2] = bv + l * DIM;
        qk.out[0] = q16; qk.out[1] = k16; qk.out[2] = v16;
        pdl_launch(hgemm<128,128,2,2,4>, dim3(18, 50), dim3(256), GS_2T_128,
                   (const __half*)xn, (const __half*)nullptr, (const __half*)nullptr,
                   (const float*)nullptr, (const float*)nullptr,
                   (float*)nullptr, (__half*)nullptr,
                   TOK, 2304, DIM, 4, qk);

        pdl_launch(attn_mma, dim3(BB * NH), dim3(256), AMEM,
                   (const __half*)q16, (const __half*)k16, (const __half*)v16, oo);

        pdl_launch(hgemm<128,64,2,2,4>, dim3(12, 50), dim3(256), GS_2T_64,
                   (const __half*)oo, (const __half*)(woH + wo768),
                   (const __half*)(woL + wo768), bo + l * DIM,
                   (const float*)x, x, (__half*)nullptr,
                   TOK, DIM, DIM, 1, dummy);

        pdl_launch(ln_kernel, dim3(TOK), dim3(192), 0,
                   (const float*)x, ln2_g + l * DIM, ln2_b + l * DIM, xn,
                   (long long)DIM, (long long)DIM);

        pdl_launch(hgemm<128,128,1,2,4>, dim3(24, 50), dim3(256), GS_1T_128,
                   (const __half*)xn, (const __half*)(w1H + woff),
                   (const __half*)nullptr, b1 + l * FF, (const float*)nullptr,
                   (float*)nullptr, hbuf, TOK, FF, DIM, 2, dummy);
        pdl_launch(hgemm<128,128,1,2,4>, dim3(6, 50), dim3(256), GS_1T_128,
                   (const __half*)hbuf, (const __half*)(w2H + woff),
                   (const __half*)nullptr, b2 + l * DIM, (const float*)x,
                   x, (__half*)nullptr, TOK, DIM, FF, 1, dummy);
    }

    pdl_launch(ln_kernel, dim3(BB), dim3(192), 0,
               (const float*)x, head_g, head_bn, cls16,
               (long long)(SEQ * DIM), (long long)DIM);
    pdl_launch(hgemm<128,128,2,2,4>, dim3(8, 1), dim3(256), GS_2T_128,
               (const __half*)cls16, (const __half*)whH, (const __half*)whL,
               head_bias, (const float*)nullptr, (float*)d_out, (__half*)nullptr,
               BB, NCLS, DIM, 0, dummy);
}

// round 16
// speedup vs baseline: 2.4534x; 1.1725x over previous
#include <cuda_runtime.h>
#include <cuda_fp16.h>
#include <cstdint>

#define BB 32
#define IMGSZ 224
#define PSZ 16
#define NSIDE 14
#define NPATCH 196
#define SEQ 197
#define DIM 768
#define NH 12
#define HD 64
#define FF 3072
#define NL 12
#define NCLS 1000
#define TOK (BB*SEQ)     // 6304
#define PTOK (BB*NPATCH) // 6272

// PDL: wait for upstream grids (no-op if launched without programmatic dep)
__device__ __forceinline__ void pdl_sync() {
#if defined(__CUDA_ARCH__) && (__CUDA_ARCH__ >= 900)
    cudaGridDependencySynchronize();
#endif
}

// ---------------- scratch (device globals: allocation-free) ----------------
__device__ float  g_x[TOK*DIM];
__device__ __half g_q[TOK*DIM];
__device__ __half g_k[TOK*DIM];
__device__ __half g_v[TOK*DIM];

__device__ __half g_xn[TOK*DIM];
__device__ __half g_o[TOK*DIM];
__device__ __half g_h[(size_t)TOK*FF];
__device__ __half g_p[(size_t)PTOK*DIM];
__device__ __half g_cls16[BB*DIM];

// transposed fp16 hi/lo weights: [N][K] layout per layer (lo only where used)
__device__ __half w_pat_h[589824],  w_pat_l[589824];
__device__ __half w_q_h[7077888];
__device__ __half w_k_h[7077888];
__device__ __half w_v_h[7077888];
__device__ __half w_o_h[7077888],   w_o_l[7077888];
__device__ __half w_1_h[28311552];
__device__ __half w_2_h[28311552];
__device__ __half w_hd_h[768000],   w_hd_l[768000];

struct QKV {
    const __half* bh[3];
    const __half* bl[3];
    const float*  bias[3];
    __half*       out[3];
};

// ---------------- weight transpose + hi[/lo] split ----------------
__global__ void wprep(const float* __restrict__ in, __half* __restrict__ oh,
                      __half* __restrict__ ol, int K, int ng) {
    __shared__ float t[32][33];
    int g = blockIdx.z;
    int e0 = blockIdx.x * 32, k0 = blockIdx.y * 32;
    int tx = threadIdx.x, ty = threadIdx.y;  // 32x8
    const float* gin = in + (size_t)g * K * ng;
    #pragma unroll
    for (int i = 0; i < 4; i++) {
        int kk = k0 + ty + i * 8;
        int e  = e0 + tx;
        float v = 0.f;
        if (e < ng) v = gin[(size_t)kk * ng + e];
        t[ty + i * 8][tx] = v;
    }
    __syncthreads();
    __half* goh = oh + (size_t)g * ng * K;
    __half* gol = (ol != nullptr) ? ol + (size_t)g * ng * K : nullptr;
    #pragma unroll
    for (int i = 0; i < 4; i++) {
        int e  = e0 + ty + i * 8;
        int kk = k0 + tx;
        if (e < ng) {
            float v = t[tx][ty + i * 8];
            __half hv = __float2half_rn(v);
            goh[(size_t)e * K + kk] = hv;
            if (gol != nullptr)
                gol[(size_t)e * K + kk] = __float2half_rn(v - __half2float(hv));
        }
    }
}

// ---------------- patch extraction (fp16) ----------------
__global__ void patch_extract(const float* __restrict__ img,
                              __half* __restrict__ oh) {
    int idx = blockIdx.x * 256 + threadIdx.x;
    if (idx >= PTOK * DIM) return;
    int kcol = idx % DIM;
    int row  = idx / DIM;
    int b  = row / NPATCH;
    int p  = row % NPATCH;
    int pr = p / NSIDE, pc = p % NSIDE;
    int c  = kcol % 3;
    int t  = kcol / 3;
    int py = t / PSZ, px = t % PSZ;
    float v = img[(((size_t)(b*IMGSZ + pr*PSZ + py) * IMGSZ) + pc*PSZ + px) * 3 + c];
    oh[idx] = __float2half_rn(v);
}

__global__ void cls_fill(const float* __restrict__ cls, float* __restrict__ x) {
    int i = blockIdx.x * 256 + threadIdx.x;
    if (i < BB * DIM) x[(size_t)(i / DIM) * SEQ * DIM + (i % DIM)] = cls[i % DIM];
}

// ---------------- LayerNorm (fp32 in, fp16 out), 192 thr x float4 -------------
__global__ void ln_kernel(const float* __restrict__ x, const float* __restrict__ g,
                          const float* __restrict__ bt,
                          __half* __restrict__ yh,
                          long long in_stride, long long out_stride) {
    int row = blockIdx.x;
    int tid = threadIdx.x;          // 0..191
    int wid = tid >> 5, lane = tid & 31;
    pdl_sync();
    const float* xr = x + (size_t)row * in_stride;
    float4 v = *reinterpret_cast<const float4*>(&xr[tid * 4]);

    __shared__ float red1[6];
    __shared__ float red2[6];

    float s = v.x + v.y + v.z + v.w;
    #pragma unroll
    for (int o = 16; o; o >>= 1) s += __shfl_xor_sync(0xffffffffu, s, o);
    if (lane == 0) red1[wid] = s;
    __syncthreads();
    if (tid == 0) {
        float t = red1[0];
        #pragma unroll
        for (int i = 1; i < 6; i++) t += red1[i];
        red1[0] = t;
    }
    __syncthreads();
    float mean = red1[0] * (1.0f / 768.0f);

    float dx = v.x - mean, dy = v.y - mean, dz = v.z - mean, dw = v.w - mean;
    float q = dx*dx + dy*dy + dz*dz + dw*dw;
    #pragma unroll
    for (int o = 16; o; o >>= 1) q += __shfl_xor_sync(0xffffffffu, q, o);
    if (lane == 0) red2[wid] = q;
    __syncthreads();
    if (tid == 0) {
        float t = red2[0];
        #pragma unroll
        for (int i = 1; i < 6; i++) t += red2[i];
        red2[0] = t;
    }
    __syncthreads();
    float var = red2[0] * (1.0f / 768.0f);
    float r = rsqrtf(var + 1e-5f);

    float4 gg = *reinterpret_cast<const float4*>(&g[tid * 4]);
    float4 bb = *reinterpret_cast<const float4*>(&bt[tid * 4]);
    __half2 h01 = __floats2half2_rn(dx * r * gg.x + bb.x, dy * r * gg.y + bb.y);
    __half2 h23 = __floats2half2_rn(dz * r * gg.z + bb.z, dw * r * gg.w + bb.w);
    uint2 packed;
    packed.x = *reinterpret_cast<uint32_t*>(&h01);
    packed.y = *reinterpret_cast<uint32_t*>(&h23);
    *reinterpret_cast<uint2*>(&yh[(size_t)row * out_stride + tid * 4]) = packed;
}

// ---------------- pipelined HMMA GEMM: TERMS-term (A fp16, B hi[/lo]) ----------
#define RS 40                   // padded row stride (halfs): 80B
#define NST 3

__device__ __forceinline__ void cpa16(uint32_t sa, const void* ga, uint32_t ss) {
    asm volatile("cp.async.cg.shared.global [%0], [%1], 16, %2;"
                 :: "r"(sa), "l"(ga), "r"(ss) : "memory");
}

template<int BM, int BN, int TERMS>
__device__ __forceinline__ void load_stage(
    uint32_t sbase, const __half* __restrict__ A,
    const __half* __restrict__ Bh, const __half* __restrict__ Bl,
    int m0, int M, int n0, int N, int K, int k0, int tid)
{
    constexpr int ACH = BM * 4;
    constexpr int BCH = BN * 4;
    constexpr int ATB = BM * RS * 2;
    constexpr int BTB = BN * RS * 2;
    constexpr int CH_TOT = ACH + TERMS * BCH;
    constexpr int PER_T = CH_TOT / 256;
    #pragma unroll
    for (int t = 0; t < PER_T; t++) {
        int ch = tid + t * 256;
        const __half* src; int r0, lim; uint32_t tb; int idx;
        if (ch < ACH)            { src = A;  r0 = m0; lim = M; tb = 0;         idx = ch; }
        else if (ch < ACH + BCH) { src = Bh; r0 = n0; lim = N; tb = ATB;       idx = ch - ACH; }
        else                     { src = Bl; r0 = n0; lim = N; tb = ATB + BTB; idx = ch - ACH - BCH; }
        int row = idx >> 2, c4 = idx & 3;
        int gr = r0 + row;
        uint32_t ss = 16u;
        if (gr >= lim) { gr = lim - 1; ss = 0u; }
        const void* ga = src + (size_t)gr * K + k0 + c4 * 8;
        uint32_t sa = sbase + tb + (uint32_t)(row * RS + c4 * 8) * 2;
        cpa16(sa, ga, ss);
    }
}

#define LDSM_X4(r0, r1, r2, r3, addr) \
    asm volatile("ldmatrix.sync.aligned.m8n8.x4.shared.b16 {%0,%1,%2,%3}, [%4];" \
                 : "=r"(r0), "=r"(r1), "=r"(r2), "=r"(r3) : "r"(addr))

#define LDSM_X2(r0, r1, addr) \
    asm volatile("ldmatrix.sync.aligned.m8n8.x2.shared.b16 {%0,%1}, [%2];" \
                 : "=r"(r0), "=r"(r1) : "r"(addr))

#define MMA16816(c, a, b) \
    asm volatile("mma.sync.aligned.m16n8k16.row.col.f32.f16.f16.f32 " \
                 "{%0,%1,%2,%3}, {%4,%5,%6,%7}, {%8,%9}, {%0,%1,%2,%3};" \
                 : "+f"((c)[0]), "+f"((c)[1]), "+f"((c)[2]), "+f"((c)[3]) \
                 : "r"((a)[0]), "r"((a)[1]), "r"((a)[2]), "r"((a)[3]), \
                   "r"((b)[0]), "r"((b)[1]))

// ep: 0=+bias fp32 | 1=+bias+residual | 2=gelu->fp16 | 3=patch embed | 4=fused QKV (fp16 out)
template<int BM, int BN, int TERMS, int WROWS, int WCOLS>
__global__ __launch_bounds__(256) void hgemm(
    const __half* __restrict__ A,
    const __half* __restrict__ Bh, const __half* __restrict__ Bl,
    const float* __restrict__ bias, const float* __restrict__ extra,
    float* __restrict__ Cf, __half* __restrict__ Choh,
    int M, int N, int K, int ep, QKV qkv)
{
    constexpr int WTILE_M = BM / WROWS;
    constexpr int WTM     = WTILE_M / 16;
    constexpr int WTILE_N = BN / WCOLS;
    constexpr int WTN     = WTILE_N / 8;
    constexpr int ATB  = BM * RS * 2;
    constexpr int BTB  = BN * RS * 2;
    constexpr int STGB = ATB + TERMS * BTB;

    extern __shared__ __align__(16) char dsm[];
    uint32_t sb = (uint32_t)__cvta_generic_to_shared(dsm);
    int tid = threadIdx.x, wid = tid >> 5, lane = tid & 31;
    int warp_m = wid / WCOLS, warp_n = wid % WCOLS;
    int m0 = blockIdx.y * BM;
    int n0 = blockIdx.x * BN;
    int Nl = N;
    int epe = ep;
    const __half* Bh_ = Bh; const __half* Bl_ = Bl;
    const float* bias_ = bias; float* Cf_ = Cf; __half* Ch_ = Choh;
    if (ep == 4) {
        int seg = n0 / 768;
        Bh_ = qkv.bh[seg]; Bl_ = qkv.bl[seg];
        bias_ = qkv.bias[seg]; Ch_ = qkv.out[seg];
        n0 -= seg * 768; Nl = 768; epe = 6;
    }
    int wrow = warp_m * WTILE_M, wcol = warp_n * WTILE_N;

    float acc[WTM][WTN][4];
    #pragma unroll
    for (int i = 0; i < WTM; i++)
        #pragma unroll
        for (int j = 0; j < WTN; j++)
            #pragma unroll
            for (int r = 0; r < 4; r++) acc[i][j][r] = 0.0f;

    int NC = K >> 5;

    pdl_sync();   // wait on producer before first global read

    #pragma unroll
    for (int s = 0; s < NST - 1; s++) {
        load_stage<BM,BN,TERMS>(sb + s * STGB, A, Bh_, Bl_, m0, M, n0, Nl, K, s * 32, tid);
        asm volatile("cp.async.commit_group;" ::: "memory");
    }

    int a_off = (wrow + (lane & 15)) * RS + ((lane >> 4) << 3);
    int b_off = (wcol + (lane & 7) + ((lane >> 4) & 1) * 8) * RS
              + ((lane >> 3) & 1) * 8;

    for (int c = 0; c < NC; c++) {
        asm volatile("cp.async.wait_group 1;" ::: "memory");
        __syncthreads();

        int pf = c + NST - 1;
        if (pf < NC) {
            load_stage<BM,BN,TERMS>(sb + (pf % NST) * STGB, A, Bh_, Bl_, m0, M, n0, Nl, K,
                                    pf * 32, tid);
        }
        asm volatile("cp.async.commit_group;" ::: "memory");

        uint32_t stg = sb + (c % NST) * STGB;
        uint32_t sA  = stg;
        uint32_t sBh = stg + ATB;
        uint32_t sBl = stg + ATB + BTB;

        #pragma unroll
        for (int ks = 0; ks < 2; ks++) {
            uint32_t a[WTM][4], bh[WTN][2], bl[WTN][2];
            #pragma unroll
            for (int mt = 0; mt < WTM; mt++) {
                uint32_t ad = sA + (uint32_t)(a_off + mt * 16 * RS + ks * 16) * 2;
                LDSM_X4(a[mt][0], a[mt][1], a[mt][2], a[mt][3], ad);
            }
            #pragma unroll
            for (int nb = 0; nb < WTN / 2; nb++) {
                uint32_t bd = sBh + (uint32_t)(b_off + nb * 16 * RS + ks * 16) * 2;
                LDSM_X4(bh[nb*2][0], bh[nb*2][1], bh[nb*2+1][0], bh[nb*2+1][1], bd);
                if (TERMS == 2) {
                    bd = sBl + (uint32_t)(b_off + nb * 16 * RS + ks * 16) * 2;
                    LDSM_X4(bl[nb*2][0], bl[nb*2][1], bl[nb*2+1][0], bl[nb*2+1][1], bd);
                }
            }
            #pragma unroll
            for (int mt = 0; mt < WTM; mt++)
                #pragma unroll
                for (int nt = 0; nt < WTN; nt++) MMA16816(acc[mt][nt], a[mt], bh[nt]);
            if (TERMS == 2) {
                #pragma unroll
                for (int mt = 0; mt < WTM; mt++)
                    #pragma unroll
                    for (int nt = 0; nt < WTN; nt++) MMA16816(acc[mt][nt], a[mt], bl[nt]);
            }
        }
    }

    // ---------------- epilogue ----------------
    int r  = lane >> 2;
    int c2 = (lane & 3) * 2;
    #pragma unroll
    for (int mt = 0; mt < WTM; mt++) {
        #pragma unroll
        for (int nt = 0; nt < WTN; nt++) {
            int n = n0 + wcol + nt * 8 + c2;
            if (n >= Nl) continue;
            float bn0 = bias_[n], bn1 = bias_[n + 1];
            #pragma unroll
            for (int hh = 0; hh < 2; hh++) {
                int m = m0 + wrow + mt * 16 + r + hh * 8;
                if (m >= M) continue;
                float v0 = acc[mt][nt][hh * 2 + 0] + bn0;
                float v1 = acc[mt][nt][hh * 2 + 1] + bn1;
                if (epe == 0) {
                    *reinterpret_cast<float2*>(&Cf_[(size_t)m * Nl + n]) =
                        make_float2(v0, v1);
                } else if (epe == 6) {
                    *reinterpret_cast<__half2*>(&Ch_[(size_t)m * Nl + n]) =
                        __halves2half2(__float2half_rn(v0), __float2half_rn(v1));
                } else if (epe == 1) {
                    float2 e = *reinterpret_cast<const float2*>(&extra[(size_t)m * Nl + n]);
                    *reinterpret_cast<float2*>(&Cf_[(size_t)m * Nl + n]) =
                        make_float2(v0 + e.x, v1 + e.y);
                } else if (epe == 2) {
                    v0 = 0.5f * v0 * (1.0f + erff(v0 * 0.70710678118654752f));
                    v1 = 0.5f * v1 * (1.0f + erff(v1 * 0.70710678118654752f));
                    *reinterpret_cast<__half2*>(&Ch_[(size_t)m * Nl + n]) =
                        __halves2half2(__float2half_rn(v0), __float2half_rn(v1));
                } else {
                    int bb = m / NPATCH, p = m % NPATCH;
                    float2 e = *reinterpret_cast<const float2*>(&extra[(size_t)p * DIM + n]);
                    *reinterpret_cast<float2*>(
                        &Cf_[((size_t)(bb * SEQ + p + 1)) * DIM + n]) =
                        make_float2(v0 + e.x, v1 + e.y);
                }
            }
        }
    }
}

// ---------------- tensor-core attention ----------------
#define SP 208
#define QK_RS 72     // Qs/Ks row stride (halfs), 144B
#define PT_RS 216    // P/VT row stride (halfs), 432B
#define S_RS 212     // S row stride (floats), 848B
#define MPASS 96
#define QS_OFF 0
#define KS_OFF 29952
#define VT_OFF 59904
#define S_OFF  87552
#define P_OFF  168960
#define AMEM   210432

__global__ __launch_bounds__(256) void attn_mma(
    const __half* __restrict__ q, const __half* __restrict__ k,
    const __half* __restrict__ v, __half* __restrict__ oh)
{
    extern __shared__ __align__(16) char dsm[];
    uint32_t sb = (uint32_t)__cvta_generic_to_shared(dsm);
    int bh = blockIdx.x, b = bh / NH, h = bh % NH;
    int tid = threadIdx.x, wid = tid >> 5, lane = tid & 31;

    const __half* qg = q + (size_t)b * SEQ * DIM + h * HD;
    const __half* kg = k + (size_t)b * SEQ * DIM + h * HD;
    const __half* vg = v + (size_t)b * SEQ * DIM + h * HD;

    pdl_sync();

    for (int ch = tid; ch < SP * 8; ch += 256) {
        int row = ch >> 3, c8 = (ch & 7) * 8;
        uint32_t qa = sb + QS_OFF + (uint32_t)(row * QK_RS + c8) * 2;
        uint32_t ka = sb + KS_OFF + (uint32_t)(row * QK_RS + c8) * 2;
        if (row < SEQ) {
            cpa16(qa, qg + (size_t)row * DIM + c8, 16);
            cpa16(ka, kg + (size_t)row * DIM + c8, 16);
        } else {
            asm volatile("st.shared.v4.b32 [%0], {%1,%1,%1,%1};"
                         :: "r"(qa), "r"(0) : "memory");
            asm volatile("st.shared.v4.b32 [%0], {%1,%1,%1,%1};"
                         :: "r"(ka), "r"(0) : "memory");
        }
    }
    asm volatile("cp.async.commit_group;" ::: "memory");
    for (int i = tid; i < SP * 32; i += 256) {
        int e2 = (i & 31) * 2, j = i >> 5;
        __half2 val = (j < SEQ)
            ? *reinterpret_cast<const __half2*>(&vg[(size_t)j * DIM + e2])
            : __halves2half2(__ushort_as_half(0), __ushort_as_half(0));
        uint16_t b0 = __half_as_ushort(__low2half(val));
        uint16_t b1 = __half_as_ushort(__high2half(val));
        asm volatile("st.shared.u16 [%0], %1;"
                     :: "r"(sb + VT_OFF + (uint32_t)(e2 * PT_RS + j) * 2), "h"(b0)
                     : "memory");
        asm volatile("st.shared.u16 [%0], %1;"
                     :: "r"(sb + VT_OFF + (uint32_t)((e2 + 1) * PT_RS + j) * 2), "h"(b1)
                     : "memory");
    }
    asm volatile("cp.async.wait_group 0;" ::: "memory");
    __syncthreads();

    int p0   = (wid < 5) ? 2 * wid : 10 + (wid - 5);
    int pcnt = (wid < 5) ? 2 : 1;
    int r4 = lane >> 2, c2 = (lane & 3) * 2;

    for (int m0 = 0; m0 < SEQ; m0 += MPASS) {
        int mt_cnt = (SEQ - m0 + 15) >> 4; if (mt_cnt > 6) mt_cnt = 6;

        float acc[6][4][4];
        #pragma unroll
        for (int i = 0; i < 6; i++)
            #pragma unroll
            for (int j = 0; j < 4; j++)
                #pragma unroll
                for (int r = 0; r < 4; r++) acc[i][j][r] = 0.f;
        #pragma unroll
        for (int ks = 0; ks < 4; ks++) {
            uint32_t a[6][4];
            for (int mt = 0; mt < mt_cnt; mt++) {
                uint32_t ad = sb + QS_OFF + (uint32_t)(
                    (m0 + mt * 16 + (lane & 15)) * QK_RS + ((lane >> 4) << 3) + ks * 16) * 2;
                LDSM_X4(a[mt][0], a[mt][1], a[mt][2], a[mt][3], ad);
            }
            for (int p = 0; p < pcnt; p++) {
                uint32_t b0[2], b1[2];
                uint32_t bd = sb + KS_OFF + (uint32_t)(
                    ((p0 + p) * 16 + (lane & 7) + ((lane >> 4) & 1) * 8) * QK_RS
                    + ((lane >> 3) & 1) * 8 + ks * 16) * 2;
                LDSM_X4(b0[0], b0[1], b1[0], b1[1], bd);
                for (int mt = 0; mt < mt_cnt; mt++) {
                    MMA16816(acc[mt][p * 2 + 0], a[mt], b0);
                    MMA16816(acc[mt][p * 2 + 1], a[mt], b1);
                }
            }
        }
        for (int mt = 0; mt < mt_cnt; mt++)
            for (int p = 0; p < pcnt; p++)
                #pragma unroll
                for (int t = 0; t < 2; t++) {
                    int col = (p0 + p) * 16 + t * 8 + c2;
                    #pragma unroll
                    for (int hh = 0; hh < 2; hh++) {
                        int row = mt * 16 + r4 + hh * 8;
                        *reinterpret_cast<float2*>(
                            dsm + S_OFF + ((size_t)row * S_RS + col) * 4) =
                            make_float2(acc[mt][p*2+t][hh*2], acc[mt][p*2+t][hh*2+1]);
                    }
                }
        __syncthreads();

        int rows = mt_cnt * 16;
        for (int r = wid; r < rows; r += 8) {
            const float* Srow = reinterpret_cast<const float*>(dsm + S_OFF + (size_t)r * S_RS * 4);
            float mx = -3.0e38f;
            for (int c = lane; c < SEQ; c += 32)
                mx = fmaxf(mx, Srow[c] * 0.125f);
            #pragma unroll
            for (int o = 16; o; o >>= 1) mx = fmaxf(mx, __shfl_xor_sync(0xffffffffu, mx, o));
            float pv[7];
            int cnt = 0;
            float sum = 0.f;
            for (int c = lane; c < SEQ; c += 32) {
                float p = __expf(Srow[c] * 0.125f - mx);
                pv[cnt++] = p; sum += p;
            }
            #pragma unroll
            for (int o = 16; o; o >>= 1) sum += __shfl_xor_sync(0xffffffffu, sum, o);
            float inv = 1.0f / sum;
            __half* Prow = reinterpret_cast<__half*>(dsm + P_OFF + (size_t)r * PT_RS * 2);
            cnt = 0;
            for (int c = lane; c < PT_RS; c += 32) {
                __half val;
                if (c < SEQ) { val = __float2half_rn(pv[cnt] * inv); cnt++; }
                else val = __ushort_as_half((uint16_t)0);
                Prow[c] = val;
            }
        }
        __syncthreads();

        float oacc[6][4];
        #pragma unroll
        for (int i = 0; i < 6; i++)
            #pragma unroll
            for (int r = 0; r < 4; r++) oacc[i][r] = 0.f;
        int l = lane & 15;
        for (int ks = 0; ks < 13; ks++) {
            uint32_t a[6][4];
            for (int mt = 0; mt < mt_cnt; mt++) {
                uint32_t ad = sb + P_OFF + (uint32_t)(
                    (mt * 16 + (lane & 15)) * PT_RS + ((lane >> 4) << 3) + ks * 16) * 2;
                LDSM_X4(a[mt][0], a[mt][1], a[mt][2], a[mt][3], ad);
            }
            uint32_t bfr[2];
            uint32_t bd = sb + VT_OFF + (uint32_t)(
                (wid * 8 + (l & 7)) * PT_RS + ((l >> 3) & 1) * 8 + ks * 16) * 2;
            LDSM_X2(bfr[0], bfr[1], bd);
            for (int mt = 0; mt < mt_cnt; mt++)
                MMA16816(oacc[mt], a[mt], bfr);
        }
        for (int mt = 0; mt < mt_cnt; mt++)
            #pragma unroll
            for (int hh = 0; hh < 2; hh++) {
                int gr = m0 + mt * 16 + r4 + hh * 8;
                if (gr >= SEQ) continue;
                *reinterpret_cast<__half2*>(
                    &oh[((size_t)(b * SEQ + gr)) * DIM + h * HD + wid * 8 + c2]) =
                    __halves2half2(__float2half_rn(oacc[mt][hh*2]),
                                   __float2half_rn(oacc[mt][hh*2+1]));
            }
        __syncthreads();
    }
}

// ---------------- host orchestration ----------------
#define GS_2T_128 (NST * (128*RS*2 + 2*128*RS*2))   // 92160
#define GS_2T_64  (NST * (128*RS*2 + 2*64*RS*2))    // 61440
#define GS_1T_128 (NST * (128*RS*2 + 128*RS*2))     // 61440

template<typename F, typename... Args>
static void pdl_launch(F func, dim3 grid, dim3 block, size_t smem, Args... args) {
    cudaLaunchConfig_t cfg = {};
    cfg.gridDim = grid;
    cfg.blockDim = block;
    cfg.dynamicSmemBytes = smem;
    cudaLaunchAttribute attr[1];
    attr[0].id = cudaLaunchAttributeProgrammaticStreamSerialization;
    attr[0].val.programmaticStreamSerializationAllowed = 1;
    cfg.attrs = attr;
    cfg.numAttrs = 1;
    cudaLaunchKernelEx(&cfg, func, args...);
}

extern "C" void kernel_launch(void* const* d_in, const int* in_sizes, int n_in,
                              void* d_out, int out_size) {
    const float* images    = (const float*)d_in[0];
    const float* patch_W   = (const float*)d_in[1];
    const float* patch_b   = (const float*)d_in[2];
    const float* pos_emb   = (const float*)d_in[3];
    const float* cls       = (const float*)d_in[4];
    const float* ln1_g     = (const float*)d_in[5];
    const float* ln1_b     = (const float*)d_in[6];
    const float* Wq        = (const float*)d_in[7];
    const float* bq        = (const float*)d_in[8];
    const float* Wk        = (const float*)d_in[9];
    const float* bk        = (const float*)d_in[10];
    const float* Wv        = (const float*)d_in[11];
    const float* bv        = (const float*)d_in[12];
    const float* Wo        = (const float*)d_in[13];
    const float* bo        = (const float*)d_in[14];
    const float* ln2_g     = (const float*)d_in[15];
    const float* ln2_b     = (const float*)d_in[16];
    const float* W1        = (const float*)d_in[17];
    const float* b1        = (const float*)d_in[18];
    const float* W2        = (const float*)d_in[19];
    const float* b2        = (const float*)d_in[20];
    const float* head_g    = (const float*)d_in[21];
    const float* head_bn   = (const float*)d_in[22];
    const float* head_W    = (const float*)d_in[23];
    const float* head_bias = (const float*)d_in[24];

    float *x;
    __half *q16, *k16, *v16;
    __half *xn, *oo, *hbuf, *pbuf, *cls16;
    __half *wpH, *wpL, *wqH, *wkH, *wvH, *woH, *woL;
    __half *w1H, *w2H, *whH, *whL;
    cudaGetSymbolAddress((void**)&x,     g_x);
    cudaGetSymbolAddress((void**)&q16,   g_q);
    cudaGetSymbolAddress((void**)&k16,   g_k);
    cudaGetSymbolAddress((void**)&v16,   g_v);
    cudaGetSymbolAddress((void**)&xn,    g_xn);
    cudaGetSymbolAddress((void**)&oo,    g_o);
    cudaGetSymbolAddress((void**)&hbuf,  g_h);
    cudaGetSymbolAddress((void**)&pbuf,  g_p);
    cudaGetSymbolAddress((void**)&cls16, g_cls16);
    cudaGetSymbolAddress((void**)&wpH, w_pat_h);cudaGetSymbolAddress((void**)&wpL, w_pat_l);
    cudaGetSymbolAddress((void**)&wqH, w_q_h);
    cudaGetSymbolAddress((void**)&wkH, w_k_h);
    cudaGetSymbolAddress((void**)&wvH, w_v_h);
    cudaGetSymbolAddress((void**)&woH, w_o_h);  cudaGetSymbolAddress((void**)&woL, w_o_l);
    cudaGetSymbolAddress((void**)&w1H, w_1_h);
    cudaGetSymbolAddress((void**)&w2H, w_2_h);
    cudaGetSymbolAddress((void**)&whH, w_hd_h); cudaGetSymbolAddress((void**)&whL, w_hd_l);

    cudaFuncSetAttribute(hgemm<128,128,2,2,4>, cudaFuncAttributeMaxDynamicSharedMemorySize, GS_2T_128);
    cudaFuncSetAttribute(hgemm<128,64,2,2,4>,  cudaFuncAttributeMaxDynamicSharedMemorySize, GS_2T_64);
    cudaFuncSetAttribute(hgemm<128,128,1,2,4>, cudaFuncAttributeMaxDynamicSharedMemorySize, GS_1T_128);
    cudaFuncSetAttribute(attn_mma, cudaFuncAttributeMaxDynamicSharedMemorySize, AMEM);

    QKV dummy = {};

    dim3 tblk(32, 8);
    wprep<<<dim3(24, 24, 1),   tblk>>>(patch_W, wpH, wpL, DIM, DIM);
    wprep<<<dim3(2, 24, 144),  tblk>>>(Wq, wqH, nullptr, DIM, HD);
    wprep<<<dim3(2, 24, 144),  tblk>>>(Wk, wkH, nullptr, DIM, HD);
    wprep<<<dim3(2, 24, 144),  tblk>>>(Wv, wvH, nullptr, DIM, HD);
    wprep<<<dim3(24, 24, 12),  tblk>>>(Wo, woH, woL, DIM, DIM);
    wprep<<<dim3(96, 24, 12),  tblk>>>(W1, w1H, nullptr, DIM, FF);
    wprep<<<dim3(24, 96, 12),  tblk>>>(W2, w2H, nullptr, FF, DIM);
    wprep<<<dim3(32, 24, 1),   tblk>>>(head_W, whH, whL, DIM, NCLS);

    patch_extract<<<(PTOK * DIM + 255) / 256, 256>>>(images, pbuf);
    pdl_launch(hgemm<128,128,2,2,4>, dim3(6, 49), dim3(256), GS_2T_128,
               (const __half*)pbuf, (const __half*)wpH, (const __half*)wpL,
               patch_b, pos_emb, x, (__half*)nullptr,
               PTOK, DIM, DIM, 3, dummy);
    cls_fill<<<(BB * DIM + 255) / 256, 256>>>(cls, x);

    for (int l = 0; l < NL; l++) {
        size_t wo768 = (size_t)l * DIM * DIM;
        size_t woff  = (size_t)l * DIM * FF;

        pdl_launch(ln_kernel, dim3(TOK), dim3(192), 0,
                   (const float*)x, ln1_g + l * DIM, ln1_b + l * DIM, xn,
                   (long long)DIM, (long long)DIM);

        QKV qk;
        qk.bh[0] = wqH + wo768; qk.bh[1] = wkH + wo768; qk.bh[2] = wvH + wo768;
        qk.bl[0] = nullptr; qk.bl[1] = nullptr; qk.bl[2] = nullptr;
        qk.bias[0] = bq + l * DIM; qk.bias[1] = bk + l * DIM; qk.bias[2] = bv + l * DIM;
        qk.out[0] = q16; qk.out[1] = k16; qk.out[2] = v16;
        pdl_launch(hgemm<128,128,1,2,4>, dim3(18, 50), dim3(256), GS_1T_128,
                   (const __half*)xn, (const __half*)nullptr, (const __half*)nullptr,
                   (const float*)nullptr, (const float*)nullptr,
                   (float*)nullptr, (__half*)nullptr,
                   TOK, 2304, DIM, 4, qk);

        pdl_launch(attn_mma, dim3(BB * NH), dim3(256), AMEM,
                   (const __half*)q16, (const __half*)k16, (const __half*)v16, oo);

        pdl_launch(hgemm<128,64,2,2,4>, dim3(12, 50), dim3(256), GS_2T_64,
                   (const __half*)oo, (const __half*)(woH + wo768),
                   (const __half*)(woL + wo768), bo + l * DIM,
                   (const float*)x, x, (__half*)nullptr,
                   TOK, DIM, DIM, 1, dummy);

        pdl_launch(ln_kernel, dim3(TOK), dim3(192), 0,
                   (const float*)x, ln2_g + l * DIM, ln2_b + l * DIM, xn,
                   (long long)DIM, (long long)DIM);

        pdl_launch(hgemm<128,128,1,2,4>, dim3(24, 50), dim3(256), GS_1T_128,
                   (const __half*)xn, (const __half*)(w1H + woff),
                   (const __half*)nullptr, b1 + l * FF, (const float*)nullptr,
                   (float*)nullptr, hbuf, TOK, FF, DIM, 2, dummy);
        pdl_launch(hgemm<128,128,1,2,4>, dim3(6, 50), dim3(256), GS_1T_128,
                   (const __half*)hbuf, (const __half*)(w2H + woff),
                   (const __half*)nullptr, b2 + l * DIM, (const float*)x,
                   x, (__half*)nullptr, TOK, DIM, FF, 1, dummy);
    }

    pdl_launch(ln_kernel, dim3(BB), dim3(192), 0,
               (const float*)x, head_g, head_bn, cls16,
               (long long)(SEQ * DIM), (long long)DIM);
    pdl_launch(hgemm<128,128,2,2,4>, dim3(8, 1), dim3(256), GS_2T_128,
               (const __half*)cls16, (const __half*)whH, (const __half*)whL,
               head_bias, (const float*)nullptr, (float*)d_out, (__half*)nullptr,
               BB, NCLS, DIM, 0, dummy);
}

// round 17
// speedup vs baseline: 2.5724x; 1.0485x over previous
#include <cuda_runtime.h>
#include <cuda_fp16.h>
#include <cstdint>

#define BB 32
#define IMGSZ 224
#define PSZ 16
#define NSIDE 14
#define NPATCH 196
#define SEQ 197
#define DIM 768
#define NH 12
#define HD 64
#define FF 3072
#define NL 12
#define NCLS 1000
#define TOK (BB*SEQ)     // 6304
#define PTOK (BB*NPATCH) // 6272

// PDL: wait for upstream grids (no-op if launched without programmatic dep)
__device__ __forceinline__ void pdl_sync() {
#if defined(__CUDA_ARCH__) && (__CUDA_ARCH__ >= 900)
    cudaGridDependencySynchronize();
#endif
}

// ---------------- scratch (device globals: allocation-free) ----------------
__device__ float  g_x[TOK*DIM];
__device__ __half g_q[TOK*DIM];
__device__ __half g_k[TOK*DIM];
__device__ __half g_v[TOK*DIM];

__device__ __half g_xn[TOK*DIM];
__device__ __half g_o[TOK*DIM];
__device__ __half g_h[(size_t)TOK*FF];
__device__ __half g_p[(size_t)PTOK*DIM];
__device__ __half g_cls16[BB*DIM];

// transposed fp16 hi/lo weights: [N][K] layout per layer (lo only where used)
__device__ __half w_pat_h[589824],  w_pat_l[589824];
__device__ __half w_q_h[7077888];
__device__ __half w_k_h[7077888];
__device__ __half w_v_h[7077888];
__device__ __half w_o_h[7077888];
__device__ __half w_1_h[28311552];
__device__ __half w_2_h[28311552];
__device__ __half w_hd_h[768000],   w_hd_l[768000];

struct QKV {
    const __half* bh[3];
    const __half* bl[3];
    const float*  bias[3];
    __half*       out[3];
};

// ---------------- weight transpose + hi[/lo] split ----------------
__global__ void wprep(const float* __restrict__ in, __half* __restrict__ oh,
                      __half* __restrict__ ol, int K, int ng) {
    __shared__ float t[32][33];
    int g = blockIdx.z;
    int e0 = blockIdx.x * 32, k0 = blockIdx.y * 32;
    int tx = threadIdx.x, ty = threadIdx.y;  // 32x8
    const float* gin = in + (size_t)g * K * ng;
    #pragma unroll
    for (int i = 0; i < 4; i++) {
        int kk = k0 + ty + i * 8;
        int e  = e0 + tx;
        float v = 0.f;
        if (e < ng) v = gin[(size_t)kk * ng + e];
        t[ty + i * 8][tx] = v;
    }
    __syncthreads();
    __half* goh = oh + (size_t)g * ng * K;
    __half* gol = (ol != nullptr) ? ol + (size_t)g * ng * K : nullptr;
    #pragma unroll
    for (int i = 0; i < 4; i++) {
        int e  = e0 + ty + i * 8;
        int kk = k0 + tx;
        if (e < ng) {
            float v = t[tx][ty + i * 8];
            __half hv = __float2half_rn(v);
            goh[(size_t)e * K + kk] = hv;
            if (gol != nullptr)
                gol[(size_t)e * K + kk] = __float2half_rn(v - __half2float(hv));
        }
    }
}

// ---------------- patch extraction (fp16) ----------------
__global__ void patch_extract(const float* __restrict__ img,
                              __half* __restrict__ oh) {
    int idx = blockIdx.x * 256 + threadIdx.x;
    if (idx >= PTOK * DIM) return;
    int kcol = idx % DIM;
    int row  = idx / DIM;
    int b  = row / NPATCH;
    int p  = row % NPATCH;
    int pr = p / NSIDE, pc = p % NSIDE;
    int c  = kcol % 3;
    int t  = kcol / 3;
    int py = t / PSZ, px = t % PSZ;
    float v = img[(((size_t)(b*IMGSZ + pr*PSZ + py) * IMGSZ) + pc*PSZ + px) * 3 + c];
    oh[idx] = __float2half_rn(v);
}

__global__ void cls_fill(const float* __restrict__ cls, float* __restrict__ x) {
    int i = blockIdx.x * 256 + threadIdx.x;
    if (i < BB * DIM) x[(size_t)(i / DIM) * SEQ * DIM + (i % DIM)] = cls[i % DIM];
}

// ---------------- LayerNorm (fp32 in, fp16 out), 192 thr x float4 -------------
__global__ void ln_kernel(const float* __restrict__ x, const float* __restrict__ g,
                          const float* __restrict__ bt,
                          __half* __restrict__ yh,
                          long long in_stride, long long out_stride) {
    int row = blockIdx.x;
    int tid = threadIdx.x;          // 0..191
    int wid = tid >> 5, lane = tid & 31;
    pdl_sync();
    const float* xr = x + (size_t)row * in_stride;
    float4 v = *reinterpret_cast<const float4*>(&xr[tid * 4]);

    __shared__ float red1[6];
    __shared__ float red2[6];

    float s = v.x + v.y + v.z + v.w;
    #pragma unroll
    for (int o = 16; o; o >>= 1) s += __shfl_xor_sync(0xffffffffu, s, o);
    if (lane == 0) red1[wid] = s;
    __syncthreads();
    if (tid == 0) {
        float t = red1[0];
        #pragma unroll
        for (int i = 1; i < 6; i++) t += red1[i];
        red1[0] = t;
    }
    __syncthreads();
    float mean = red1[0] * (1.0f / 768.0f);

    float dx = v.x - mean, dy = v.y - mean, dz = v.z - mean, dw = v.w - mean;
    float q = dx*dx + dy*dy + dz*dz + dw*dw;
    #pragma unroll
    for (int o = 16; o; o >>= 1) q += __shfl_xor_sync(0xffffffffu, q, o);
    if (lane == 0) red2[wid] = q;
    __syncthreads();
    if (tid == 0) {
        float t = red2[0];
        #pragma unroll
        for (int i = 1; i < 6; i++) t += red2[i];
        red2[0] = t;
    }
    __syncthreads();
    float var = red2[0] * (1.0f / 768.0f);
    float r = rsqrtf(var + 1e-5f);

    float4 gg = *reinterpret_cast<const float4*>(&g[tid * 4]);
    float4 bb = *reinterpret_cast<const float4*>(&bt[tid * 4]);
    __half2 h01 = __floats2half2_rn(dx * r * gg.x + bb.x, dy * r * gg.y + bb.y);
    __half2 h23 = __floats2half2_rn(dz * r * gg.z + bb.z, dw * r * gg.w + bb.w);
    uint2 packed;
    packed.x = *reinterpret_cast<uint32_t*>(&h01);
    packed.y = *reinterpret_cast<uint32_t*>(&h23);
    *reinterpret_cast<uint2*>(&yh[(size_t)row * out_stride + tid * 4]) = packed;
}

// ---------------- pipelined HMMA GEMM: TERMS-term (A fp16, B hi[/lo]) ----------
#define RS 40                   // padded row stride (halfs): 80B
#define NST 3

__device__ __forceinline__ void cpa16(uint32_t sa, const void* ga, uint32_t ss) {
    asm volatile("cp.async.cg.shared.global [%0], [%1], 16, %2;"
                 :: "r"(sa), "l"(ga), "r"(ss) : "memory");
}

template<int BM, int BN, int TERMS>
__device__ __forceinline__ void load_stage(
    uint32_t sbase, const __half* __restrict__ A,
    const __half* __restrict__ Bh, const __half* __restrict__ Bl,
    int m0, int M, int n0, int N, int K, int k0, int tid)
{
    constexpr int ACH = BM * 4;
    constexpr int BCH = BN * 4;
    constexpr int ATB = BM * RS * 2;
    constexpr int BTB = BN * RS * 2;
    constexpr int CH_TOT = ACH + TERMS * BCH;
    constexpr int PER_T = CH_TOT / 256;
    #pragma unroll
    for (int t = 0; t < PER_T; t++) {
        int ch = tid + t * 256;
        const __half* src; int r0, lim; uint32_t tb; int idx;
        if (ch < ACH)            { src = A;  r0 = m0; lim = M; tb = 0;         idx = ch; }
        else if (ch < ACH + BCH) { src = Bh; r0 = n0; lim = N; tb = ATB;       idx = ch - ACH; }
        else                     { src = Bl; r0 = n0; lim = N; tb = ATB + BTB; idx = ch - ACH - BCH; }
        int row = idx >> 2, c4 = idx & 3;
        int gr = r0 + row;
        uint32_t ss = 16u;
        if (gr >= lim) { gr = lim - 1; ss = 0u; }
        const void* ga = src + (size_t)gr * K + k0 + c4 * 8;
        uint32_t sa = sbase + tb + (uint32_t)(row * RS + c4 * 8) * 2;
        cpa16(sa, ga, ss);
    }
}

#define LDSM_X4(r0, r1, r2, r3, addr) \
    asm volatile("ldmatrix.sync.aligned.m8n8.x4.shared.b16 {%0,%1,%2,%3}, [%4];" \
                 : "=r"(r0), "=r"(r1), "=r"(r2), "=r"(r3) : "r"(addr))

#define LDSM_X2(r0, r1, addr) \
    asm volatile("ldmatrix.sync.aligned.m8n8.x2.shared.b16 {%0,%1}, [%2];" \
                 : "=r"(r0), "=r"(r1) : "r"(addr))

#define MMA16816(c, a, b) \
    asm volatile("mma.sync.aligned.m16n8k16.row.col.f32.f16.f16.f32 " \
                 "{%0,%1,%2,%3}, {%4,%5,%6,%7}, {%8,%9}, {%0,%1,%2,%3};" \
                 : "+f"((c)[0]), "+f"((c)[1]), "+f"((c)[2]), "+f"((c)[3]) \
                 : "r"((a)[0]), "r"((a)[1]), "r"((a)[2]), "r"((a)[3]), \
                   "r"((b)[0]), "r"((b)[1]))

// ep: 0=+bias fp32 | 1=+bias+residual | 2=gelu->fp16 | 3=patch embed | 4=fused QKV (fp16 out)
template<int BM, int BN, int TERMS, int WROWS, int WCOLS>
__global__ __launch_bounds__(256) void hgemm(
    const __half* __restrict__ A,
    const __half* __restrict__ Bh, const __half* __restrict__ Bl,
    const float* __restrict__ bias, const float* __restrict__ extra,
    float* __restrict__ Cf, __half* __restrict__ Choh,
    int M, int N, int K, int ep, QKV qkv)
{
    constexpr int WTILE_M = BM / WROWS;
    constexpr int WTM     = WTILE_M / 16;
    constexpr int WTILE_N = BN / WCOLS;
    constexpr int WTN     = WTILE_N / 8;
    constexpr int ATB  = BM * RS * 2;
    constexpr int BTB  = BN * RS * 2;
    constexpr int STGB = ATB + TERMS * BTB;

    extern __shared__ __align__(16) char dsm[];
    uint32_t sb = (uint32_t)__cvta_generic_to_shared(dsm);
    int tid = threadIdx.x, wid = tid >> 5, lane = tid & 31;
    int warp_m = wid / WCOLS, warp_n = wid % WCOLS;
    int m0 = blockIdx.y * BM;
    int n0 = blockIdx.x * BN;
    int Nl = N;
    int epe = ep;
    const __half* Bh_ = Bh; const __half* Bl_ = Bl;
    const float* bias_ = bias; float* Cf_ = Cf; __half* Ch_ = Choh;
    if (ep == 4) {
        int seg = n0 / 768;
        Bh_ = qkv.bh[seg]; Bl_ = qkv.bl[seg];
        bias_ = qkv.bias[seg]; Ch_ = qkv.out[seg];
        n0 -= seg * 768; Nl = 768; epe = 6;
    }
    int wrow = warp_m * WTILE_M, wcol = warp_n * WTILE_N;

    float acc[WTM][WTN][4];
    #pragma unroll
    for (int i = 0; i < WTM; i++)
        #pragma unroll
        for (int j = 0; j < WTN; j++)
            #pragma unroll
            for (int r = 0; r < 4; r++) acc[i][j][r] = 0.0f;

    int NC = K >> 5;

    pdl_sync();   // wait on producer before first global read

    #pragma unroll
    for (int s = 0; s < NST - 1; s++) {
        load_stage<BM,BN,TERMS>(sb + s * STGB, A, Bh_, Bl_, m0, M, n0, Nl, K, s * 32, tid);
        asm volatile("cp.async.commit_group;" ::: "memory");
    }

    int a_off = (wrow + (lane & 15)) * RS + ((lane >> 4) << 3);
    int b_off = (wcol + (lane & 7) + ((lane >> 4) & 1) * 8) * RS
              + ((lane >> 3) & 1) * 8;

    for (int c = 0; c < NC; c++) {
        asm volatile("cp.async.wait_group 1;" ::: "memory");
        __syncthreads();

        int pf = c + NST - 1;
        if (pf < NC) {
            load_stage<BM,BN,TERMS>(sb + (pf % NST) * STGB, A, Bh_, Bl_, m0, M, n0, Nl, K,
                                    pf * 32, tid);
        }
        asm volatile("cp.async.commit_group;" ::: "memory");

        uint32_t stg = sb + (c % NST) * STGB;
        uint32_t sA  = stg;
        uint32_t sBh = stg + ATB;
        uint32_t sBl = stg + ATB + BTB;

        #pragma unroll
        for (int ks = 0; ks < 2; ks++) {
            uint32_t a[WTM][4], bh[WTN][2], bl[WTN][2];
            #pragma unroll
            for (int mt = 0; mt < WTM; mt++) {
                uint32_t ad = sA + (uint32_t)(a_off + mt * 16 * RS + ks * 16) * 2;
                LDSM_X4(a[mt][0], a[mt][1], a[mt][2], a[mt][3], ad);
            }
            #pragma unroll
            for (int nb = 0; nb < WTN / 2; nb++) {
                uint32_t bd = sBh + (uint32_t)(b_off + nb * 16 * RS + ks * 16) * 2;
                LDSM_X4(bh[nb*2][0], bh[nb*2][1], bh[nb*2+1][0], bh[nb*2+1][1], bd);
                if (TERMS == 2) {
                    bd = sBl + (uint32_t)(b_off + nb * 16 * RS + ks * 16) * 2;
                    LDSM_X4(bl[nb*2][0], bl[nb*2][1], bl[nb*2+1][0], bl[nb*2+1][1], bd);
                }
            }
            #pragma unroll
            for (int mt = 0; mt < WTM; mt++)
                #pragma unroll
                for (int nt = 0; nt < WTN; nt++) MMA16816(acc[mt][nt], a[mt], bh[nt]);
            if (TERMS == 2) {
                #pragma unroll
                for (int mt = 0; mt < WTM; mt++)
                    #pragma unroll
                    for (int nt = 0; nt < WTN; nt++) MMA16816(acc[mt][nt], a[mt], bl[nt]);
            }
        }
    }

    // ---------------- epilogue ----------------
    int r  = lane >> 2;
    int c2 = (lane & 3) * 2;
    #pragma unroll
    for (int mt = 0; mt < WTM; mt++) {
        #pragma unroll
        for (int nt = 0; nt < WTN; nt++) {
            int n = n0 + wcol + nt * 8 + c2;
            if (n >= Nl) continue;
            float bn0 = bias_[n], bn1 = bias_[n + 1];
            #pragma unroll
            for (int hh = 0; hh < 2; hh++) {
                int m = m0 + wrow + mt * 16 + r + hh * 8;
                if (m >= M) continue;
                float v0 = acc[mt][nt][hh * 2 + 0] + bn0;
                float v1 = acc[mt][nt][hh * 2 + 1] + bn1;
                if (epe == 0) {
                    *reinterpret_cast<float2*>(&Cf_[(size_t)m * Nl + n]) =
                        make_float2(v0, v1);
                } else if (epe == 6) {
                    *reinterpret_cast<__half2*>(&Ch_[(size_t)m * Nl + n]) =
                        __halves2half2(__float2half_rn(v0), __float2half_rn(v1));
                } else if (epe == 1) {
                    float2 e = *reinterpret_cast<const float2*>(&extra[(size_t)m * Nl + n]);
                    *reinterpret_cast<float2*>(&Cf_[(size_t)m * Nl + n]) =
                        make_float2(v0 + e.x, v1 + e.y);
                } else if (epe == 2) {
                    v0 = 0.5f * v0 * (1.0f + erff(v0 * 0.70710678118654752f));
                    v1 = 0.5f * v1 * (1.0f + erff(v1 * 0.70710678118654752f));
                    *reinterpret_cast<__half2*>(&Ch_[(size_t)m * Nl + n]) =
                        __halves2half2(__float2half_rn(v0), __float2half_rn(v1));
                } else {
                    int bb = m / NPATCH, p = m % NPATCH;
                    float2 e = *reinterpret_cast<const float2*>(&extra[(size_t)p * DIM + n]);
                    *reinterpret_cast<float2*>(
                        &Cf_[((size_t)(bb * SEQ + p + 1)) * DIM + n]) =
                        make_float2(v0 + e.x, v1 + e.y);
                }
            }
        }
    }
}

// ---------------- tensor-core attention ----------------
#define SP 208
#define QK_RS 72     // Qs/Ks row stride (halfs), 144B
#define PT_RS 216    // P/VT row stride (halfs), 432B
#define S_RS 212     // S row stride (floats), 848B
#define MPASS 96
#define QS_OFF 0
#define KS_OFF 29952
#define VT_OFF 59904
#define S_OFF  87552
#define P_OFF  168960
#define AMEM   210432

__global__ __launch_bounds__(256) void attn_mma(
    const __half* __restrict__ q, const __half* __restrict__ k,
    const __half* __restrict__ v, __half* __restrict__ oh)
{
    extern __shared__ __align__(16) char dsm[];
    uint32_t sb = (uint32_t)__cvta_generic_to_shared(dsm);
    int bh = blockIdx.x, b = bh / NH, h = bh % NH;
    int tid = threadIdx.x, wid = tid >> 5, lane = tid & 31;

    const __half* qg = q + (size_t)b * SEQ * DIM + h * HD;
    const __half* kg = k + (size_t)b * SEQ * DIM + h * HD;
    const __half* vg = v + (size_t)b * SEQ * DIM + h * HD;

    pdl_sync();

    for (int ch = tid; ch < SP * 8; ch += 256) {
        int row = ch >> 3, c8 = (ch & 7) * 8;
        uint32_t qa = sb + QS_OFF + (uint32_t)(row * QK_RS + c8) * 2;
        uint32_t ka = sb + KS_OFF + (uint32_t)(row * QK_RS + c8) * 2;
        if (row < SEQ) {
            cpa16(qa, qg + (size_t)row * DIM + c8, 16);
            cpa16(ka, kg + (size_t)row * DIM + c8, 16);
        } else {
            asm volatile("st.shared.v4.b32 [%0], {%1,%1,%1,%1};"
                         :: "r"(qa), "r"(0) : "memory");
            asm volatile("st.shared.v4.b32 [%0], {%1,%1,%1,%1};"
                         :: "r"(ka), "r"(0) : "memory");
        }
    }
    asm volatile("cp.async.commit_group;" ::: "memory");
    for (int i = tid; i < SP * 32; i += 256) {
        int e2 = (i & 31) * 2, j = i >> 5;
        __half2 val = (j < SEQ)
            ? *reinterpret_cast<const __half2*>(&vg[(size_t)j * DIM + e2])
            : __halves2half2(__ushort_as_half(0), __ushort_as_half(0));
        uint16_t b0 = __half_as_ushort(__low2half(val));
        uint16_t b1 = __half_as_ushort(__high2half(val));
        asm volatile("st.shared.u16 [%0], %1;"
                     :: "r"(sb + VT_OFF + (uint32_t)(e2 * PT_RS + j) * 2), "h"(b0)
                     : "memory");
        asm volatile("st.shared.u16 [%0], %1;"
                     :: "r"(sb + VT_OFF + (uint32_t)((e2 + 1) * PT_RS + j) * 2), "h"(b1)
                     : "memory");
    }
    asm volatile("cp.async.wait_group 0;" ::: "memory");
    __syncthreads();

    int p0   = (wid < 5) ? 2 * wid : 10 + (wid - 5);
    int pcnt = (wid < 5) ? 2 : 1;
    int r4 = lane >> 2, c2 = (lane & 3) * 2;

    for (int m0 = 0; m0 < SEQ; m0 += MPASS) {
        int mt_cnt = (SEQ - m0 + 15) >> 4; if (mt_cnt > 6) mt_cnt = 6;

        float acc[6][4][4];
        #pragma unroll
        for (int i = 0; i < 6; i++)
            #pragma unroll
            for (int j = 0; j < 4; j++)
                #pragma unroll
                for (int r = 0; r < 4; r++) acc[i][j][r] = 0.f;
        #pragma unroll
        for (int ks = 0; ks < 4; ks++) {
            uint32_t a[6][4];
            for (int mt = 0; mt < mt_cnt; mt++) {
                uint32_t ad = sb + QS_OFF + (uint32_t)(
                    (m0 + mt * 16 + (lane & 15)) * QK_RS + ((lane >> 4) << 3) + ks * 16) * 2;
                LDSM_X4(a[mt][0], a[mt][1], a[mt][2], a[mt][3], ad);
            }
            for (int p = 0; p < pcnt; p++) {
                uint32_t b0[2], b1[2];
                uint32_t bd = sb + KS_OFF + (uint32_t)(
                    ((p0 + p) * 16 + (lane & 7) + ((lane >> 4) & 1) * 8) * QK_RS
                    + ((lane >> 3) & 1) * 8 + ks * 16) * 2;
                LDSM_X4(b0[0], b0[1], b1[0], b1[1], bd);
                for (int mt = 0; mt < mt_cnt; mt++) {
                    MMA16816(acc[mt][p * 2 + 0], a[mt], b0);
                    MMA16816(acc[mt][p * 2 + 1], a[mt], b1);
                }
            }
        }
        for (int mt = 0; mt < mt_cnt; mt++)
            for (int p = 0; p < pcnt; p++)
                #pragma unroll
                for (int t = 0; t < 2; t++) {
                    int col = (p0 + p) * 16 + t * 8 + c2;
                    #pragma unroll
                    for (int hh = 0; hh < 2; hh++) {
                        int row = mt * 16 + r4 + hh * 8;
                        *reinterpret_cast<float2*>(
                            dsm + S_OFF + ((size_t)row * S_RS + col) * 4) =
                            make_float2(acc[mt][p*2+t][hh*2], acc[mt][p*2+t][hh*2+1]);
                    }
                }
        __syncthreads();

        int rows = mt_cnt * 16;
        for (int r = wid; r < rows; r += 8) {
            const float* Srow = reinterpret_cast<const float*>(dsm + S_OFF + (size_t)r * S_RS * 4);
            float mx = -3.0e38f;
            for (int c = lane; c < SEQ; c += 32)
                mx = fmaxf(mx, Srow[c] * 0.125f);
            #pragma unroll
            for (int o = 16; o; o >>= 1) mx = fmaxf(mx, __shfl_xor_sync(0xffffffffu, mx, o));
            float pv[7];
            int cnt = 0;
            float sum = 0.f;
            for (int c = lane; c < SEQ; c += 32) {
                float p = __expf(Srow[c] * 0.125f - mx);
                pv[cnt++] = p; sum += p;
            }
            #pragma unroll
            for (int o = 16; o; o >>= 1) sum += __shfl_xor_sync(0xffffffffu, sum, o);
            float inv = 1.0f / sum;
            __half* Prow = reinterpret_cast<__half*>(dsm + P_OFF + (size_t)r * PT_RS * 2);
            cnt = 0;
            for (int c = lane; c < PT_RS; c += 32) {
                __half val;
                if (c < SEQ) { val = __float2half_rn(pv[cnt] * inv); cnt++; }
                else val = __ushort_as_half((uint16_t)0);
                Prow[c] = val;
            }
        }
        __syncthreads();

        float oacc[6][4];
        #pragma unroll
        for (int i = 0; i < 6; i++)
            #pragma unroll
            for (int r = 0; r < 4; r++) oacc[i][r] = 0.f;
        int l = lane & 15;
        for (int ks = 0; ks < 13; ks++) {
            uint32_t a[6][4];
            for (int mt = 0; mt < mt_cnt; mt++) {
                uint32_t ad = sb + P_OFF + (uint32_t)(
                    (mt * 16 + (lane & 15)) * PT_RS + ((lane >> 4) << 3) + ks * 16) * 2;
                LDSM_X4(a[mt][0], a[mt][1], a[mt][2], a[mt][3], ad);
            }
            uint32_t bfr[2];
            uint32_t bd = sb + VT_OFF + (uint32_t)(
                (wid * 8 + (l & 7)) * PT_RS + ((l >> 3) & 1) * 8 + ks * 16) * 2;
            LDSM_X2(bfr[0], bfr[1], bd);
            for (int mt = 0; mt < mt_cnt; mt++)
                MMA16816(oacc[mt], a[mt], bfr);
        }
        for (int mt = 0; mt < mt_cnt; mt++)
            #pragma unroll
            for (int hh = 0; hh < 2; hh++) {
                int gr = m0 + mt * 16 + r4 + hh * 8;
                if (gr >= SEQ) continue;
                *reinterpret_cast<__half2*>(
                    &oh[((size_t)(b * SEQ + gr)) * DIM + h * HD + wid * 8 + c2]) =
                    __halves2half2(__float2half_rn(oacc[mt][hh*2]),
                                   __float2half_rn(oacc[mt][hh*2+1]));
            }
        __syncthreads();
    }
}

// ---------------- host orchestration ----------------
#define GS_2T_128 (NST * (128*RS*2 + 2*128*RS*2))   // 92160
#define GS_1T_128 (NST * (128*RS*2 + 128*RS*2))     // 61440

template<typename F, typename... Args>
static void pdl_launch(F func, dim3 grid, dim3 block, size_t smem, Args... args) {
    cudaLaunchConfig_t cfg = {};
    cfg.gridDim = grid;
    cfg.blockDim = block;
    cfg.dynamicSmemBytes = smem;
    cudaLaunchAttribute attr[1];
    attr[0].id = cudaLaunchAttributeProgrammaticStreamSerialization;
    attr[0].val.programmaticStreamSerializationAllowed = 1;
    cfg.attrs = attr;
    cfg.numAttrs = 1;
    cudaLaunchKernelEx(&cfg, func, args...);
}

extern "C" void kernel_launch(void* const* d_in, const int* in_sizes, int n_in,
                              void* d_out, int out_size) {
    const float* images    = (const float*)d_in[0];
    const float* patch_W   = (const float*)d_in[1];
    const float* patch_b   = (const float*)d_in[2];
    const float* pos_emb   = (const float*)d_in[3];
    const float* cls       = (const float*)d_in[4];
    const float* ln1_g     = (const float*)d_in[5];
    const float* ln1_b     = (const float*)d_in[6];
    const float* Wq        = (const float*)d_in[7];
    const float* bq        = (const float*)d_in[8];
    const float* Wk        = (const float*)d_in[9];
    const float* bk        = (const float*)d_in[10];
    const float* Wv        = (const float*)d_in[11];
    const float* bv        = (const float*)d_in[12];
    const float* Wo        = (const float*)d_in[13];
    const float* bo        = (const float*)d_in[14];
    const float* ln2_g     = (const float*)d_in[15];
    const float* ln2_b     = (const float*)d_in[16];
    const float* W1        = (const float*)d_in[17];
    const float* b1        = (const float*)d_in[18];
    const float* W2        = (const float*)d_in[19];
    const float* b2        = (const float*)d_in[20];
    const float* head_g    = (const float*)d_in[21];
    const float* head_bn   = (const float*)d_in[22];
    const float* head_W    = (const float*)d_in[23];
    const float* head_bias = (const float*)d_in[24];

    float *x;
    __half *q16, *k16, *v16;
    __half *xn, *oo, *hbuf, *pbuf, *cls16;
    __half *wpH, *wpL, *wqH, *wkH, *wvH, *woH;
    __half *w1H, *w2H, *whH, *whL;
    cudaGetSymbolAddress((void**)&x,     g_x);
    cudaGetSymbolAddress((void**)&q16,   g_q);
    cudaGetSymbolAddress((void**)&k16,   g_k);
    cudaGetSymbolAddress((void**)&v16,   g_v);
    cudaGetSymbolAddress((void**)&xn,    g_xn);
    cudaGetSymbolAddress((void**)&oo,    g_o);
    cudaGetSymbolAddress((void**)&hbuf,  g_h);
    cudaGetSymbolAddress((void**)&pbuf,  g_p);
    cudaGetSymbolAddress((void**)&cls16, g_cls16);
    cudaGetSymbolAddress((void**)&wpH, w_pat_h);cudaGetSymbolAddress((void**)&wpL, w_pat_l);
    cudaGetSymbolAddress((void**)&wqH, w_q_h);
    cudaGetSymbolAddress((void**)&wkH, w_k_h);
    cudaGetSymbolAddress((void**)&wvH, w_v_h);
    cudaGetSymbolAddress((void**)&woH, w_o_h);
    cudaGetSymbolAddress((void**)&w1H, w_1_h);
    cudaGetSymbolAddress((void**)&w2H, w_2_h);
    cudaGetSymbolAddress((void**)&whH, w_hd_h); cudaGetSymbolAddress((void**)&whL, w_hd_l);

    cudaFuncSetAttribute(hgemm<128,128,2,2,4>, cudaFuncAttributeMaxDynamicSharedMemorySize, GS_2T_128);
    cudaFuncSetAttribute(hgemm<128,128,1,2,4>, cudaFuncAttributeMaxDynamicSharedMemorySize, GS_1T_128);
    cudaFuncSetAttribute(attn_mma, cudaFuncAttributeMaxDynamicSharedMemorySize, AMEM);

    QKV dummy = {};

    dim3 tblk(32, 8);
    wprep<<<dim3(24, 24, 1),   tblk>>>(patch_W, wpH, wpL, DIM, DIM);
    wprep<<<dim3(2, 24, 144),  tblk>>>(Wq, wqH, nullptr, DIM, HD);
    wprep<<<dim3(2, 24, 144),  tblk>>>(Wk, wkH, nullptr, DIM, HD);
    wprep<<<dim3(2, 24, 144),  tblk>>>(Wv, wvH, nullptr, DIM, HD);
    wprep<<<dim3(24, 24, 12),  tblk>>>(Wo, woH, nullptr, DIM, DIM);
    wprep<<<dim3(96, 24, 12),  tblk>>>(W1, w1H, nullptr, DIM, FF);
    wprep<<<dim3(24, 96, 12),  tblk>>>(W2, w2H, nullptr, FF, DIM);
    wprep<<<dim3(32, 24, 1),   tblk>>>(head_W, whH, whL, DIM, NCLS);

    patch_extract<<<(PTOK * DIM + 255) / 256, 256>>>(images, pbuf);
    pdl_launch(hgemm<128,128,2,2,4>, dim3(6, 49), dim3(256), GS_2T_128,
               (const __half*)pbuf, (const __half*)wpH, (const __half*)wpL,
               patch_b, pos_emb, x, (__half*)nullptr,
               PTOK, DIM, DIM, 3, dummy);
    cls_fill<<<(BB * DIM + 255) / 256, 256>>>(cls, x);

    for (int l = 0; l < NL; l++) {
        size_t wo768 = (size_t)l * DIM * DIM;
        size_t woff  = (size_t)l * DIM * FF;

        pdl_launch(ln_kernel, dim3(TOK), dim3(192), 0,
                   (const float*)x, ln1_g + l * DIM, ln1_b + l * DIM, xn,
                   (long long)DIM, (long long)DIM);

        QKV qk;
        qk.bh[0] = wqH + wo768; qk.bh[1] = wkH + wo768; qk.bh[2] = wvH + wo768;
        qk.bl[0] = nullptr; qk.bl[1] = nullptr; qk.bl[2] = nullptr;
        qk.bias[0] = bq + l * DIM; qk.bias[1] = bk + l * DIM; qk.bias[2] = bv + l * DIM;
        qk.out[0] = q16; qk.out[1] = k16; qk.out[2] = v16;
        pdl_launch(hgemm<128,128,1,2,4>, dim3(18, 50), dim3(256), GS_1T_128,
                   (const __half*)xn, (const __half*)nullptr, (const __half*)nullptr,
                   (const float*)nullptr, (const float*)nullptr,
                   (float*)nullptr, (__half*)nullptr,
                   TOK, 2304, DIM, 4, qk);

        pdl_launch(attn_mma, dim3(BB * NH), dim3(256), AMEM,
                   (const __half*)q16, (const __half*)k16, (const __half*)v16, oo);

        pdl_launch(hgemm<128,128,1,2,4>, dim3(6, 50), dim3(256), GS_1T_128,
                   (const __half*)oo, (const __half*)(woH + wo768),
                   (const __half*)nullptr, bo + l * DIM,
                   (const float*)x, x, (__half*)nullptr,
                   TOK, DIM, DIM, 1, dummy);

        pdl_launch(ln_kernel, dim3(TOK), dim3(192), 0,
                   (const float*)x, ln2_g + l * DIM, ln2_b + l * DIM, xn,
                   (long long)DIM, (long long)DIM);

        pdl_launch(hgemm<128,128,1,2,4>, dim3(24, 50), dim3(256), GS_1T_128,
                   (const __half*)xn, (const __half*)(w1H + woff),
                   (const __half*)nullptr, b1 + l * FF, (const float*)nullptr,
                   (float*)nullptr, hbuf, TOK, FF, DIM, 2, dummy);
        pdl_launch(hgemm<128,128,1,2,4>, dim3(6, 50), dim3(256), GS_1T_128,
                   (const __half*)hbuf, (const __half*)(w2H + woff),
                   (const __half*)nullptr, b2 + l * DIM, (const float*)x,
                   x, (__half*)nullptr, TOK, DIM, FF, 1, dummy);
    }

    pdl_launch(ln_kernel, dim3(BB), dim3(192), 0,
               (const float*)x, head_g, head_bn, cls16,
               (long long)(SEQ * DIM), (long long)DIM);
    pdl_launch(hgemm<128,128,2,2,4>, dim3(8, 1), dim3(256), GS_2T_128,
               (const __half*)cls16, (const __half*)whH, (const __half*)whL,
               head_bias, (const float*)nullptr, (float*)d_out, (__half*)nullptr,
               BB, NCLS, DIM, 0, dummy);
}